// round 8
// baseline (speedup 1.0000x reference)
#include <cuda_runtime.h>
#include <cuda_bf16.h>
#include <math_constants.h>
#include <cstdint>

// Problem constants
#define Bq   4
#define Sq   1024
#define Dm   1024
#define Hh   16
#define DHd  64
#define Ff   4096
#define NBb  33
#define Ll   6
#define ROWS (Bq*Sq)
#define SCALE_ATTN 0.125f

// ---------------- scratch (device globals) ----------------
__device__ float g_x [ROWS*Dm];
__device__ float g_y [ROWS*Dm];
__device__ float g_k [ROWS*Dm];
__device__ float g_v [ROWS*Dm];
__device__ float g_qe[Bq*Hh*Sq*NBb];

__device__ __nv_bfloat16 g_xh [ROWS*Dm], g_xl [ROWS*Dm];
__device__ __nv_bfloat16 g_ah [ROWS*Dm], g_al [ROWS*Dm];
__device__ __nv_bfloat16 g_ffh[ROWS*Dm], g_ffl[ROWS*Dm];
__device__ __nv_bfloat16 g_hh [ROWS*Ff], g_hl [ROWS*Ff];

// transposed bf16 weights: [N][K]
__device__ __nv_bfloat16 g_wT4h[Ll*4*Dm*Dm], g_wT4l[Ll*4*Dm*Dm];
__device__ __nv_bfloat16 g_w1Th[Ll*Ff*Dm],  g_w1Tl[Ll*Ff*Dm];
__device__ __nv_bfloat16 g_w2Th[Ll*Dm*Ff],  g_w2Tl[Ll*Dm*Ff];

__device__ __forceinline__ void bsplit(float f, __nv_bfloat16& h, __nv_bfloat16& l) {
    h = __float2bfloat16_rn(f);
    l = __float2bfloat16_rn(f - __bfloat162float(h));
}

// ---------------- weight transpose + split ----------------
__global__ void wconv_kernel(const float* __restrict__ W,
                             __nv_bfloat16* __restrict__ Th, __nv_bfloat16* __restrict__ Tl,
                             int K, int N)
{
    __shared__ float t[32][33];
    int n0 = blockIdx.x * 32, k0 = blockIdx.y * 32;
    int tx = threadIdx.x, ty = threadIdx.y;
#pragma unroll
    for (int i = 0; i < 4; i++)
        t[ty + 8 * i][tx] = W[(size_t)(k0 + ty + 8 * i) * N + n0 + tx];
    __syncthreads();
#pragma unroll
    for (int i = 0; i < 4; i++) {
        float f = t[tx][ty + 8 * i];
        int n = n0 + ty + 8 * i, k = k0 + tx;
        __nv_bfloat16 h, l; bsplit(f, h, l);
        Th[(size_t)n * K + k] = h;
        Tl[(size_t)n * K + k] = l;
    }
}

// ---------------- copy + split ----------------
__global__ void copy_split_kernel(const float* __restrict__ in, float* __restrict__ out,
                                  __nv_bfloat16* __restrict__ oh, __nv_bfloat16* __restrict__ ol,
                                  int n)
{
    int i = blockIdx.x * blockDim.x + threadIdx.x;
    if (i < n) {
        float f = in[i];
        out[i] = f;
        __nv_bfloat16 h, l; bsplit(f, h, l);
        oh[i] = h; ol[i] = l;
    }
}

// =========================================================================
// bf16-split mma.sync GEMM, ldmatrix fragment loads, 2-stage BK=32 pipeline
// C = (Ah+Al) @ (Bh+Bl)^T + bias (+resid)(relu)
// A[M][K] hi/lo row-major; B[N][K] hi/lo row-major (= W^T).
// CTA 128x128, 256 thr = 8 warps (4m x 2n), warp tile 32x64.
// =========================================================================
#define PADk 40                        // 32 data + 8 pad bf16 (80B rows, 16B aligned)
#define STG  (128 * PADk)              // bf16 per array per stage
#define GEMM_SMEM (2 * 4 * STG * 2)    // 2 stages * 4 arrays * STG * 2B = 81920

__device__ __forceinline__ void mma_bf16(float* c, const uint32_t* a, uint32_t b0, uint32_t b1) {
    asm volatile(
        "mma.sync.aligned.m16n8k16.row.col.f32.bf16.bf16.f32 "
        "{%0,%1,%2,%3}, {%4,%5,%6,%7}, {%8,%9}, {%0,%1,%2,%3};\n"
        : "+f"(c[0]), "+f"(c[1]), "+f"(c[2]), "+f"(c[3])
        : "r"(a[0]), "r"(a[1]), "r"(a[2]), "r"(a[3]), "r"(b0), "r"(b1));
}

__device__ __forceinline__ void ldsm4(uint32_t* r, uint32_t addr) {
    asm volatile("ldmatrix.sync.aligned.m8n8.x4.shared.b16 {%0,%1,%2,%3}, [%4];"
                 : "=r"(r[0]), "=r"(r[1]), "=r"(r[2]), "=r"(r[3]) : "r"(addr));
}

__device__ __forceinline__ uint32_t s2u(const void* p) {
    uint32_t a;
    asm("{ .reg .u64 t; cvta.to.shared.u64 t, %1; cvt.u32.u64 %0, t; }" : "=r"(a) : "l"(p));
    return a;
}

__device__ __forceinline__ void cp16s(uint32_t s, const void* g) {
    asm volatile("cp.async.cg.shared.global [%0], [%1], 16;\n" :: "r"(s), "l"(g));
}

__device__ __forceinline__ void gemm16_core(
    const __nv_bfloat16* __restrict__ Ah, const __nv_bfloat16* __restrict__ Al,
    const __nv_bfloat16* __restrict__ Bh, const __nv_bfloat16* __restrict__ Bl,
    const float* __restrict__ bias, const float* __restrict__ resid,
    float* __restrict__ C, __nv_bfloat16* __restrict__ Ch, __nv_bfloat16* __restrict__ Cl,
    int N, int K, bool relu)
{
    extern __shared__ __nv_bfloat16 smem[];
    // layout: [stage][array(Ah,Al,Bh,Bl)][STG]
    const uint32_t smb = s2u(smem);

    const int tid  = threadIdx.x;
    const int lane = tid & 31;
    const int warp = tid >> 5;
    const int wm   = warp >> 1;
    const int wn   = warp & 1;
    const int g    = lane >> 2;
    const int tig  = lane & 3;

    const int bm = blockIdx.y * 128, bn = blockIdx.x * 128;

    // cp.async mapping: thread -> (row = tid>>1, khalf = (tid&1)*16), 2x16B per array
    const int prow = tid >> 1, kh = (tid & 1) * 16;
    const uint32_t soff = (uint32_t)(prow * PADk + kh) * 2;

    const __nv_bfloat16* gA0 = Ah + (size_t)(bm + prow) * K + kh;
    const __nv_bfloat16* gA1 = Al + (size_t)(bm + prow) * K + kh;
    const __nv_bfloat16* gB0 = Bh + (size_t)(bn + prow) * K + kh;
    const __nv_bfloat16* gB1 = Bl + (size_t)(bn + prow) * K + kh;

    // ldmatrix per-lane offsets
    const int mi = lane >> 3, li = lane & 7;
    // A: row = wm*32 + mf*16 + (mi&1)*8 + li ; k = ks + (mi>>1)*8
    const uint32_t aoff0 = (uint32_t)(((wm * 32 + (mi & 1) * 8 + li) * PADk) + (mi >> 1) * 8) * 2;
    // B: n = wn*64 + p*16 + (mi>>1)*8 + li ; k = ks + (mi&1)*8
    const uint32_t boff0 = (uint32_t)(((wn * 64 + (mi >> 1) * 8 + li) * PADk) + (mi & 1) * 8) * 2;

    float acc[2][8][4];
#pragma unroll
    for (int i = 0; i < 2; i++)
#pragma unroll
        for (int j = 0; j < 8; j++)
#pragma unroll
            for (int c = 0; c < 4; c++) acc[i][j][c] = 0.f;

    const int nck = K >> 5;   // BK=32 chunks
    const uint32_t stageB = 4 * STG * 2;   // bytes per stage
    const uint32_t arrB   = STG * 2;       // bytes per array

    // prefetch chunk 0 -> stage 0
    {
        cp16s(smb + 0 * arrB + soff,      gA0);
        cp16s(smb + 0 * arrB + soff + 16, gA0 + 8);
        cp16s(smb + 1 * arrB + soff,      gA1);
        cp16s(smb + 1 * arrB + soff + 16, gA1 + 8);
        cp16s(smb + 2 * arrB + soff,      gB0);
        cp16s(smb + 2 * arrB + soff + 16, gB0 + 8);
        cp16s(smb + 3 * arrB + soff,      gB1);
        cp16s(smb + 3 * arrB + soff + 16, gB1 + 8);
        asm volatile("cp.async.commit_group;\n");
    }

    for (int kc = 0; kc < nck; kc++) {
        asm volatile("cp.async.wait_group 0;\n");
        __syncthreads();
        if (kc + 1 < nck) {
            const uint32_t sb = ((kc + 1) & 1) * stageB;
            const int go = (kc + 1) * 32;
            cp16s(smb + sb + 0 * arrB + soff,      gA0 + go);
            cp16s(smb + sb + 0 * arrB + soff + 16, gA0 + go + 8);
            cp16s(smb + sb + 1 * arrB + soff,      gA1 + go);
            cp16s(smb + sb + 1 * arrB + soff + 16, gA1 + go + 8);
            cp16s(smb + sb + 2 * arrB + soff,      gB0 + go);
            cp16s(smb + sb + 2 * arrB + soff + 16, gB0 + go + 8);
            cp16s(smb + sb + 3 * arrB + soff,      gB1 + go);
            cp16s(smb + sb + 3 * arrB + soff + 16, gB1 + go + 8);
            asm volatile("cp.async.commit_group;\n");
        }
        const uint32_t sb = (kc & 1) * stageB;
        const uint32_t aH = smb + sb + 0 * arrB + aoff0;
        const uint32_t aL = smb + sb + 1 * arrB + aoff0;
        const uint32_t bH = smb + sb + 2 * arrB + boff0;
        const uint32_t bL = smb + sb + 3 * arrB + boff0;

#pragma unroll
        for (int ks = 0; ks < 2; ks++) {
            const uint32_t ko = ks * 32;   // 16 bf16 = 32 bytes
            uint32_t ah[2][4], al[2][4];
            ldsm4(ah[0], aH + ko);
            ldsm4(ah[1], aH + 16 * PADk * 2 + ko);
            ldsm4(al[0], aL + ko);
            ldsm4(al[1], aL + 16 * PADk * 2 + ko);
#pragma unroll
            for (int p = 0; p < 4; p++) {
                uint32_t bh[4], bl[4];
                ldsm4(bh, bH + p * 16 * PADk * 2 + ko);
                ldsm4(bl, bL + p * 16 * PADk * 2 + ko);
#pragma unroll
                for (int q = 0; q < 2; q++) {
                    const int nf = 2 * p + q;
#pragma unroll
                    for (int mf = 0; mf < 2; mf++) {
                        mma_bf16(acc[mf][nf], ah[mf], bh[2 * q], bh[2 * q + 1]);
                        mma_bf16(acc[mf][nf], ah[mf], bl[2 * q], bl[2 * q + 1]);
                        mma_bf16(acc[mf][nf], al[mf], bh[2 * q], bh[2 * q + 1]);
                    }
                }
            }
        }
    }

    // ---- epilogue ----
#pragma unroll
    for (int mf = 0; mf < 2; mf++) {
#pragma unroll
        for (int nf = 0; nf < 8; nf++) {
            const int r0 = bm + wm * 32 + mf * 16 + g;
            const int cc = bn + wn * 64 + nf * 8 + 2 * tig;
            const float bs0 = bias[cc], bs1 = bias[cc + 1];
            float v0 = acc[mf][nf][0] + bs0;
            float v1 = acc[mf][nf][1] + bs1;
            float v2 = acc[mf][nf][2] + bs0;
            float v3 = acc[mf][nf][3] + bs1;
            const size_t i0 = (size_t)r0 * N + cc;
            const size_t i1 = (size_t)(r0 + 8) * N + cc;
            if (resid) {
                const float2 r0v = *(const float2*)(resid + i0);
                const float2 r1v = *(const float2*)(resid + i1);
                v0 += r0v.x; v1 += r0v.y; v2 += r1v.x; v3 += r1v.y;
            }
            if (relu) {
                v0 = fmaxf(v0, 0.f); v1 = fmaxf(v1, 0.f);
                v2 = fmaxf(v2, 0.f); v3 = fmaxf(v3, 0.f);
            }
            if (C) {
                *(float2*)(C + i0) = make_float2(v0, v1);
                *(float2*)(C + i1) = make_float2(v2, v3);
            }
            if (Ch) {
                __nv_bfloat16 h0, l0, h1, l1, h2, l2, h3, l3;
                bsplit(v0, h0, l0); bsplit(v1, h1, l1);
                bsplit(v2, h2, l2); bsplit(v3, h3, l3);
                *(__nv_bfloat162*)(Ch + i0) = __nv_bfloat162(h0, h1);
                *(__nv_bfloat162*)(Ch + i1) = __nv_bfloat162(h2, h3);
                *(__nv_bfloat162*)(Cl + i0) = __nv_bfloat162(l0, l1);
                *(__nv_bfloat162*)(Cl + i1) = __nv_bfloat162(l2, l3);
            }
        }
    }
}

__global__ __launch_bounds__(256) void gemm16_kernel(
    const __nv_bfloat16* __restrict__ Ah, const __nv_bfloat16* __restrict__ Al,
    const __nv_bfloat16* __restrict__ Bh, const __nv_bfloat16* __restrict__ Bl,
    const float* __restrict__ bias, const float* __restrict__ resid,
    float* __restrict__ C, __nv_bfloat16* __restrict__ Ch, __nv_bfloat16* __restrict__ Cl,
    int N, int K, int relu)
{
    gemm16_core(Ah, Al, Bh, Bl, bias, resid, C, Ch, Cl, N, K, relu != 0);
}

__global__ __launch_bounds__(256) void gemm16_qkv_kernel(
    const __nv_bfloat16* __restrict__ Ah, const __nv_bfloat16* __restrict__ Al,
    const __nv_bfloat16* __restrict__ WTh, const __nv_bfloat16* __restrict__ WTl,
    const float* __restrict__ bq, const float* __restrict__ bk, const float* __restrict__ bv,
    int N, int K)
{
    const size_t off = (size_t)blockIdx.z * Dm * Dm;
    const float* bias; float* C;
    if      (blockIdx.z == 0) { bias = bq; C = g_y; }
    else if (blockIdx.z == 1) { bias = bk; C = g_k; }
    else                      { bias = bv; C = g_v; }
    gemm16_core(Ah, Al, WTh + off, WTl + off, bias, nullptr, C, nullptr, nullptr, N, K, false);
}

// ---------------- qe = q @ Erel^T ----------------
__global__ void qe_kernel(const float* __restrict__ er)
{
    int idx = blockIdx.x * blockDim.x + threadIdx.x;
    const int total = Bq * Hh * Sq * NBb;
    if (idx >= total) return;
    int nb = idx % NBb;
    int s  = (idx / NBb) % Sq;
    int h  = (idx / (NBb * Sq)) % Hh;
    int b  =  idx / (NBb * Sq * Hh);
    const float* qr = g_y + ((size_t)(b * Sq + s)) * Dm + h * DHd;
    const float* e  = er + nb * DHd;
    float acc = 0.f;
#pragma unroll
    for (int d = 0; d < DHd; d++) acc = fmaf(qr[d], e[d], acc);
    g_qe[idx] = acc;
}

// ---------------- flash attention: 64q x 64k tile, 4x4/thread -------------------
#define ATTN_SMEM ((64 * 64 * 3 + 64 * NBb) * 4)

__global__ void attn_kernel(const float* __restrict__ brel, const int* __restrict__ rid)
{
    extern __shared__ float sm[];
    float* Qs = sm;
    float* Ks = sm + 4096;
    float* Vs = sm + 8192;
    float* Cb = sm + 12288;

    int tid = threadIdx.x;
    int tx = tid & 15, ty = tid >> 4;
    int b = blockIdx.z, h = blockIdx.y;
    int q0 = blockIdx.x * 64;

    size_t qbase = ((size_t)(b * Sq) + q0) * Dm + h * DHd;
    for (int i = tid; i < 64 * 16; i += 256) {
        int r = i >> 4, d4 = (i & 15) * 4;
        float4 t = *(const float4*)(g_y + qbase + (size_t)r * Dm + d4);
        Qs[(d4 + 0) * 64 + r] = t.x;
        Qs[(d4 + 1) * 64 + r] = t.y;
        Qs[(d4 + 2) * 64 + r] = t.z;
        Qs[(d4 + 3) * 64 + r] = t.w;
    }
    for (int i = tid; i < 64 * NBb; i += 256) {
        int r = i / NBb, nb = i - r * NBb;
        Cb[i] = g_qe[(((size_t)(b * Hh + h)) * Sq + q0 + r) * NBb + nb] + brel[h * NBb + nb];
    }

    float m_i[4], l_i[4], o[4][4];
#pragma unroll
    for (int i = 0; i < 4; i++) {
        m_i[i] = -CUDART_INF_F; l_i[i] = 0.f;
#pragma unroll
        for (int j = 0; j < 4; j++) o[i][j] = 0.f;
    }
    __syncthreads();

    for (int k0 = 0; k0 < Sq; k0 += 64) {
        size_t kbase = ((size_t)(b * Sq) + k0) * Dm + h * DHd;
        for (int i = tid; i < 64 * 16; i += 256) {
            int r = i >> 4, d4 = (i & 15) * 4;
            float4 tk = *(const float4*)(g_k + kbase + (size_t)r * Dm + d4);
            Ks[(d4 + 0) * 64 + r] = tk.x;
            Ks[(d4 + 1) * 64 + r] = tk.y;
            Ks[(d4 + 2) * 64 + r] = tk.z;
            Ks[(d4 + 3) * 64 + r] = tk.w;
            float4 tv = *(const float4*)(g_v + kbase + (size_t)r * Dm + d4);
            *(float4*)(Vs + r * 64 + d4) = tv;
        }
        __syncthreads();

        float s4[4][4];
#pragma unroll
        for (int i = 0; i < 4; i++)
#pragma unroll
            for (int j = 0; j < 4; j++) s4[i][j] = 0.f;
#pragma unroll
        for (int d = 0; d < 64; d++) {
            float4 aq = *(const float4*)(Qs + d * 64 + ty * 4);
            float4 bk = *(const float4*)(Ks + d * 64 + tx * 4);
            float a_[4] = {aq.x, aq.y, aq.z, aq.w};
            float b_[4] = {bk.x, bk.y, bk.z, bk.w};
#pragma unroll
            for (int i = 0; i < 4; i++)
#pragma unroll
                for (int j = 0; j < 4; j++)
                    s4[i][j] = fmaf(a_[i], b_[j], s4[i][j]);
        }

#pragma unroll
        for (int i = 0; i < 4; i++) {
            int qr = ty * 4 + i;
            const int* rr = rid + (size_t)(q0 + qr) * Sq + k0 + tx * 4;
            float mt = -CUDART_INF_F;
#pragma unroll
            for (int j = 0; j < 4; j++) {
                float sv = (s4[i][j] + Cb[qr * NBb + rr[j]]) * SCALE_ATTN;
                s4[i][j] = sv;
                mt = fmaxf(mt, sv);
            }
#pragma unroll
            for (int off = 8; off; off >>= 1)
                mt = fmaxf(mt, __shfl_xor_sync(0xffffffffu, mt, off));
            float mnew = fmaxf(m_i[i], mt);
            float fac = __expf(m_i[i] - mnew);
            float rs = 0.f;
#pragma unroll
            for (int j = 0; j < 4; j++) {
                float p = __expf(s4[i][j] - mnew);
                s4[i][j] = p;
                rs += p;
            }
#pragma unroll
            for (int off = 8; off; off >>= 1)
                rs += __shfl_xor_sync(0xffffffffu, rs, off);
            l_i[i] = l_i[i] * fac + rs;
            m_i[i] = mnew;
#pragma unroll
            for (int j = 0; j < 4; j++) o[i][j] *= fac;
        }
        __syncthreads();
#pragma unroll
        for (int i = 0; i < 4; i++)
            *(float4*)(Ks + (ty * 4 + i) * 64 + tx * 4) =
                make_float4(s4[i][0], s4[i][1], s4[i][2], s4[i][3]);
        __syncthreads();

#pragma unroll 8
        for (int kc = 0; kc < 64; kc++) {
            float4 vv = *(const float4*)(Vs + kc * 64 + tx * 4);
#pragma unroll
            for (int i = 0; i < 4; i++) {
                float p = Ks[(ty * 4 + i) * 64 + kc];
                o[i][0] = fmaf(p, vv.x, o[i][0]);
                o[i][1] = fmaf(p, vv.y, o[i][1]);
                o[i][2] = fmaf(p, vv.z, o[i][2]);
                o[i][3] = fmaf(p, vv.w, o[i][3]);
            }
        }
        __syncthreads();
    }

#pragma unroll
    for (int i = 0; i < 4; i++) {
        float inv = 1.f / l_i[i];
        size_t ob = ((size_t)(b * Sq) + q0 + ty * 4 + i) * Dm + h * DHd + tx * 4;
        float f0 = o[i][0] * inv, f1 = o[i][1] * inv, f2 = o[i][2] * inv, f3 = o[i][3] * inv;
        __nv_bfloat16 h0, l0, h1, l1, h2, l2, h3, l3;
        bsplit(f0, h0, l0); bsplit(f1, h1, l1);
        bsplit(f2, h2, l2); bsplit(f3, h3, l3);
        *(__nv_bfloat162*)(g_ah + ob)     = __nv_bfloat162(h0, h1);
        *(__nv_bfloat162*)(g_ah + ob + 2) = __nv_bfloat162(h2, h3);
        *(__nv_bfloat162*)(g_al + ob)     = __nv_bfloat162(l0, l1);
        *(__nv_bfloat162*)(g_al + ob + 2) = __nv_bfloat162(l2, l3);
    }
}

// ---------------- layernorm ----------------
__device__ __forceinline__ float block_sum_256(float val, float* sh) {
#pragma unroll
    for (int off = 16; off; off >>= 1) val += __shfl_xor_sync(0xffffffffu, val, off);
    if ((threadIdx.x & 31) == 0) sh[threadIdx.x >> 5] = val;
    __syncthreads();
    float t = 0.f;
    if (threadIdx.x < 8) t = sh[threadIdx.x];
    if (threadIdx.x < 32) {
#pragma unroll
        for (int off = 4; off; off >>= 1) t += __shfl_xor_sync(0xffffffffu, t, off);
        if (threadIdx.x == 0) sh[0] = t;
    }
    __syncthreads();
    float r = sh[0];
    __syncthreads();
    return r;
}

__global__ void ln_kernel(const float* __restrict__ in, const float* __restrict__ gam,
                          const float* __restrict__ bet, float* __restrict__ out,
                          __nv_bfloat16* __restrict__ oh, __nv_bfloat16* __restrict__ ol)
{
    __shared__ float sh[8];
    int row = blockIdx.x, tid = threadIdx.x;
    float4 x4 = ((const float4*)(in + (size_t)row * Dm))[tid];
    float s = x4.x + x4.y + x4.z + x4.w;
    float mean = block_sum_256(s, sh) * (1.f / Dm);
    float dx = x4.x - mean, dy = x4.y - mean, dz = x4.z - mean, dw = x4.w - mean;
    float s2 = dx * dx + dy * dy + dz * dz + dw * dw;
    float var = block_sum_256(s2, sh) * (1.f / Dm);
    float inv = rsqrtf(var + 1e-6f);
    int c = tid * 4;
    float4 o;
    o.x = dx * inv * gam[c + 0] + bet[c + 0];
    o.y = dy * inv * gam[c + 1] + bet[c + 1];
    o.z = dz * inv * gam[c + 2] + bet[c + 2];
    o.w = dw * inv * gam[c + 3] + bet[c + 3];
    ((float4*)(out + (size_t)row * Dm))[tid] = o;
    if (oh) {
        size_t base = (size_t)row * Dm + c;
        __nv_bfloat16 h0, l0, h1, l1, h2, l2, h3, l3;
        bsplit(o.x, h0, l0); bsplit(o.y, h1, l1);
        bsplit(o.z, h2, l2); bsplit(o.w, h3, l3);
        *(__nv_bfloat162*)(oh + base)     = __nv_bfloat162(h0, h1);
        *(__nv_bfloat162*)(oh + base + 2) = __nv_bfloat162(h2, h3);
        *(__nv_bfloat162*)(ol + base)     = __nv_bfloat162(l0, l1);
        *(__nv_bfloat162*)(ol + base + 2) = __nv_bfloat162(l2, l3);
    }
}

// ---------------- launch ----------------
extern "C" void kernel_launch(void* const* d_in, const int* in_sizes, int n_in,
                              void* d_out, int out_size)
{
    const float* x_in = (const float*)d_in[0];
    const int*   rid  = (const int*)  d_in[1];
    const float* Wq   = (const float*)d_in[2];
    const float* bqp  = (const float*)d_in[3];
    const float* Wk   = (const float*)d_in[4];
    const float* bkp  = (const float*)d_in[5];
    const float* Wv   = (const float*)d_in[6];
    const float* bvp  = (const float*)d_in[7];
    const float* Wo   = (const float*)d_in[8];
    const float* bop  = (const float*)d_in[9];
    const float* Erel = (const float*)d_in[10];
    const float* Brel = (const float*)d_in[11];
    const float* g1   = (const float*)d_in[12];
    const float* be1  = (const float*)d_in[13];
    const float* g2   = (const float*)d_in[14];
    const float* be2  = (const float*)d_in[15];
    const float* W1   = (const float*)d_in[16];
    const float* b1   = (const float*)d_in[17];
    const float* W2   = (const float*)d_in[18];
    const float* b2   = (const float*)d_in[19];
    float* outp = (float*)d_out;

    float *x, *y, *k, *v;
    __nv_bfloat16 *xh, *xl, *ah, *al, *ffh, *ffl, *hh, *hl;
    __nv_bfloat16 *wT4h, *wT4l, *w1Th, *w1Tl, *w2Th, *w2Tl;
    cudaGetSymbolAddress((void**)&x,  g_x);
    cudaGetSymbolAddress((void**)&y,  g_y);
    cudaGetSymbolAddress((void**)&k,  g_k);
    cudaGetSymbolAddress((void**)&v,  g_v);
    cudaGetSymbolAddress((void**)&xh, g_xh);  cudaGetSymbolAddress((void**)&xl, g_xl);
    cudaGetSymbolAddress((void**)&ah, g_ah);  cudaGetSymbolAddress((void**)&al, g_al);
    cudaGetSymbolAddress((void**)&ffh, g_ffh); cudaGetSymbolAddress((void**)&ffl, g_ffl);
    cudaGetSymbolAddress((void**)&hh, g_hh);  cudaGetSymbolAddress((void**)&hl, g_hl);
    cudaGetSymbolAddress((void**)&wT4h, g_wT4h); cudaGetSymbolAddress((void**)&wT4l, g_wT4l);
    cudaGetSymbolAddress((void**)&w1Th, g_w1Th); cudaGetSymbolAddress((void**)&w1Tl, g_w1Tl);
    cudaGetSymbolAddress((void**)&w2Th, g_w2Th); cudaGetSymbolAddress((void**)&w2Tl, g_w2Tl);

    cudaFuncSetAttribute(gemm16_kernel,     cudaFuncAttributeMaxDynamicSharedMemorySize, GEMM_SMEM);
    cudaFuncSetAttribute(gemm16_qkv_kernel, cudaFuncAttributeMaxDynamicSharedMemorySize, GEMM_SMEM);
    cudaFuncSetAttribute(attn_kernel,       cudaFuncAttributeMaxDynamicSharedMemorySize, ATTN_SMEM);

    // ---- preconvert all weights ----
    const dim3 tb(32, 8);
    for (int l = 0; l < Ll; l++) {
        const size_t wdd = (size_t)l * Dm * Dm;
        const size_t o4  = (size_t)l * 4 * Dm * Dm;
        wconv_kernel<<<dim3(Dm / 32, Dm / 32), tb>>>(Wq + wdd, wT4h + o4,                   wT4l + o4,                   Dm, Dm);
        wconv_kernel<<<dim3(Dm / 32, Dm / 32), tb>>>(Wk + wdd, wT4h + o4 + (size_t)Dm*Dm,   wT4l + o4 + (size_t)Dm*Dm,   Dm, Dm);
        wconv_kernel<<<dim3(Dm / 32, Dm / 32), tb>>>(Wv + wdd, wT4h + o4 + (size_t)2*Dm*Dm, wT4l + o4 + (size_t)2*Dm*Dm, Dm, Dm);
        wconv_kernel<<<dim3(Dm / 32, Dm / 32), tb>>>(Wo + wdd, wT4h + o4 + (size_t)3*Dm*Dm, wT4l + o4 + (size_t)3*Dm*Dm, Dm, Dm);
        wconv_kernel<<<dim3(Ff / 32, Dm / 32), tb>>>(W1 + (size_t)l * Dm * Ff, w1Th + (size_t)l * Ff * Dm, w1Tl + (size_t)l * Ff * Dm, Dm, Ff);
        wconv_kernel<<<dim3(Dm / 32, Ff / 32), tb>>>(W2 + (size_t)l * Ff * Dm, w2Th + (size_t)l * Dm * Ff, w2Tl + (size_t)l * Dm * Ff, Ff, Dm);
    }

    copy_split_kernel<<<(ROWS * Dm + 255) / 256, 256>>>(x_in, x, xh, xl, ROWS * Dm);

    for (int l = 0; l < Ll; l++) {
        const size_t o4 = (size_t)l * 4 * Dm * Dm;

        gemm16_qkv_kernel<<<dim3(Dm / 128, ROWS / 128, 3), 256, GEMM_SMEM>>>(
            xh, xl, wT4h + o4, wT4l + o4,
            bqp + l * Dm, bkp + l * Dm, bvp + l * Dm, Dm, Dm);

        const int qetot = Bq * Hh * Sq * NBb;
        qe_kernel<<<(qetot + 255) / 256, 256>>>(Erel + (size_t)l * NBb * DHd);

        attn_kernel<<<dim3(Sq / 64, Hh, Bq), 256, ATTN_SMEM>>>(Brel + (size_t)l * Hh * NBb, rid);

        gemm16_kernel<<<dim3(Dm / 128, ROWS / 128), 256, GEMM_SMEM>>>(
            ah, al, wT4h + o4 + (size_t)3 * Dm * Dm, wT4l + o4 + (size_t)3 * Dm * Dm,
            bop + l * Dm, x, y, nullptr, nullptr, Dm, Dm, 0);

        ln_kernel<<<ROWS, 256>>>(y, g1 + l * Dm, be1 + l * Dm, k, ffh, ffl);

        gemm16_kernel<<<dim3(Ff / 128, ROWS / 128), 256, GEMM_SMEM>>>(
            ffh, ffl, w1Th + (size_t)l * Ff * Dm, w1Tl + (size_t)l * Ff * Dm,
            b1 + l * Ff, nullptr, nullptr, hh, hl, Ff, Dm, 1);

        gemm16_kernel<<<dim3(Dm / 128, ROWS / 128), 256, GEMM_SMEM>>>(
            hh, hl, w2Th + (size_t)l * Dm * Ff, w2Tl + (size_t)l * Dm * Ff,
            b2 + l * Dm, k, v, nullptr, nullptr, Dm, Ff, 0);

        ln_kernel<<<ROWS, 256>>>(v, g2 + l * Dm, be2 + l * Dm,
                                 (l == Ll - 1) ? outp : x, xh, xl);
    }
}

// round 9
// speedup vs baseline: 1.1684x; 1.1684x over previous
#include <cuda_runtime.h>
#include <cuda_bf16.h>
#include <math_constants.h>
#include <cstdint>

// Problem constants
#define Bq   4
#define Sq   1024
#define Dm   1024
#define Hh   16
#define DHd  64
#define Ff   4096
#define NBb  33
#define Ll   6
#define ROWS (Bq*Sq)
#define SCALE_ATTN 0.125f

// ---------------- scratch (device globals) ----------------
__device__ float g_x [ROWS*Dm];
__device__ float g_y [ROWS*Dm];
__device__ float g_k [ROWS*Dm];
__device__ float g_v [ROWS*Dm];
__device__ float g_qe[Bq*Hh*Sq*NBb];

__device__ __nv_bfloat16 g_xh [ROWS*Dm], g_xl [ROWS*Dm];
__device__ __nv_bfloat16 g_ah [ROWS*Dm], g_al [ROWS*Dm];
__device__ __nv_bfloat16 g_ffh[ROWS*Dm], g_ffl[ROWS*Dm];
__device__ __nv_bfloat16 g_hh [ROWS*Ff], g_hl [ROWS*Ff];
__device__ __nv_bfloat16 g_qh [ROWS*Dm], g_ql [ROWS*Dm];
__device__ __nv_bfloat16 g_kh [ROWS*Dm], g_kl [ROWS*Dm];
__device__ __nv_bfloat16 g_vh [ROWS*Dm], g_vl [ROWS*Dm];

// transposed bf16 weights: [N][K]
__device__ __nv_bfloat16 g_wT4h[Ll*4*Dm*Dm], g_wT4l[Ll*4*Dm*Dm];
__device__ __nv_bfloat16 g_w1Th[Ll*Ff*Dm],  g_w1Tl[Ll*Ff*Dm];
__device__ __nv_bfloat16 g_w2Th[Ll*Dm*Ff],  g_w2Tl[Ll*Dm*Ff];

__device__ __forceinline__ void bsplit(float f, __nv_bfloat16& h, __nv_bfloat16& l) {
    h = __float2bfloat16_rn(f);
    l = __float2bfloat16_rn(f - __bfloat162float(h));
}

// ---------------- common asm helpers ----------------
__device__ __forceinline__ uint32_t s2u(const void* p) {
    uint32_t a;
    asm("{ .reg .u64 t; cvta.to.shared.u64 t, %1; cvt.u32.u64 %0, t; }" : "=r"(a) : "l"(p));
    return a;
}
__device__ __forceinline__ void cp16s(uint32_t s, const void* g) {
    asm volatile("cp.async.cg.shared.global [%0], [%1], 16;\n" :: "r"(s), "l"(g));
}
__device__ __forceinline__ void mma_bf16(float* c, const uint32_t* a, uint32_t b0, uint32_t b1) {
    asm volatile(
        "mma.sync.aligned.m16n8k16.row.col.f32.bf16.bf16.f32 "
        "{%0,%1,%2,%3}, {%4,%5,%6,%7}, {%8,%9}, {%0,%1,%2,%3};\n"
        : "+f"(c[0]), "+f"(c[1]), "+f"(c[2]), "+f"(c[3])
        : "r"(a[0]), "r"(a[1]), "r"(a[2]), "r"(a[3]), "r"(b0), "r"(b1));
}
__device__ __forceinline__ void ldsm4(uint32_t* r, uint32_t addr) {
    asm volatile("ldmatrix.sync.aligned.m8n8.x4.shared.b16 {%0,%1,%2,%3}, [%4];"
                 : "=r"(r[0]), "=r"(r[1]), "=r"(r[2]), "=r"(r[3]) : "r"(addr));
}
__device__ __forceinline__ void ldsm4t(uint32_t* r, uint32_t addr) {
    asm volatile("ldmatrix.sync.aligned.m8n8.x4.trans.shared.b16 {%0,%1,%2,%3}, [%4];"
                 : "=r"(r[0]), "=r"(r[1]), "=r"(r[2]), "=r"(r[3]) : "r"(addr));
}
__device__ __forceinline__ uint32_t pk_bf2(float a, float b) {
    __nv_bfloat162 t = __floats2bfloat162_rn(a, b);
    return *(uint32_t*)&t;
}

// ---------------- weight transpose + split ----------------
__global__ void wconv_kernel(const float* __restrict__ W,
                             __nv_bfloat16* __restrict__ Th, __nv_bfloat16* __restrict__ Tl,
                             int K, int N)
{
    __shared__ float t[32][33];
    int n0 = blockIdx.x * 32, k0 = blockIdx.y * 32;
    int tx = threadIdx.x, ty = threadIdx.y;
#pragma unroll
    for (int i = 0; i < 4; i++)
        t[ty + 8 * i][tx] = W[(size_t)(k0 + ty + 8 * i) * N + n0 + tx];
    __syncthreads();
#pragma unroll
    for (int i = 0; i < 4; i++) {
        float f = t[tx][ty + 8 * i];
        int n = n0 + ty + 8 * i, k = k0 + tx;
        __nv_bfloat16 h, l; bsplit(f, h, l);
        Th[(size_t)n * K + k] = h;
        Tl[(size_t)n * K + k] = l;
    }
}

// ---------------- copy + split ----------------
__global__ void copy_split_kernel(const float* __restrict__ in, float* __restrict__ out,
                                  __nv_bfloat16* __restrict__ oh, __nv_bfloat16* __restrict__ ol,
                                  int n)
{
    int i = blockIdx.x * blockDim.x + threadIdx.x;
    if (i < n) {
        float f = in[i];
        out[i] = f;
        __nv_bfloat16 h, l; bsplit(f, h, l);
        oh[i] = h; ol[i] = l;
    }
}

// =========================================================================
// bf16-split mma.sync GEMM (round-8, at HMMA roof)
// =========================================================================
#define PADk 40
#define STG  (128 * PADk)
#define GEMM_SMEM (2 * 4 * STG * 2)

__device__ __forceinline__ void gemm16_core(
    const __nv_bfloat16* __restrict__ Ah, const __nv_bfloat16* __restrict__ Al,
    const __nv_bfloat16* __restrict__ Bh, const __nv_bfloat16* __restrict__ Bl,
    const float* __restrict__ bias, const float* __restrict__ resid,
    float* __restrict__ C, __nv_bfloat16* __restrict__ Ch, __nv_bfloat16* __restrict__ Cl,
    int N, int K, bool relu)
{
    extern __shared__ __nv_bfloat16 smem[];
    const uint32_t smb = s2u(smem);

    const int tid  = threadIdx.x;
    const int lane = tid & 31;
    const int warp = tid >> 5;
    const int wm   = warp >> 1;
    const int wn   = warp & 1;
    const int g    = lane >> 2;
    const int tig  = lane & 3;

    const int bm = blockIdx.y * 128, bn = blockIdx.x * 128;

    const int prow = tid >> 1, kh = (tid & 1) * 16;
    const uint32_t soff = (uint32_t)(prow * PADk + kh) * 2;

    const __nv_bfloat16* gA0 = Ah + (size_t)(bm + prow) * K + kh;
    const __nv_bfloat16* gA1 = Al + (size_t)(bm + prow) * K + kh;
    const __nv_bfloat16* gB0 = Bh + (size_t)(bn + prow) * K + kh;
    const __nv_bfloat16* gB1 = Bl + (size_t)(bn + prow) * K + kh;

    const int mi = lane >> 3, li = lane & 7;
    const uint32_t aoff0 = (uint32_t)(((wm * 32 + (mi & 1) * 8 + li) * PADk) + (mi >> 1) * 8) * 2;
    const uint32_t boff0 = (uint32_t)(((wn * 64 + (mi >> 1) * 8 + li) * PADk) + (mi & 1) * 8) * 2;

    float acc[2][8][4];
#pragma unroll
    for (int i = 0; i < 2; i++)
#pragma unroll
        for (int j = 0; j < 8; j++)
#pragma unroll
            for (int c = 0; c < 4; c++) acc[i][j][c] = 0.f;

    const int nck = K >> 5;
    const uint32_t stageB = 4 * STG * 2;
    const uint32_t arrB   = STG * 2;

    {
        cp16s(smb + 0 * arrB + soff,      gA0);
        cp16s(smb + 0 * arrB + soff + 16, gA0 + 8);
        cp16s(smb + 1 * arrB + soff,      gA1);
        cp16s(smb + 1 * arrB + soff + 16, gA1 + 8);
        cp16s(smb + 2 * arrB + soff,      gB0);
        cp16s(smb + 2 * arrB + soff + 16, gB0 + 8);
        cp16s(smb + 3 * arrB + soff,      gB1);
        cp16s(smb + 3 * arrB + soff + 16, gB1 + 8);
        asm volatile("cp.async.commit_group;\n");
    }

    for (int kc = 0; kc < nck; kc++) {
        asm volatile("cp.async.wait_group 0;\n");
        __syncthreads();
        if (kc + 1 < nck) {
            const uint32_t sb = ((kc + 1) & 1) * stageB;
            const int go = (kc + 1) * 32;
            cp16s(smb + sb + 0 * arrB + soff,      gA0 + go);
            cp16s(smb + sb + 0 * arrB + soff + 16, gA0 + go + 8);
            cp16s(smb + sb + 1 * arrB + soff,      gA1 + go);
            cp16s(smb + sb + 1 * arrB + soff + 16, gA1 + go + 8);
            cp16s(smb + sb + 2 * arrB + soff,      gB0 + go);
            cp16s(smb + sb + 2 * arrB + soff + 16, gB0 + go + 8);
            cp16s(smb + sb + 3 * arrB + soff,      gB1 + go);
            cp16s(smb + sb + 3 * arrB + soff + 16, gB1 + go + 8);
            asm volatile("cp.async.commit_group;\n");
        }
        const uint32_t sb = (kc & 1) * stageB;
        const uint32_t aH = smb + sb + 0 * arrB + aoff0;
        const uint32_t aL = smb + sb + 1 * arrB + aoff0;
        const uint32_t bH = smb + sb + 2 * arrB + boff0;
        const uint32_t bL = smb + sb + 3 * arrB + boff0;

#pragma unroll
        for (int ks = 0; ks < 2; ks++) {
            const uint32_t ko = ks * 32;
            uint32_t ah[2][4], al[2][4];
            ldsm4(ah[0], aH + ko);
            ldsm4(ah[1], aH + 16 * PADk * 2 + ko);
            ldsm4(al[0], aL + ko);
            ldsm4(al[1], aL + 16 * PADk * 2 + ko);
#pragma unroll
            for (int p = 0; p < 4; p++) {
                uint32_t bh[4], bl[4];
                ldsm4(bh, bH + p * 16 * PADk * 2 + ko);
                ldsm4(bl, bL + p * 16 * PADk * 2 + ko);
#pragma unroll
                for (int q = 0; q < 2; q++) {
                    const int nf = 2 * p + q;
#pragma unroll
                    for (int mf = 0; mf < 2; mf++) {
                        mma_bf16(acc[mf][nf], ah[mf], bh[2 * q], bh[2 * q + 1]);
                        mma_bf16(acc[mf][nf], ah[mf], bl[2 * q], bl[2 * q + 1]);
                        mma_bf16(acc[mf][nf], al[mf], bh[2 * q], bh[2 * q + 1]);
                    }
                }
            }
        }
    }

#pragma unroll
    for (int mf = 0; mf < 2; mf++) {
#pragma unroll
        for (int nf = 0; nf < 8; nf++) {
            const int r0 = bm + wm * 32 + mf * 16 + g;
            const int cc = bn + wn * 64 + nf * 8 + 2 * tig;
            const float bs0 = bias[cc], bs1 = bias[cc + 1];
            float v0 = acc[mf][nf][0] + bs0;
            float v1 = acc[mf][nf][1] + bs1;
            float v2 = acc[mf][nf][2] + bs0;
            float v3 = acc[mf][nf][3] + bs1;
            const size_t i0 = (size_t)r0 * N + cc;
            const size_t i1 = (size_t)(r0 + 8) * N + cc;
            if (resid) {
                const float2 r0v = *(const float2*)(resid + i0);
                const float2 r1v = *(const float2*)(resid + i1);
                v0 += r0v.x; v1 += r0v.y; v2 += r1v.x; v3 += r1v.y;
            }
            if (relu) {
                v0 = fmaxf(v0, 0.f); v1 = fmaxf(v1, 0.f);
                v2 = fmaxf(v2, 0.f); v3 = fmaxf(v3, 0.f);
            }
            if (C) {
                *(float2*)(C + i0) = make_float2(v0, v1);
                *(float2*)(C + i1) = make_float2(v2, v3);
            }
            if (Ch) {
                __nv_bfloat16 h0, l0, h1, l1, h2, l2, h3, l3;
                bsplit(v0, h0, l0); bsplit(v1, h1, l1);
                bsplit(v2, h2, l2); bsplit(v3, h3, l3);
                *(__nv_bfloat162*)(Ch + i0) = __nv_bfloat162(h0, h1);
                *(__nv_bfloat162*)(Ch + i1) = __nv_bfloat162(h2, h3);
                *(__nv_bfloat162*)(Cl + i0) = __nv_bfloat162(l0, l1);
                *(__nv_bfloat162*)(Cl + i1) = __nv_bfloat162(l2, l3);
            }
        }
    }
}

__global__ __launch_bounds__(256) void gemm16_kernel(
    const __nv_bfloat16* __restrict__ Ah, const __nv_bfloat16* __restrict__ Al,
    const __nv_bfloat16* __restrict__ Bh, const __nv_bfloat16* __restrict__ Bl,
    const float* __restrict__ bias, const float* __restrict__ resid,
    float* __restrict__ C, __nv_bfloat16* __restrict__ Ch, __nv_bfloat16* __restrict__ Cl,
    int N, int K, int relu)
{
    gemm16_core(Ah, Al, Bh, Bl, bias, resid, C, Ch, Cl, N, K, relu != 0);
}

// QKV: z=0 -> fp32 y + qh/ql ; z=1 -> kh/kl ; z=2 -> vh/vl
__global__ __launch_bounds__(256) void gemm16_qkv_kernel(
    const __nv_bfloat16* __restrict__ Ah, const __nv_bfloat16* __restrict__ Al,
    const __nv_bfloat16* __restrict__ WTh, const __nv_bfloat16* __restrict__ WTl,
    const float* __restrict__ bq, const float* __restrict__ bk, const float* __restrict__ bv,
    int N, int K)
{
    const size_t off = (size_t)blockIdx.z * Dm * Dm;
    const float* bias; float* C; __nv_bfloat16 *Ch, *Cl;
    if      (blockIdx.z == 0) { bias = bq; C = g_y;     Ch = g_qh; Cl = g_ql; }
    else if (blockIdx.z == 1) { bias = bk; C = nullptr; Ch = g_kh; Cl = g_kl; }
    else                      { bias = bv; C = nullptr; Ch = g_vh; Cl = g_vl; }
    gemm16_core(Ah, Al, WTh + off, WTl + off, bias, nullptr, C, Ch, Cl, N, K, false);
}

// ---------------- qe = q @ Erel^T ----------------
__global__ void qe_kernel(const float* __restrict__ er)
{
    int idx = blockIdx.x * blockDim.x + threadIdx.x;
    const int total = Bq * Hh * Sq * NBb;
    if (idx >= total) return;
    int nb = idx % NBb;
    int s  = (idx / NBb) % Sq;
    int h  = (idx / (NBb * Sq)) % Hh;
    int b  =  idx / (NBb * Sq * Hh);
    const float* qr = g_y + ((size_t)(b * Sq + s)) * Dm + h * DHd;
    const float* e  = er + nb * DHd;
    float acc = 0.f;
#pragma unroll
    for (int d = 0; d < DHd; d++) acc = fmaf(qr[d], e[d], acc);
    g_qe[idx] = acc;
}

// =========================================================================
// MMA flash attention: 64q x 64k tiles, 4 warps, bf16 hi/lo split throughout
// =========================================================================
#define APITCH 72   // bf16 pitch: 64 data + 8 pad; 144B rows (16B aligned, ldsm conflict-free)

__global__ __launch_bounds__(128) void attn_kernel(const float* __restrict__ brel,
                                                   const int* __restrict__ rid)
{
    __shared__ __nv_bfloat16 Kh_s[64 * APITCH], Kl_s[64 * APITCH];
    __shared__ __nv_bfloat16 Vh_s[64 * APITCH], Vl_s[64 * APITCH];
    __shared__ float Cb[64 * NBb];

    const int tid = threadIdx.x, lane = tid & 31, w = tid >> 5;
    const int g = lane >> 2, tig = lane & 3;
    const int b = blockIdx.z, h = blockIdx.y;
    const int q0 = blockIdx.x * 64;

    const uint32_t kh_b = s2u(Kh_s), kl_b = s2u(Kl_s);
    const uint32_t vh_b = s2u(Vh_s), vl_b = s2u(Vl_s);
    const int mi = lane >> 3, li = lane & 7;

    // ---- stage Q tile into Kh_s/Kl_s, build Q fragments (kept in regs) ----
#pragma unroll
    for (int j = 0; j < 4; j++) {
        int chunk = tid + 128 * j;
        int r = chunk >> 3, c8 = chunk & 7;
        size_t go = ((size_t)(b * Sq + q0 + r)) * Dm + h * DHd + c8 * 8;
        uint32_t so = (uint32_t)(r * APITCH + c8 * 8) * 2;
        cp16s(kh_b + so, g_qh + go);
        cp16s(kl_b + so, g_ql + go);
    }
    asm volatile("cp.async.commit_group;\n cp.async.wait_group 0;\n");
    __syncthreads();

    uint32_t aqh[4][4], aql[4][4];
    {
        const int row = w * 16 + (mi & 1) * 8 + li;
#pragma unroll
        for (int ks = 0; ks < 4; ks++) {
            uint32_t off = (uint32_t)(row * APITCH + ks * 16 + (mi >> 1) * 8) * 2;
            ldsm4(aqh[ks], kh_b + off);
            ldsm4(aql[ks], kl_b + off);
        }
    }
    // combo table
    for (int i = tid; i < 64 * NBb; i += 128) {
        int r = i / NBb, nb = i - r * NBb;
        Cb[i] = g_qe[(((size_t)(b * Hh + h)) * Sq + q0 + r) * NBb + nb] + brel[h * NBb + nb];
    }
    __syncthreads();   // Q frags read; smem now free for K/V

    float m0 = -CUDART_INF_F, m1 = -CUDART_INF_F, l0 = 0.f, l1 = 0.f;
    float o[8][4];
#pragma unroll
    for (int i = 0; i < 8; i++)
#pragma unroll
        for (int c = 0; c < 4; c++) o[i][c] = 0.f;

    const int qr0 = w * 16 + g;       // local rows qr0, qr0+8
    const int grow0 = q0 + qr0;

    for (int k0 = 0; k0 < Sq; k0 += 64) {
        // load K,V hi/lo tiles
#pragma unroll
        for (int j = 0; j < 4; j++) {
            int chunk = tid + 128 * j;
            int r = chunk >> 3, c8 = chunk & 7;
            size_t go = ((size_t)(b * Sq + k0 + r)) * Dm + h * DHd + c8 * 8;
            uint32_t so = (uint32_t)(r * APITCH + c8 * 8) * 2;
            cp16s(kh_b + so, g_kh + go);
            cp16s(kl_b + so, g_kl + go);
            cp16s(vh_b + so, g_vh + go);
            cp16s(vl_b + so, g_vl + go);
        }
        asm volatile("cp.async.commit_group;\n cp.async.wait_group 0;\n");
        __syncthreads();

        // ---- S = Q K^T (3-MMA split) ----
        float s[8][4];
#pragma unroll
        for (int i = 0; i < 8; i++)
#pragma unroll
            for (int c = 0; c < 4; c++) s[i][c] = 0.f;

#pragma unroll
        for (int ks = 0; ks < 4; ks++) {
#pragma unroll
            for (int ntp = 0; ntp < 4; ntp++) {
                uint32_t bh[4], bl[4];
                uint32_t off = (uint32_t)((ntp * 16 + (mi >> 1) * 8 + li) * APITCH
                                          + ks * 16 + (mi & 1) * 8) * 2;
                ldsm4(bh, kh_b + off);
                ldsm4(bl, kl_b + off);
                mma_bf16(s[2 * ntp],     aqh[ks], bh[0], bh[1]);
                mma_bf16(s[2 * ntp],     aqh[ks], bl[0], bl[1]);
                mma_bf16(s[2 * ntp],     aql[ks], bh[0], bh[1]);
                mma_bf16(s[2 * ntp + 1], aqh[ks], bh[2], bh[3]);
                mma_bf16(s[2 * ntp + 1], aqh[ks], bl[2], bl[3]);
                mma_bf16(s[2 * ntp + 1], aql[ks], bh[2], bh[3]);
            }
        }

        // ---- rel terms + scale + online softmax in fragments ----
        float mt0 = -CUDART_INF_F, mt1 = -CUDART_INF_F;
#pragma unroll
        for (int nt = 0; nt < 8; nt++) {
            const int col = k0 + 8 * nt + 2 * tig;
            const int r0i = rid[(size_t)grow0 * Sq + col];
            const int r1i = rid[(size_t)grow0 * Sq + col + 1];
            const int r2i = rid[(size_t)(grow0 + 8) * Sq + col];
            const int r3i = rid[(size_t)(grow0 + 8) * Sq + col + 1];
            float v0 = (s[nt][0] + Cb[qr0 * NBb + r0i]) * SCALE_ATTN;
            float v1 = (s[nt][1] + Cb[qr0 * NBb + r1i]) * SCALE_ATTN;
            float v2 = (s[nt][2] + Cb[(qr0 + 8) * NBb + r2i]) * SCALE_ATTN;
            float v3 = (s[nt][3] + Cb[(qr0 + 8) * NBb + r3i]) * SCALE_ATTN;
            s[nt][0] = v0; s[nt][1] = v1; s[nt][2] = v2; s[nt][3] = v3;
            mt0 = fmaxf(mt0, fmaxf(v0, v1));
            mt1 = fmaxf(mt1, fmaxf(v2, v3));
        }
        mt0 = fmaxf(mt0, __shfl_xor_sync(0xffffffffu, mt0, 1));
        mt0 = fmaxf(mt0, __shfl_xor_sync(0xffffffffu, mt0, 2));
        mt1 = fmaxf(mt1, __shfl_xor_sync(0xffffffffu, mt1, 1));
        mt1 = fmaxf(mt1, __shfl_xor_sync(0xffffffffu, mt1, 2));

        const float mn0 = fmaxf(m0, mt0), mn1 = fmaxf(m1, mt1);
        const float fac0 = __expf(m0 - mn0), fac1 = __expf(m1 - mn1);
        float rs0 = 0.f, rs1 = 0.f;
#pragma unroll
        for (int nt = 0; nt < 8; nt++) {
            float p0 = __expf(s[nt][0] - mn0);
            float p1 = __expf(s[nt][1] - mn0);
            float p2 = __expf(s[nt][2] - mn1);
            float p3 = __expf(s[nt][3] - mn1);
            s[nt][0] = p0; s[nt][1] = p1; s[nt][2] = p2; s[nt][3] = p3;
            rs0 += p0 + p1; rs1 += p2 + p3;
        }
        rs0 += __shfl_xor_sync(0xffffffffu, rs0, 1);
        rs0 += __shfl_xor_sync(0xffffffffu, rs0, 2);
        rs1 += __shfl_xor_sync(0xffffffffu, rs1, 1);
        rs1 += __shfl_xor_sync(0xffffffffu, rs1, 2);
        l0 = l0 * fac0 + rs0;  m0 = mn0;
        l1 = l1 * fac1 + rs1;  m1 = mn1;
#pragma unroll
        for (int nt = 0; nt < 8; nt++) {
            o[nt][0] *= fac0; o[nt][1] *= fac0;
            o[nt][2] *= fac1; o[nt][3] *= fac1;
        }

        // ---- O += P V  (P re-split hi/lo in registers; V frags via trans-ldsm) ----
#pragma unroll
        for (int ks = 0; ks < 4; ks++) {
            uint32_t aph[4], apl[4];
            {
                float p00 = s[2 * ks][0],     p01 = s[2 * ks][1];
                float p10 = s[2 * ks][2],     p11 = s[2 * ks][3];
                float p20 = s[2 * ks + 1][0], p21 = s[2 * ks + 1][1];
                float p30 = s[2 * ks + 1][2], p31 = s[2 * ks + 1][3];
                __nv_bfloat16 hh, ll;
                float h00, h01, h10, h11, h20, h21, h30, h31;
                bsplit(p00, hh, ll); h00 = __bfloat162float(hh);
                bsplit(p01, hh, ll); h01 = __bfloat162float(hh);
                bsplit(p10, hh, ll); h10 = __bfloat162float(hh);
                bsplit(p11, hh, ll); h11 = __bfloat162float(hh);
                bsplit(p20, hh, ll); h20 = __bfloat162float(hh);
                bsplit(p21, hh, ll); h21 = __bfloat162float(hh);
                bsplit(p30, hh, ll); h30 = __bfloat162float(hh);
                bsplit(p31, hh, ll); h31 = __bfloat162float(hh);
                aph[0] = pk_bf2(h00, h01);
                aph[1] = pk_bf2(h10, h11);
                aph[2] = pk_bf2(h20, h21);
                aph[3] = pk_bf2(h30, h31);
                apl[0] = pk_bf2(p00 - h00, p01 - h01);
                apl[1] = pk_bf2(p10 - h10, p11 - h11);
                apl[2] = pk_bf2(p20 - h20, p21 - h21);
                apl[3] = pk_bf2(p30 - h30, p31 - h31);
            }
#pragma unroll
            for (int ntp = 0; ntp < 4; ntp++) {
                uint32_t vh[4], vl[4];
                uint32_t off = (uint32_t)((ks * 16 + (mi & 1) * 8 + li) * APITCH
                                          + (2 * ntp + (mi >> 1)) * 8) * 2;
                ldsm4t(vh, vh_b + off);
                ldsm4t(vl, vl_b + off);
                mma_bf16(o[2 * ntp],     aph, vh[0], vh[1]);
                mma_bf16(o[2 * ntp],     apl, vh[0], vh[1]);
                mma_bf16(o[2 * ntp],     aph, vl[0], vl[1]);
                mma_bf16(o[2 * ntp + 1], aph, vh[2], vh[3]);
                mma_bf16(o[2 * ntp + 1], apl, vh[2], vh[3]);
                mma_bf16(o[2 * ntp + 1], aph, vl[2], vl[3]);
            }
        }
        __syncthreads();   // all reads done before next tile's cp.async
    }

    // ---- epilogue: normalize, split, store bf16 hi/lo ----
    const float inv0 = 1.f / l0, inv1 = 1.f / l1;
#pragma unroll
    for (int nt = 0; nt < 8; nt++) {
        const int col = h * DHd + 8 * nt + 2 * tig;
        size_t i0 = ((size_t)(b * Sq) + grow0) * Dm + col;
        size_t i1 = ((size_t)(b * Sq) + grow0 + 8) * Dm + col;
        float v0 = o[nt][0] * inv0, v1 = o[nt][1] * inv0;
        float v2 = o[nt][2] * inv1, v3 = o[nt][3] * inv1;
        __nv_bfloat16 h0, e0, h1, e1, h2, e2, h3, e3;
        bsplit(v0, h0, e0); bsplit(v1, h1, e1);
        bsplit(v2, h2, e2); bsplit(v3, h3, e3);
        *(__nv_bfloat162*)(g_ah + i0) = __nv_bfloat162(h0, h1);
        *(__nv_bfloat162*)(g_al + i0) = __nv_bfloat162(e0, e1);
        *(__nv_bfloat162*)(g_ah + i1) = __nv_bfloat162(h2, h3);
        *(__nv_bfloat162*)(g_al + i1) = __nv_bfloat162(e2, e3);
    }
}

// ---------------- layernorm ----------------
__device__ __forceinline__ float block_sum_256(float val, float* sh) {
#pragma unroll
    for (int off = 16; off; off >>= 1) val += __shfl_xor_sync(0xffffffffu, val, off);
    if ((threadIdx.x & 31) == 0) sh[threadIdx.x >> 5] = val;
    __syncthreads();
    float t = 0.f;
    if (threadIdx.x < 8) t = sh[threadIdx.x];
    if (threadIdx.x < 32) {
#pragma unroll
        for (int off = 4; off; off >>= 1) t += __shfl_xor_sync(0xffffffffu, t, off);
        if (threadIdx.x == 0) sh[0] = t;
    }
    __syncthreads();
    float r = sh[0];
    __syncthreads();
    return r;
}

__global__ void ln_kernel(const float* __restrict__ in, const float* __restrict__ gam,
                          const float* __restrict__ bet, float* __restrict__ out,
                          __nv_bfloat16* __restrict__ oh, __nv_bfloat16* __restrict__ ol)
{
    __shared__ float sh[8];
    int row = blockIdx.x, tid = threadIdx.x;
    float4 x4 = ((const float4*)(in + (size_t)row * Dm))[tid];
    float s = x4.x + x4.y + x4.z + x4.w;
    float mean = block_sum_256(s, sh) * (1.f / Dm);
    float dx = x4.x - mean, dy = x4.y - mean, dz = x4.z - mean, dw = x4.w - mean;
    float s2 = dx * dx + dy * dy + dz * dz + dw * dw;
    float var = block_sum_256(s2, sh) * (1.f / Dm);
    float inv = rsqrtf(var + 1e-6f);
    int c = tid * 4;
    float4 o;
    o.x = dx * inv * gam[c + 0] + bet[c + 0];
    o.y = dy * inv * gam[c + 1] + bet[c + 1];
    o.z = dz * inv * gam[c + 2] + bet[c + 2];
    o.w = dw * inv * gam[c + 3] + bet[c + 3];
    ((float4*)(out + (size_t)row * Dm))[tid] = o;
    if (oh) {
        size_t base = (size_t)row * Dm + c;
        __nv_bfloat16 h0, l0, h1, l1, h2, l2, h3, l3;
        bsplit(o.x, h0, l0); bsplit(o.y, h1, l1);
        bsplit(o.z, h2, l2); bsplit(o.w, h3, l3);
        *(__nv_bfloat162*)(oh + base)     = __nv_bfloat162(h0, h1);
        *(__nv_bfloat162*)(oh + base + 2) = __nv_bfloat162(h2, h3);
        *(__nv_bfloat162*)(ol + base)     = __nv_bfloat162(l0, l1);
        *(__nv_bfloat162*)(ol + base + 2) = __nv_bfloat162(l2, l3);
    }
}

// ---------------- launch ----------------
extern "C" void kernel_launch(void* const* d_in, const int* in_sizes, int n_in,
                              void* d_out, int out_size)
{
    const float* x_in = (const float*)d_in[0];
    const int*   rid  = (const int*)  d_in[1];
    const float* Wq   = (const float*)d_in[2];
    const float* bqp  = (const float*)d_in[3];
    const float* Wk   = (const float*)d_in[4];
    const float* bkp  = (const float*)d_in[5];
    const float* Wv   = (const float*)d_in[6];
    const float* bvp  = (const float*)d_in[7];
    const float* Wo   = (const float*)d_in[8];
    const float* bop  = (const float*)d_in[9];
    const float* Erel = (const float*)d_in[10];
    const float* Brel = (const float*)d_in[11];
    const float* g1   = (const float*)d_in[12];
    const float* be1  = (const float*)d_in[13];
    const float* g2   = (const float*)d_in[14];
    const float* be2  = (const float*)d_in[15];
    const float* W1   = (const float*)d_in[16];
    const float* b1   = (const float*)d_in[17];
    const float* W2   = (const float*)d_in[18];
    const float* b2   = (const float*)d_in[19];
    float* outp = (float*)d_out;

    float *x, *y, *k, *v;
    __nv_bfloat16 *xh, *xl, *ah, *al, *ffh, *ffl, *hh, *hl;
    __nv_bfloat16 *wT4h, *wT4l, *w1Th, *w1Tl, *w2Th, *w2Tl;
    cudaGetSymbolAddress((void**)&x,  g_x);
    cudaGetSymbolAddress((void**)&y,  g_y);
    cudaGetSymbolAddress((void**)&k,  g_k);
    cudaGetSymbolAddress((void**)&v,  g_v);
    cudaGetSymbolAddress((void**)&xh, g_xh);  cudaGetSymbolAddress((void**)&xl, g_xl);
    cudaGetSymbolAddress((void**)&ah, g_ah);  cudaGetSymbolAddress((void**)&al, g_al);
    cudaGetSymbolAddress((void**)&ffh, g_ffh); cudaGetSymbolAddress((void**)&ffl, g_ffl);
    cudaGetSymbolAddress((void**)&hh, g_hh);  cudaGetSymbolAddress((void**)&hl, g_hl);
    cudaGetSymbolAddress((void**)&wT4h, g_wT4h); cudaGetSymbolAddress((void**)&wT4l, g_wT4l);
    cudaGetSymbolAddress((void**)&w1Th, g_w1Th); cudaGetSymbolAddress((void**)&w1Tl, g_w1Tl);
    cudaGetSymbolAddress((void**)&w2Th, g_w2Th); cudaGetSymbolAddress((void**)&w2Tl, g_w2Tl);

    cudaFuncSetAttribute(gemm16_kernel,     cudaFuncAttributeMaxDynamicSharedMemorySize, GEMM_SMEM);
    cudaFuncSetAttribute(gemm16_qkv_kernel, cudaFuncAttributeMaxDynamicSharedMemorySize, GEMM_SMEM);

    // ---- preconvert all weights ----
    const dim3 tb(32, 8);
    for (int l = 0; l < Ll; l++) {
        const size_t wdd = (size_t)l * Dm * Dm;
        const size_t o4  = (size_t)l * 4 * Dm * Dm;
        wconv_kernel<<<dim3(Dm / 32, Dm / 32), tb>>>(Wq + wdd, wT4h + o4,                   wT4l + o4,                   Dm, Dm);
        wconv_kernel<<<dim3(Dm / 32, Dm / 32), tb>>>(Wk + wdd, wT4h + o4 + (size_t)Dm*Dm,   wT4l + o4 + (size_t)Dm*Dm,   Dm, Dm);
        wconv_kernel<<<dim3(Dm / 32, Dm / 32), tb>>>(Wv + wdd, wT4h + o4 + (size_t)2*Dm*Dm, wT4l + o4 + (size_t)2*Dm*Dm, Dm, Dm);
        wconv_kernel<<<dim3(Dm / 32, Dm / 32), tb>>>(Wo + wdd, wT4h + o4 + (size_t)3*Dm*Dm, wT4l + o4 + (size_t)3*Dm*Dm, Dm, Dm);
        wconv_kernel<<<dim3(Ff / 32, Dm / 32), tb>>>(W1 + (size_t)l * Dm * Ff, w1Th + (size_t)l * Ff * Dm, w1Tl + (size_t)l * Ff * Dm, Dm, Ff);
        wconv_kernel<<<dim3(Dm / 32, Ff / 32), tb>>>(W2 + (size_t)l * Ff * Dm, w2Th + (size_t)l * Dm * Ff, w2Tl + (size_t)l * Dm * Ff, Ff, Dm);
    }

    copy_split_kernel<<<(ROWS * Dm + 255) / 256, 256>>>(x_in, x, xh, xl, ROWS * Dm);

    for (int l = 0; l < Ll; l++) {
        const size_t o4 = (size_t)l * 4 * Dm * Dm;

        gemm16_qkv_kernel<<<dim3(Dm / 128, ROWS / 128, 3), 256, GEMM_SMEM>>>(
            xh, xl, wT4h + o4, wT4l + o4,
            bqp + l * Dm, bkp + l * Dm, bvp + l * Dm, Dm, Dm);

        const int qetot = Bq * Hh * Sq * NBb;
        qe_kernel<<<(qetot + 255) / 256, 256>>>(Erel + (size_t)l * NBb * DHd);

        attn_kernel<<<dim3(Sq / 64, Hh, Bq), 128>>>(Brel + (size_t)l * Hh * NBb, rid);

        gemm16_kernel<<<dim3(Dm / 128, ROWS / 128), 256, GEMM_SMEM>>>(
            ah, al, wT4h + o4 + (size_t)3 * Dm * Dm, wT4l + o4 + (size_t)3 * Dm * Dm,
            bop + l * Dm, x, y, nullptr, nullptr, Dm, Dm, 0);

        ln_kernel<<<ROWS, 256>>>(y, g1 + l * Dm, be1 + l * Dm, k, ffh, ffl);

        gemm16_kernel<<<dim3(Ff / 128, ROWS / 128), 256, GEMM_SMEM>>>(
            ffh, ffl, w1Th + (size_t)l * Ff * Dm, w1Tl + (size_t)l * Ff * Dm,
            b1 + l * Ff, nullptr, nullptr, hh, hl, Ff, Dm, 1);

        gemm16_kernel<<<dim3(Dm / 128, ROWS / 128), 256, GEMM_SMEM>>>(
            hh, hl, w2Th + (size_t)l * Dm * Ff, w2Tl + (size_t)l * Dm * Ff,
            b2 + l * Dm, k, v, nullptr, nullptr, Dm, Ff, 0);

        ln_kernel<<<ROWS, 256>>>(v, g2 + l * Dm, be2 + l * Dm,
                                 (l == Ll - 1) ? outp : x, xh, xl);
    }
}

// round 10
// speedup vs baseline: 1.1924x; 1.0206x over previous
#include <cuda_runtime.h>
#include <cuda_bf16.h>
#include <cuda_fp16.h>
#include <math_constants.h>
#include <cstdint>

// Problem constants
#define Bq   4
#define Sq   1024
#define Dm   1024
#define Hh   16
#define DHd  64
#define Ff   4096
#define NBb  33
#define Ll   6
#define ROWS (Bq*Sq)
#define SCALE_ATTN 0.125f

// ---------------- scratch (device globals) ----------------
__device__ float g_x [ROWS*Dm];
__device__ float g_y [ROWS*Dm];
__device__ float g_k [ROWS*Dm];
__device__ float g_v [ROWS*Dm];
__device__ float g_qe[Bq*Hh*Sq*NBb];

__device__ __nv_bfloat16 g_xh [ROWS*Dm], g_xl [ROWS*Dm];
__device__ __nv_bfloat16 g_ah [ROWS*Dm], g_al [ROWS*Dm];
__device__ __nv_bfloat16 g_ffh[ROWS*Dm], g_ffl[ROWS*Dm];
__device__ __nv_bfloat16 g_hh [ROWS*Ff], g_hl [ROWS*Ff];
// fp16 attention operands
__device__ __half g_qh2[ROWS*Dm], g_ql2[ROWS*Dm];
__device__ __half g_kh2[ROWS*Dm];
__device__ __half g_vh2[ROWS*Dm], g_vl2[ROWS*Dm];

// transposed bf16 weights: [N][K]
__device__ __nv_bfloat16 g_wT4h[Ll*4*Dm*Dm], g_wT4l[Ll*4*Dm*Dm];
__device__ __nv_bfloat16 g_w1Th[Ll*Ff*Dm],  g_w1Tl[Ll*Ff*Dm];
__device__ __nv_bfloat16 g_w2Th[Ll*Dm*Ff],  g_w2Tl[Ll*Dm*Ff];

__device__ __forceinline__ void bsplit(float f, __nv_bfloat16& h, __nv_bfloat16& l) {
    h = __float2bfloat16_rn(f);
    l = __float2bfloat16_rn(f - __bfloat162float(h));
}
__device__ __forceinline__ void hsplit(float f, __half& h, __half& l) {
    h = __float2half_rn(f);
    l = __float2half_rn(f - __half2float(h));
}

// ---------------- common asm helpers ----------------
__device__ __forceinline__ uint32_t s2u(const void* p) {
    uint32_t a;
    asm("{ .reg .u64 t; cvta.to.shared.u64 t, %1; cvt.u32.u64 %0, t; }" : "=r"(a) : "l"(p));
    return a;
}
__device__ __forceinline__ void cp16s(uint32_t s, const void* g) {
    asm volatile("cp.async.cg.shared.global [%0], [%1], 16;\n" :: "r"(s), "l"(g));
}
__device__ __forceinline__ void mma_bf16(float* c, const uint32_t* a, uint32_t b0, uint32_t b1) {
    asm volatile(
        "mma.sync.aligned.m16n8k16.row.col.f32.bf16.bf16.f32 "
        "{%0,%1,%2,%3}, {%4,%5,%6,%7}, {%8,%9}, {%0,%1,%2,%3};\n"
        : "+f"(c[0]), "+f"(c[1]), "+f"(c[2]), "+f"(c[3])
        : "r"(a[0]), "r"(a[1]), "r"(a[2]), "r"(a[3]), "r"(b0), "r"(b1));
}
__device__ __forceinline__ void mma_f16(float* c, const uint32_t* a, uint32_t b0, uint32_t b1) {
    asm volatile(
        "mma.sync.aligned.m16n8k16.row.col.f32.f16.f16.f32 "
        "{%0,%1,%2,%3}, {%4,%5,%6,%7}, {%8,%9}, {%0,%1,%2,%3};\n"
        : "+f"(c[0]), "+f"(c[1]), "+f"(c[2]), "+f"(c[3])
        : "r"(a[0]), "r"(a[1]), "r"(a[2]), "r"(a[3]), "r"(b0), "r"(b1));
}
__device__ __forceinline__ void ldsm4(uint32_t* r, uint32_t addr) {
    asm volatile("ldmatrix.sync.aligned.m8n8.x4.shared.b16 {%0,%1,%2,%3}, [%4];"
                 : "=r"(r[0]), "=r"(r[1]), "=r"(r[2]), "=r"(r[3]) : "r"(addr));
}
__device__ __forceinline__ void ldsm4t(uint32_t* r, uint32_t addr) {
    asm volatile("ldmatrix.sync.aligned.m8n8.x4.trans.shared.b16 {%0,%1,%2,%3}, [%4];"
                 : "=r"(r[0]), "=r"(r[1]), "=r"(r[2]), "=r"(r[3]) : "r"(addr));
}
__device__ __forceinline__ uint32_t pk_h2(float a, float b) {
    __half2 t = __floats2half2_rn(a, b);
    return *(uint32_t*)&t;
}

// ---------------- weight transpose + split ----------------
__global__ void wconv_kernel(const float* __restrict__ W,
                             __nv_bfloat16* __restrict__ Th, __nv_bfloat16* __restrict__ Tl,
                             int K, int N)
{
    __shared__ float t[32][33];
    int n0 = blockIdx.x * 32, k0 = blockIdx.y * 32;
    int tx = threadIdx.x, ty = threadIdx.y;
#pragma unroll
    for (int i = 0; i < 4; i++)
        t[ty + 8 * i][tx] = W[(size_t)(k0 + ty + 8 * i) * N + n0 + tx];
    __syncthreads();
#pragma unroll
    for (int i = 0; i < 4; i++) {
        float f = t[tx][ty + 8 * i];
        int n = n0 + ty + 8 * i, k = k0 + tx;
        __nv_bfloat16 h, l; bsplit(f, h, l);
        Th[(size_t)n * K + k] = h;
        Tl[(size_t)n * K + k] = l;
    }
}

// ---------------- copy + split ----------------
__global__ void copy_split_kernel(const float* __restrict__ in, float* __restrict__ out,
                                  __nv_bfloat16* __restrict__ oh, __nv_bfloat16* __restrict__ ol,
                                  int n)
{
    int i = blockIdx.x * blockDim.x + threadIdx.x;
    if (i < n) {
        float f = in[i];
        out[i] = f;
        __nv_bfloat16 h, l; bsplit(f, h, l);
        oh[i] = h; ol[i] = l;
    }
}

// =========================================================================
// bf16-split mma.sync GEMM (at HMMA roof); epilogue can also emit fp16 hi/lo
// =========================================================================
#define PADk 40
#define STG  (128 * PADk)
#define GEMM_SMEM (2 * 4 * STG * 2)

__device__ __forceinline__ void gemm16_core(
    const __nv_bfloat16* __restrict__ Ah, const __nv_bfloat16* __restrict__ Al,
    const __nv_bfloat16* __restrict__ Bh, const __nv_bfloat16* __restrict__ Bl,
    const float* __restrict__ bias, const float* __restrict__ resid,
    float* __restrict__ C, __nv_bfloat16* __restrict__ Ch, __nv_bfloat16* __restrict__ Cl,
    __half* __restrict__ Hho, __half* __restrict__ Hlo,
    int N, int K, bool relu)
{
    extern __shared__ __nv_bfloat16 smem[];
    const uint32_t smb = s2u(smem);

    const int tid  = threadIdx.x;
    const int lane = tid & 31;
    const int warp = tid >> 5;
    const int wm   = warp >> 1;
    const int wn   = warp & 1;
    const int g    = lane >> 2;
    const int tig  = lane & 3;

    const int bm = blockIdx.y * 128, bn = blockIdx.x * 128;

    const int prow = tid >> 1, kh = (tid & 1) * 16;
    const uint32_t soff = (uint32_t)(prow * PADk + kh) * 2;

    const __nv_bfloat16* gA0 = Ah + (size_t)(bm + prow) * K + kh;
    const __nv_bfloat16* gA1 = Al + (size_t)(bm + prow) * K + kh;
    const __nv_bfloat16* gB0 = Bh + (size_t)(bn + prow) * K + kh;
    const __nv_bfloat16* gB1 = Bl + (size_t)(bn + prow) * K + kh;

    const int mi = lane >> 3, li = lane & 7;
    const uint32_t aoff0 = (uint32_t)(((wm * 32 + (mi & 1) * 8 + li) * PADk) + (mi >> 1) * 8) * 2;
    const uint32_t boff0 = (uint32_t)(((wn * 64 + (mi >> 1) * 8 + li) * PADk) + (mi & 1) * 8) * 2;

    float acc[2][8][4];
#pragma unroll
    for (int i = 0; i < 2; i++)
#pragma unroll
        for (int j = 0; j < 8; j++)
#pragma unroll
            for (int c = 0; c < 4; c++) acc[i][j][c] = 0.f;

    const int nck = K >> 5;
    const uint32_t stageB = 4 * STG * 2;
    const uint32_t arrB   = STG * 2;

    {
        cp16s(smb + 0 * arrB + soff,      gA0);
        cp16s(smb + 0 * arrB + soff + 16, gA0 + 8);
        cp16s(smb + 1 * arrB + soff,      gA1);
        cp16s(smb + 1 * arrB + soff + 16, gA1 + 8);
        cp16s(smb + 2 * arrB + soff,      gB0);
        cp16s(smb + 2 * arrB + soff + 16, gB0 + 8);
        cp16s(smb + 3 * arrB + soff,      gB1);
        cp16s(smb + 3 * arrB + soff + 16, gB1 + 8);
        asm volatile("cp.async.commit_group;\n");
    }

    for (int kc = 0; kc < nck; kc++) {
        asm volatile("cp.async.wait_group 0;\n");
        __syncthreads();
        if (kc + 1 < nck) {
            const uint32_t sb = ((kc + 1) & 1) * stageB;
            const int go = (kc + 1) * 32;
            cp16s(smb + sb + 0 * arrB + soff,      gA0 + go);
            cp16s(smb + sb + 0 * arrB + soff + 16, gA0 + go + 8);
            cp16s(smb + sb + 1 * arrB + soff,      gA1 + go);
            cp16s(smb + sb + 1 * arrB + soff + 16, gA1 + go + 8);
            cp16s(smb + sb + 2 * arrB + soff,      gB0 + go);
            cp16s(smb + sb + 2 * arrB + soff + 16, gB0 + go + 8);
            cp16s(smb + sb + 3 * arrB + soff,      gB1 + go);
            cp16s(smb + sb + 3 * arrB + soff + 16, gB1 + go + 8);
            asm volatile("cp.async.commit_group;\n");
        }
        const uint32_t sb = (kc & 1) * stageB;
        const uint32_t aH = smb + sb + 0 * arrB + aoff0;
        const uint32_t aL = smb + sb + 1 * arrB + aoff0;
        const uint32_t bH = smb + sb + 2 * arrB + boff0;
        const uint32_t bL = smb + sb + 3 * arrB + boff0;

#pragma unroll
        for (int ks = 0; ks < 2; ks++) {
            const uint32_t ko = ks * 32;
            uint32_t ah[2][4], al[2][4];
            ldsm4(ah[0], aH + ko);
            ldsm4(ah[1], aH + 16 * PADk * 2 + ko);
            ldsm4(al[0], aL + ko);
            ldsm4(al[1], aL + 16 * PADk * 2 + ko);
#pragma unroll
            for (int p = 0; p < 4; p++) {
                uint32_t bh[4], bl[4];
                ldsm4(bh, bH + p * 16 * PADk * 2 + ko);
                ldsm4(bl, bL + p * 16 * PADk * 2 + ko);
#pragma unroll
                for (int q = 0; q < 2; q++) {
                    const int nf = 2 * p + q;
#pragma unroll
                    for (int mf = 0; mf < 2; mf++) {
                        mma_bf16(acc[mf][nf], ah[mf], bh[2 * q], bh[2 * q + 1]);
                        mma_bf16(acc[mf][nf], ah[mf], bl[2 * q], bl[2 * q + 1]);
                        mma_bf16(acc[mf][nf], al[mf], bh[2 * q], bh[2 * q + 1]);
                    }
                }
            }
        }
    }

#pragma unroll
    for (int mf = 0; mf < 2; mf++) {
#pragma unroll
        for (int nf = 0; nf < 8; nf++) {
            const int r0 = bm + wm * 32 + mf * 16 + g;
            const int cc = bn + wn * 64 + nf * 8 + 2 * tig;
            const float bs0 = bias[cc], bs1 = bias[cc + 1];
            float v0 = acc[mf][nf][0] + bs0;
            float v1 = acc[mf][nf][1] + bs1;
            float v2 = acc[mf][nf][2] + bs0;
            float v3 = acc[mf][nf][3] + bs1;
            const size_t i0 = (size_t)r0 * N + cc;
            const size_t i1 = (size_t)(r0 + 8) * N + cc;
            if (resid) {
                const float2 r0v = *(const float2*)(resid + i0);
                const float2 r1v = *(const float2*)(resid + i1);
                v0 += r0v.x; v1 += r0v.y; v2 += r1v.x; v3 += r1v.y;
            }
            if (relu) {
                v0 = fmaxf(v0, 0.f); v1 = fmaxf(v1, 0.f);
                v2 = fmaxf(v2, 0.f); v3 = fmaxf(v3, 0.f);
            }
            if (C) {
                *(float2*)(C + i0) = make_float2(v0, v1);
                *(float2*)(C + i1) = make_float2(v2, v3);
            }
            if (Ch) {
                __nv_bfloat16 h0, l0, h1, l1, h2, l2, h3, l3;
                bsplit(v0, h0, l0); bsplit(v1, h1, l1);
                bsplit(v2, h2, l2); bsplit(v3, h3, l3);
                *(__nv_bfloat162*)(Ch + i0) = __nv_bfloat162(h0, h1);
                *(__nv_bfloat162*)(Ch + i1) = __nv_bfloat162(h2, h3);
                *(__nv_bfloat162*)(Cl + i0) = __nv_bfloat162(l0, l1);
                *(__nv_bfloat162*)(Cl + i1) = __nv_bfloat162(l2, l3);
            }
            if (Hho) {
                if (Hlo) {
                    __half h0, l0, h1, l1, h2, l2, h3, l3;
                    hsplit(v0, h0, l0); hsplit(v1, h1, l1);
                    hsplit(v2, h2, l2); hsplit(v3, h3, l3);
                    *(__half2*)(Hho + i0) = __half2(h0, h1);
                    *(__half2*)(Hho + i1) = __half2(h2, h3);
                    *(__half2*)(Hlo + i0) = __half2(l0, l1);
                    *(__half2*)(Hlo + i1) = __half2(l2, l3);
                } else {
                    *(__half2*)(Hho + i0) = __floats2half2_rn(v0, v1);
                    *(__half2*)(Hho + i1) = __floats2half2_rn(v2, v3);
                }
            }
        }
    }
}

__global__ __launch_bounds__(256) void gemm16_kernel(
    const __nv_bfloat16* __restrict__ Ah, const __nv_bfloat16* __restrict__ Al,
    const __nv_bfloat16* __restrict__ Bh, const __nv_bfloat16* __restrict__ Bl,
    const float* __restrict__ bias, const float* __restrict__ resid,
    float* __restrict__ C, __nv_bfloat16* __restrict__ Ch, __nv_bfloat16* __restrict__ Cl,
    int N, int K, int relu)
{
    gemm16_core(Ah, Al, Bh, Bl, bias, resid, C, Ch, Cl, nullptr, nullptr, N, K, relu != 0);
}

// QKV: z=0 -> fp32 y + fp16 q hi/lo ; z=1 -> fp16 k hi ; z=2 -> fp16 v hi/lo
__global__ __launch_bounds__(256) void gemm16_qkv_kernel(
    const __nv_bfloat16* __restrict__ Ah, const __nv_bfloat16* __restrict__ Al,
    const __nv_bfloat16* __restrict__ WTh, const __nv_bfloat16* __restrict__ WTl,
    const float* __restrict__ bq, const float* __restrict__ bk, const float* __restrict__ bv,
    int N, int K)
{
    const size_t off = (size_t)blockIdx.z * Dm * Dm;
    const float* bias; float* C; __half *Hho, *Hlo;
    if      (blockIdx.z == 0) { bias = bq; C = g_y;     Hho = g_qh2; Hlo = g_ql2; }
    else if (blockIdx.z == 1) { bias = bk; C = nullptr; Hho = g_kh2; Hlo = nullptr; }
    else                      { bias = bv; C = nullptr; Hho = g_vh2; Hlo = g_vl2; }
    gemm16_core(Ah, Al, WTh + off, WTl + off, bias, nullptr, C, nullptr, nullptr, Hho, Hlo, N, K, false);
}

// ---------------- qe = q @ Erel^T ----------------
__global__ void qe_kernel(const float* __restrict__ er)
{
    int idx = blockIdx.x * blockDim.x + threadIdx.x;
    const int total = Bq * Hh * Sq * NBb;
    if (idx >= total) return;
    int nb = idx % NBb;
    int s  = (idx / NBb) % Sq;
    int h  = (idx / (NBb * Sq)) % Hh;
    int b  =  idx / (NBb * Sq * Hh);
    const float* qr = g_y + ((size_t)(b * Sq + s)) * Dm + h * DHd;
    const float* e  = er + nb * DHd;
    float acc = 0.f;
#pragma unroll
    for (int d = 0; d < DHd; d++) acc = fmaf(qr[d], e[d], acc);
    g_qe[idx] = acc;
}

// =========================================================================
// MMA flash attention (fp16): S = Qh*K + Ql*K ; PV = P*Vh + P*Vl
// 64q x 64k tiles, 4 warps. K single fp16; Q,V fp16 hi/lo; P single fp16.
// =========================================================================
#define APITCH 72

__global__ __launch_bounds__(128) void attn_kernel(const float* __restrict__ brel,
                                                   const int* __restrict__ rid)
{
    __shared__ __half Kh_s[64 * APITCH];   // K; also Q-hi staging
    __shared__ __half Vh_s[64 * APITCH];   // V hi; also Q-lo staging
    __shared__ __half Vl_s[64 * APITCH];   // V lo
    __shared__ float Cb[64 * NBb];

    const int tid = threadIdx.x, lane = tid & 31, w = tid >> 5;
    const int g = lane >> 2, tig = lane & 3;
    const int b = blockIdx.z, h = blockIdx.y;
    const int q0 = blockIdx.x * 64;

    const uint32_t kh_b = s2u(Kh_s), vh_b = s2u(Vh_s), vl_b = s2u(Vl_s);
    const int mi = lane >> 3, li = lane & 7;

    // ---- stage Q hi/lo, build fragments ----
#pragma unroll
    for (int j = 0; j < 4; j++) {
        int chunk = tid + 128 * j;
        int r = chunk >> 3, c8 = chunk & 7;
        size_t go = ((size_t)(b * Sq + q0 + r)) * Dm + h * DHd + c8 * 8;
        uint32_t so = (uint32_t)(r * APITCH + c8 * 8) * 2;
        cp16s(kh_b + so, g_qh2 + go);
        cp16s(vh_b + so, g_ql2 + go);
    }
    asm volatile("cp.async.commit_group;\n cp.async.wait_group 0;\n");
    __syncthreads();

    uint32_t aqh[4][4], aql[4][4];
    {
        const int row = w * 16 + (mi & 1) * 8 + li;
#pragma unroll
        for (int ks = 0; ks < 4; ks++) {
            uint32_t off = (uint32_t)(row * APITCH + ks * 16 + (mi >> 1) * 8) * 2;
            ldsm4(aqh[ks], kh_b + off);
            ldsm4(aql[ks], vh_b + off);
        }
    }
    for (int i = tid; i < 64 * NBb; i += 128) {
        int r = i / NBb, nb = i - r * NBb;
        Cb[i] = g_qe[(((size_t)(b * Hh + h)) * Sq + q0 + r) * NBb + nb] + brel[h * NBb + nb];
    }
    __syncthreads();

    float m0 = -CUDART_INF_F, m1 = -CUDART_INF_F, l0 = 0.f, l1 = 0.f;
    float o[8][4];
#pragma unroll
    for (int i = 0; i < 8; i++)
#pragma unroll
        for (int c = 0; c < 4; c++) o[i][c] = 0.f;

    const int qr0 = w * 16 + g;
    const int grow0 = q0 + qr0;

    for (int k0 = 0; k0 < Sq; k0 += 64) {
#pragma unroll
        for (int j = 0; j < 4; j++) {
            int chunk = tid + 128 * j;
            int r = chunk >> 3, c8 = chunk & 7;
            size_t go = ((size_t)(b * Sq + k0 + r)) * Dm + h * DHd + c8 * 8;
            uint32_t so = (uint32_t)(r * APITCH + c8 * 8) * 2;
            cp16s(kh_b + so, g_kh2 + go);
            cp16s(vh_b + so, g_vh2 + go);
            cp16s(vl_b + so, g_vl2 + go);
        }
        asm volatile("cp.async.commit_group;\n cp.async.wait_group 0;\n");
        __syncthreads();

        // ---- S = Qh*K + Ql*K ----
        float s[8][4];
#pragma unroll
        for (int i = 0; i < 8; i++)
#pragma unroll
            for (int c = 0; c < 4; c++) s[i][c] = 0.f;

#pragma unroll
        for (int ks = 0; ks < 4; ks++) {
#pragma unroll
            for (int ntp = 0; ntp < 4; ntp++) {
                uint32_t kb[4];
                uint32_t off = (uint32_t)((ntp * 16 + (mi >> 1) * 8 + li) * APITCH
                                          + ks * 16 + (mi & 1) * 8) * 2;
                ldsm4(kb, kh_b + off);
                mma_f16(s[2 * ntp],     aqh[ks], kb[0], kb[1]);
                mma_f16(s[2 * ntp],     aql[ks], kb[0], kb[1]);
                mma_f16(s[2 * ntp + 1], aqh[ks], kb[2], kb[3]);
                mma_f16(s[2 * ntp + 1], aql[ks], kb[2], kb[3]);
            }
        }

        // ---- rel terms + scale + online softmax ----
        float mt0 = -CUDART_INF_F, mt1 = -CUDART_INF_F;
#pragma unroll
        for (int nt = 0; nt < 8; nt++) {
            const int col = k0 + 8 * nt + 2 * tig;
            const int r0i = rid[(size_t)grow0 * Sq + col];
            const int r1i = rid[(size_t)grow0 * Sq + col + 1];
            const int r2i = rid[(size_t)(grow0 + 8) * Sq + col];
            const int r3i = rid[(size_t)(grow0 + 8) * Sq + col + 1];
            float v0 = (s[nt][0] + Cb[qr0 * NBb + r0i]) * SCALE_ATTN;
            float v1 = (s[nt][1] + Cb[qr0 * NBb + r1i]) * SCALE_ATTN;
            float v2 = (s[nt][2] + Cb[(qr0 + 8) * NBb + r2i]) * SCALE_ATTN;
            float v3 = (s[nt][3] + Cb[(qr0 + 8) * NBb + r3i]) * SCALE_ATTN;
            s[nt][0] = v0; s[nt][1] = v1; s[nt][2] = v2; s[nt][3] = v3;
            mt0 = fmaxf(mt0, fmaxf(v0, v1));
            mt1 = fmaxf(mt1, fmaxf(v2, v3));
        }
        mt0 = fmaxf(mt0, __shfl_xor_sync(0xffffffffu, mt0, 1));
        mt0 = fmaxf(mt0, __shfl_xor_sync(0xffffffffu, mt0, 2));
        mt1 = fmaxf(mt1, __shfl_xor_sync(0xffffffffu, mt1, 1));
        mt1 = fmaxf(mt1, __shfl_xor_sync(0xffffffffu, mt1, 2));

        const float mn0 = fmaxf(m0, mt0), mn1 = fmaxf(m1, mt1);
        const float fac0 = __expf(m0 - mn0), fac1 = __expf(m1 - mn1);
        float rs0 = 0.f, rs1 = 0.f;
#pragma unroll
        for (int nt = 0; nt < 8; nt++) {
            float p0 = __expf(s[nt][0] - mn0);
            float p1 = __expf(s[nt][1] - mn0);
            float p2 = __expf(s[nt][2] - mn1);
            float p3 = __expf(s[nt][3] - mn1);
            s[nt][0] = p0; s[nt][1] = p1; s[nt][2] = p2; s[nt][3] = p3;
            rs0 += p0 + p1; rs1 += p2 + p3;
        }
        rs0 += __shfl_xor_sync(0xffffffffu, rs0, 1);
        rs0 += __shfl_xor_sync(0xffffffffu, rs0, 2);
        rs1 += __shfl_xor_sync(0xffffffffu, rs1, 1);
        rs1 += __shfl_xor_sync(0xffffffffu, rs1, 2);
        l0 = l0 * fac0 + rs0;  m0 = mn0;
        l1 = l1 * fac1 + rs1;  m1 = mn1;
#pragma unroll
        for (int nt = 0; nt < 8; nt++) {
            o[nt][0] *= fac0; o[nt][1] *= fac0;
            o[nt][2] *= fac1; o[nt][3] *= fac1;
        }

        // ---- O += P V (P single fp16; V hi/lo) ----
#pragma unroll
        for (int ks = 0; ks < 4; ks++) {
            uint32_t ap[4];
            ap[0] = pk_h2(s[2 * ks][0],     s[2 * ks][1]);
            ap[1] = pk_h2(s[2 * ks][2],     s[2 * ks][3]);
            ap[2] = pk_h2(s[2 * ks + 1][0], s[2 * ks + 1][1]);
            ap[3] = pk_h2(s[2 * ks + 1][2], s[2 * ks + 1][3]);
#pragma unroll
            for (int ntp = 0; ntp < 4; ntp++) {
                uint32_t vh[4], vl[4];
                uint32_t off = (uint32_t)((ks * 16 + (mi & 1) * 8 + li) * APITCH
                                          + (2 * ntp + (mi >> 1)) * 8) * 2;
                ldsm4t(vh, vh_b + off);
                ldsm4t(vl, vl_b + off);
                mma_f16(o[2 * ntp],     ap, vh[0], vh[1]);
                mma_f16(o[2 * ntp],     ap, vl[0], vl[1]);
                mma_f16(o[2 * ntp + 1], ap, vh[2], vh[3]);
                mma_f16(o[2 * ntp + 1], ap, vl[2], vl[3]);
            }
        }
        __syncthreads();
    }

    // ---- epilogue: normalize, split, store bf16 hi/lo ----
    const float inv0 = 1.f / l0, inv1 = 1.f / l1;
#pragma unroll
    for (int nt = 0; nt < 8; nt++) {
        const int col = h * DHd + 8 * nt + 2 * tig;
        size_t i0 = ((size_t)(b * Sq) + grow0) * Dm + col;
        size_t i1 = ((size_t)(b * Sq) + grow0 + 8) * Dm + col;
        float v0 = o[nt][0] * inv0, v1 = o[nt][1] * inv0;
        float v2 = o[nt][2] * inv1, v3 = o[nt][3] * inv1;
        __nv_bfloat16 h0, e0, h1, e1, h2, e2, h3, e3;
        bsplit(v0, h0, e0); bsplit(v1, h1, e1);
        bsplit(v2, h2, e2); bsplit(v3, h3, e3);
        *(__nv_bfloat162*)(g_ah + i0) = __nv_bfloat162(h0, h1);
        *(__nv_bfloat162*)(g_al + i0) = __nv_bfloat162(e0, e1);
        *(__nv_bfloat162*)(g_ah + i1) = __nv_bfloat162(h2, h3);
        *(__nv_bfloat162*)(g_al + i1) = __nv_bfloat162(e2, e3);
    }
}

// ---------------- layernorm ----------------
__device__ __forceinline__ float block_sum_256(float val, float* sh) {
#pragma unroll
    for (int off = 16; off; off >>= 1) val += __shfl_xor_sync(0xffffffffu, val, off);
    if ((threadIdx.x & 31) == 0) sh[threadIdx.x >> 5] = val;
    __syncthreads();
    float t = 0.f;
    if (threadIdx.x < 8) t = sh[threadIdx.x];
    if (threadIdx.x < 32) {
#pragma unroll
        for (int off = 4; off; off >>= 1) t += __shfl_xor_sync(0xffffffffu, t, off);
        if (threadIdx.x == 0) sh[0] = t;
    }
    __syncthreads();
    float r = sh[0];
    __syncthreads();
    return r;
}

__global__ void ln_kernel(const float* __restrict__ in, const float* __restrict__ gam,
                          const float* __restrict__ bet, float* __restrict__ out,
                          __nv_bfloat16* __restrict__ oh, __nv_bfloat16* __restrict__ ol)
{
    __shared__ float sh[8];
    int row = blockIdx.x, tid = threadIdx.x;
    float4 x4 = ((const float4*)(in + (size_t)row * Dm))[tid];
    float s = x4.x + x4.y + x4.z + x4.w;
    float mean = block_sum_256(s, sh) * (1.f / Dm);
    float dx = x4.x - mean, dy = x4.y - mean, dz = x4.z - mean, dw = x4.w - mean;
    float s2 = dx * dx + dy * dy + dz * dz + dw * dw;
    float var = block_sum_256(s2, sh) * (1.f / Dm);
    float inv = rsqrtf(var + 1e-6f);
    int c = tid * 4;
    float4 o;
    o.x = dx * inv * gam[c + 0] + bet[c + 0];
    o.y = dy * inv * gam[c + 1] + bet[c + 1];
    o.z = dz * inv * gam[c + 2] + bet[c + 2];
    o.w = dw * inv * gam[c + 3] + bet[c + 3];
    ((float4*)(out + (size_t)row * Dm))[tid] = o;
    if (oh) {
        size_t base = (size_t)row * Dm + c;
        __nv_bfloat16 h0, l0, h1, l1, h2, l2, h3, l3;
        bsplit(o.x, h0, l0); bsplit(o.y, h1, l1);
        bsplit(o.z, h2, l2); bsplit(o.w, h3, l3);
        *(__nv_bfloat162*)(oh + base)     = __nv_bfloat162(h0, h1);
        *(__nv_bfloat162*)(oh + base + 2) = __nv_bfloat162(h2, h3);
        *(__nv_bfloat162*)(ol + base)     = __nv_bfloat162(l0, l1);
        *(__nv_bfloat162*)(ol + base + 2) = __nv_bfloat162(l2, l3);
    }
}

// ---------------- launch ----------------
extern "C" void kernel_launch(void* const* d_in, const int* in_sizes, int n_in,
                              void* d_out, int out_size)
{
    const float* x_in = (const float*)d_in[0];
    const int*   rid  = (const int*)  d_in[1];
    const float* Wq   = (const float*)d_in[2];
    const float* bqp  = (const float*)d_in[3];
    const float* Wk   = (const float*)d_in[4];
    const float* bkp  = (const float*)d_in[5];
    const float* Wv   = (const float*)d_in[6];
    const float* bvp  = (const float*)d_in[7];
    const float* Wo   = (const float*)d_in[8];
    const float* bop  = (const float*)d_in[9];
    const float* Erel = (const float*)d_in[10];
    const float* Brel = (const float*)d_in[11];
    const float* g1   = (const float*)d_in[12];
    const float* be1  = (const float*)d_in[13];
    const float* g2   = (const float*)d_in[14];
    const float* be2  = (const float*)d_in[15];
    const float* W1   = (const float*)d_in[16];
    const float* b1   = (const float*)d_in[17];
    const float* W2   = (const float*)d_in[18];
    const float* b2   = (const float*)d_in[19];
    float* outp = (float*)d_out;

    float *x, *y, *k, *v;
    __nv_bfloat16 *xh, *xl, *ah, *al, *ffh, *ffl, *hh, *hl;
    __nv_bfloat16 *wT4h, *wT4l, *w1Th, *w1Tl, *w2Th, *w2Tl;
    cudaGetSymbolAddress((void**)&x,  g_x);
    cudaGetSymbolAddress((void**)&y,  g_y);
    cudaGetSymbolAddress((void**)&k,  g_k);
    cudaGetSymbolAddress((void**)&v,  g_v);
    cudaGetSymbolAddress((void**)&xh, g_xh);  cudaGetSymbolAddress((void**)&xl, g_xl);
    cudaGetSymbolAddress((void**)&ah, g_ah);  cudaGetSymbolAddress((void**)&al, g_al);
    cudaGetSymbolAddress((void**)&ffh, g_ffh); cudaGetSymbolAddress((void**)&ffl, g_ffl);
    cudaGetSymbolAddress((void**)&hh, g_hh);  cudaGetSymbolAddress((void**)&hl, g_hl);
    cudaGetSymbolAddress((void**)&wT4h, g_wT4h); cudaGetSymbolAddress((void**)&wT4l, g_wT4l);
    cudaGetSymbolAddress((void**)&w1Th, g_w1Th); cudaGetSymbolAddress((void**)&w1Tl, g_w1Tl);
    cudaGetSymbolAddress((void**)&w2Th, g_w2Th); cudaGetSymbolAddress((void**)&w2Tl, g_w2Tl);

    cudaFuncSetAttribute(gemm16_kernel,     cudaFuncAttributeMaxDynamicSharedMemorySize, GEMM_SMEM);
    cudaFuncSetAttribute(gemm16_qkv_kernel, cudaFuncAttributeMaxDynamicSharedMemorySize, GEMM_SMEM);

    // ---- preconvert all weights ----
    const dim3 tb(32, 8);
    for (int l = 0; l < Ll; l++) {
        const size_t wdd = (size_t)l * Dm * Dm;
        const size_t o4  = (size_t)l * 4 * Dm * Dm;
        wconv_kernel<<<dim3(Dm / 32, Dm / 32), tb>>>(Wq + wdd, wT4h + o4,                   wT4l + o4,                   Dm, Dm);
        wconv_kernel<<<dim3(Dm / 32, Dm / 32), tb>>>(Wk + wdd, wT4h + o4 + (size_t)Dm*Dm,   wT4l + o4 + (size_t)Dm*Dm,   Dm, Dm);
        wconv_kernel<<<dim3(Dm / 32, Dm / 32), tb>>>(Wv + wdd, wT4h + o4 + (size_t)2*Dm*Dm, wT4l + o4 + (size_t)2*Dm*Dm, Dm, Dm);
        wconv_kernel<<<dim3(Dm / 32, Dm / 32), tb>>>(Wo + wdd, wT4h + o4 + (size_t)3*Dm*Dm, wT4l + o4 + (size_t)3*Dm*Dm, Dm, Dm);
        wconv_kernel<<<dim3(Ff / 32, Dm / 32), tb>>>(W1 + (size_t)l * Dm * Ff, w1Th + (size_t)l * Ff * Dm, w1Tl + (size_t)l * Ff * Dm, Dm, Ff);
        wconv_kernel<<<dim3(Dm / 32, Ff / 32), tb>>>(W2 + (size_t)l * Ff * Dm, w2Th + (size_t)l * Dm * Ff, w2Tl + (size_t)l * Dm * Ff, Ff, Dm);
    }

    copy_split_kernel<<<(ROWS * Dm + 255) / 256, 256>>>(x_in, x, xh, xl, ROWS * Dm);

    for (int l = 0; l < Ll; l++) {
        const size_t o4 = (size_t)l * 4 * Dm * Dm;

        gemm16_qkv_kernel<<<dim3(Dm / 128, ROWS / 128, 3), 256, GEMM_SMEM>>>(
            xh, xl, wT4h + o4, wT4l + o4,
            bqp + l * Dm, bkp + l * Dm, bvp + l * Dm, Dm, Dm);

        const int qetot = Bq * Hh * Sq * NBb;
        qe_kernel<<<(qetot + 255) / 256, 256>>>(Erel + (size_t)l * NBb * DHd);

        attn_kernel<<<dim3(Sq / 64, Hh, Bq), 128>>>(Brel + (size_t)l * Hh * NBb, rid);

        gemm16_kernel<<<dim3(Dm / 128, ROWS / 128), 256, GEMM_SMEM>>>(
            ah, al, wT4h + o4 + (size_t)3 * Dm * Dm, wT4l + o4 + (size_t)3 * Dm * Dm,
            bop + l * Dm, x, y, nullptr, nullptr, Dm, Dm, 0);

        ln_kernel<<<ROWS, 256>>>(y, g1 + l * Dm, be1 + l * Dm, k, ffh, ffl);

        gemm16_kernel<<<dim3(Ff / 128, ROWS / 128), 256, GEMM_SMEM>>>(
            ffh, ffl, w1Th + (size_t)l * Ff * Dm, w1Tl + (size_t)l * Ff * Dm,
            b1 + l * Ff, nullptr, nullptr, hh, hl, Ff, Dm, 1);

        gemm16_kernel<<<dim3(Dm / 128, ROWS / 128), 256, GEMM_SMEM>>>(
            hh, hl, w2Th + (size_t)l * Dm * Ff, w2Tl + (size_t)l * Dm * Ff,
            b2 + l * Dm, k, v, nullptr, nullptr, Dm, Ff, 0);

        ln_kernel<<<ROWS, 256>>>(v, g2 + l * Dm, be2 + l * Dm,
                                 (l == Ll - 1) ? outp : x, xh, xl);
    }
}

// round 11
// speedup vs baseline: 1.5868x; 1.3307x over previous
#include <cuda_runtime.h>
#include <cuda_fp16.h>
#include <math_constants.h>
#include <cstdint>

// Problem constants
#define Bq   4
#define Sq   1024
#define Dm   1024
#define Hh   16
#define DHd  64
#define Ff   4096
#define NBb  33
#define Ll   6
#define ROWS (Bq*Sq)
#define SCALE_ATTN 0.125f

// ---------------- scratch (device globals) ----------------
__device__ float g_x [ROWS*Dm];
__device__ float g_y [ROWS*Dm];
__device__ float g_k [ROWS*Dm];
__device__ float g_v [ROWS*Dm];
__device__ float g_qe[Bq*Hh*Sq*NBb];

// fp16 activation hi/lo
__device__ __half g_xh [ROWS*Dm], g_xl [ROWS*Dm];
__device__ __half g_ah [ROWS*Dm], g_al [ROWS*Dm];
__device__ __half g_ffh[ROWS*Dm], g_ffl[ROWS*Dm];
__device__ __half g_hh [ROWS*Ff], g_hl [ROWS*Ff];
__device__ __half g_qh2[ROWS*Dm], g_ql2[ROWS*Dm];
__device__ __half g_kh2[ROWS*Dm];
__device__ __half g_vh2[ROWS*Dm], g_vl2[ROWS*Dm];

// transposed fp16 weights (single precision term): [N][K]
__device__ __half g_wT4[Ll*4*Dm*Dm];
__device__ __half g_w1T[Ll*Ff*Dm];
__device__ __half g_w2T[Ll*Dm*Ff];

__device__ __forceinline__ void hsplit(float f, __half& h, __half& l) {
    h = __float2half_rn(f);
    l = __float2half_rn(f - __half2float(h));
}

// ---------------- common asm helpers ----------------
__device__ __forceinline__ uint32_t s2u(const void* p) {
    uint32_t a;
    asm("{ .reg .u64 t; cvta.to.shared.u64 t, %1; cvt.u32.u64 %0, t; }" : "=r"(a) : "l"(p));
    return a;
}
__device__ __forceinline__ void cp16s(uint32_t s, const void* g) {
    asm volatile("cp.async.cg.shared.global [%0], [%1], 16;\n" :: "r"(s), "l"(g));
}
__device__ __forceinline__ void mma_f16(float* c, const uint32_t* a, uint32_t b0, uint32_t b1) {
    asm volatile(
        "mma.sync.aligned.m16n8k16.row.col.f32.f16.f16.f32 "
        "{%0,%1,%2,%3}, {%4,%5,%6,%7}, {%8,%9}, {%0,%1,%2,%3};\n"
        : "+f"(c[0]), "+f"(c[1]), "+f"(c[2]), "+f"(c[3])
        : "r"(a[0]), "r"(a[1]), "r"(a[2]), "r"(a[3]), "r"(b0), "r"(b1));
}
__device__ __forceinline__ void ldsm4(uint32_t* r, uint32_t addr) {
    asm volatile("ldmatrix.sync.aligned.m8n8.x4.shared.b16 {%0,%1,%2,%3}, [%4];"
                 : "=r"(r[0]), "=r"(r[1]), "=r"(r[2]), "=r"(r[3]) : "r"(addr));
}
__device__ __forceinline__ void ldsm4t(uint32_t* r, uint32_t addr) {
    asm volatile("ldmatrix.sync.aligned.m8n8.x4.trans.shared.b16 {%0,%1,%2,%3}, [%4];"
                 : "=r"(r[0]), "=r"(r[1]), "=r"(r[2]), "=r"(r[3]) : "r"(addr));
}
__device__ __forceinline__ uint32_t pk_h2(float a, float b) {
    __half2 t = __floats2half2_rn(a, b);
    return *(uint32_t*)&t;
}

// ---------------- weight transpose -> single fp16 [N][K] ----------------
__global__ void wconv_kernel(const float* __restrict__ W,
                             __half* __restrict__ T, int K, int N)
{
    __shared__ float t[32][33];
    int n0 = blockIdx.x * 32, k0 = blockIdx.y * 32;
    int tx = threadIdx.x, ty = threadIdx.y;
#pragma unroll
    for (int i = 0; i < 4; i++)
        t[ty + 8 * i][tx] = W[(size_t)(k0 + ty + 8 * i) * N + n0 + tx];
    __syncthreads();
#pragma unroll
    for (int i = 0; i < 4; i++) {
        float f = t[tx][ty + 8 * i];
        int n = n0 + ty + 8 * i, k = k0 + tx;
        T[(size_t)n * K + k] = __float2half_rn(f);
    }
}

// ---------------- copy + split ----------------
__global__ void copy_split_kernel(const float* __restrict__ in, float* __restrict__ out,
                                  __half* __restrict__ oh, __half* __restrict__ ol, int n)
{
    int i = blockIdx.x * blockDim.x + threadIdx.x;
    if (i < n) {
        float f = in[i];
        out[i] = f;
        __half h, l; hsplit(f, h, l);
        oh[i] = h; ol[i] = l;
    }
}

// =========================================================================
// 2-MMA fp16 GEMM: C = (Ah+Al) @ B^T + bias (+resid)(relu)
// A[M][K] fp16 hi/lo; B[N][K] single fp16 (= W^T). CTA 128x128, BK=32, 2 stages.
// =========================================================================
#define PADk 40
#define STG  (128 * PADk)
#define GEMM_SMEM (2 * 3 * STG * 2)   // 61440 B

__device__ __forceinline__ void gemm16_core(
    const __half* __restrict__ Ah, const __half* __restrict__ Al,
    const __half* __restrict__ B,
    const float* __restrict__ bias, const float* __restrict__ resid,
    float* __restrict__ C, __half* __restrict__ Ch, __half* __restrict__ Cl,
    int N, int K, bool relu)
{
    extern __shared__ __half smem[];
    const uint32_t smb = s2u(smem);

    const int tid  = threadIdx.x;
    const int lane = tid & 31;
    const int warp = tid >> 5;
    const int wm   = warp >> 1;
    const int wn   = warp & 1;
    const int g    = lane >> 2;
    const int tig  = lane & 3;

    const int bm = blockIdx.y * 128, bn = blockIdx.x * 128;

    const int prow = tid >> 1, kh = (tid & 1) * 16;
    const uint32_t soff = (uint32_t)(prow * PADk + kh) * 2;

    const __half* gA0 = Ah + (size_t)(bm + prow) * K + kh;
    const __half* gA1 = Al + (size_t)(bm + prow) * K + kh;
    const __half* gB  = B  + (size_t)(bn + prow) * K + kh;

    const int mi = lane >> 3, li = lane & 7;
    const uint32_t aoff0 = (uint32_t)(((wm * 32 + (mi & 1) * 8 + li) * PADk) + (mi >> 1) * 8) * 2;
    const uint32_t boff0 = (uint32_t)(((wn * 64 + (mi >> 1) * 8 + li) * PADk) + (mi & 1) * 8) * 2;

    float acc[2][8][4];
#pragma unroll
    for (int i = 0; i < 2; i++)
#pragma unroll
        for (int j = 0; j < 8; j++)
#pragma unroll
            for (int c = 0; c < 4; c++) acc[i][j][c] = 0.f;

    const int nck = K >> 5;
    const uint32_t stageB = 3 * STG * 2;
    const uint32_t arrB   = STG * 2;

    {
        cp16s(smb + 0 * arrB + soff,      gA0);
        cp16s(smb + 0 * arrB + soff + 16, gA0 + 8);
        cp16s(smb + 1 * arrB + soff,      gA1);
        cp16s(smb + 1 * arrB + soff + 16, gA1 + 8);
        cp16s(smb + 2 * arrB + soff,      gB);
        cp16s(smb + 2 * arrB + soff + 16, gB + 8);
        asm volatile("cp.async.commit_group;\n");
    }

    for (int kc = 0; kc < nck; kc++) {
        asm volatile("cp.async.wait_group 0;\n");
        __syncthreads();
        if (kc + 1 < nck) {
            const uint32_t sb = ((kc + 1) & 1) * stageB;
            const int go = (kc + 1) * 32;
            cp16s(smb + sb + 0 * arrB + soff,      gA0 + go);
            cp16s(smb + sb + 0 * arrB + soff + 16, gA0 + go + 8);
            cp16s(smb + sb + 1 * arrB + soff,      gA1 + go);
            cp16s(smb + sb + 1 * arrB + soff + 16, gA1 + go + 8);
            cp16s(smb + sb + 2 * arrB + soff,      gB + go);
            cp16s(smb + sb + 2 * arrB + soff + 16, gB + go + 8);
            asm volatile("cp.async.commit_group;\n");
        }
        const uint32_t sb = (kc & 1) * stageB;
        const uint32_t aH = smb + sb + 0 * arrB + aoff0;
        const uint32_t aL = smb + sb + 1 * arrB + aoff0;
        const uint32_t bB = smb + sb + 2 * arrB + boff0;

#pragma unroll
        for (int ks = 0; ks < 2; ks++) {
            const uint32_t ko = ks * 32;
            uint32_t ah[2][4], al[2][4];
            ldsm4(ah[0], aH + ko);
            ldsm4(ah[1], aH + 16 * PADk * 2 + ko);
            ldsm4(al[0], aL + ko);
            ldsm4(al[1], aL + 16 * PADk * 2 + ko);
#pragma unroll
            for (int p = 0; p < 4; p++) {
                uint32_t bh[4];
                ldsm4(bh, bB + p * 16 * PADk * 2 + ko);
#pragma unroll
                for (int q = 0; q < 2; q++) {
                    const int nf = 2 * p + q;
#pragma unroll
                    for (int mf = 0; mf < 2; mf++) {
                        mma_f16(acc[mf][nf], ah[mf], bh[2 * q], bh[2 * q + 1]);
                        mma_f16(acc[mf][nf], al[mf], bh[2 * q], bh[2 * q + 1]);
                    }
                }
            }
        }
    }

    // ---- epilogue ----
#pragma unroll
    for (int mf = 0; mf < 2; mf++) {
#pragma unroll
        for (int nf = 0; nf < 8; nf++) {
            const int r0 = bm + wm * 32 + mf * 16 + g;
            const int cc = bn + wn * 64 + nf * 8 + 2 * tig;
            const float bs0 = bias[cc], bs1 = bias[cc + 1];
            float v0 = acc[mf][nf][0] + bs0;
            float v1 = acc[mf][nf][1] + bs1;
            float v2 = acc[mf][nf][2] + bs0;
            float v3 = acc[mf][nf][3] + bs1;
            const size_t i0 = (size_t)r0 * N + cc;
            const size_t i1 = (size_t)(r0 + 8) * N + cc;
            if (resid) {
                const float2 r0v = *(const float2*)(resid + i0);
                const float2 r1v = *(const float2*)(resid + i1);
                v0 += r0v.x; v1 += r0v.y; v2 += r1v.x; v3 += r1v.y;
            }
            if (relu) {
                v0 = fmaxf(v0, 0.f); v1 = fmaxf(v1, 0.f);
                v2 = fmaxf(v2, 0.f); v3 = fmaxf(v3, 0.f);
            }
            if (C) {
                *(float2*)(C + i0) = make_float2(v0, v1);
                *(float2*)(C + i1) = make_float2(v2, v3);
            }
            if (Ch) {
                if (Cl) {
                    __half h0, l0, h1, l1, h2, l2, h3, l3;
                    hsplit(v0, h0, l0); hsplit(v1, h1, l1);
                    hsplit(v2, h2, l2); hsplit(v3, h3, l3);
                    *(__half2*)(Ch + i0) = __half2(h0, h1);
                    *(__half2*)(Ch + i1) = __half2(h2, h3);
                    *(__half2*)(Cl + i0) = __half2(l0, l1);
                    *(__half2*)(Cl + i1) = __half2(l2, l3);
                } else {
                    *(__half2*)(Ch + i0) = __floats2half2_rn(v0, v1);
                    *(__half2*)(Ch + i1) = __floats2half2_rn(v2, v3);
                }
            }
        }
    }
}

__global__ __launch_bounds__(256) void gemm16_kernel(
    const __half* __restrict__ Ah, const __half* __restrict__ Al,
    const __half* __restrict__ B,
    const float* __restrict__ bias, const float* __restrict__ resid,
    float* __restrict__ C, __half* __restrict__ Ch, __half* __restrict__ Cl,
    int N, int K, int relu)
{
    gemm16_core(Ah, Al, B, bias, resid, C, Ch, Cl, N, K, relu != 0);
}

// QKV: z=0 -> fp32 y + fp16 q hi/lo ; z=1 -> fp16 k single ; z=2 -> fp16 v hi/lo
__global__ __launch_bounds__(256) void gemm16_qkv_kernel(
    const __half* __restrict__ Ah, const __half* __restrict__ Al,
    const __half* __restrict__ WT,
    const float* __restrict__ bq, const float* __restrict__ bk, const float* __restrict__ bv,
    int N, int K)
{
    const size_t off = (size_t)blockIdx.z * Dm * Dm;
    const float* bias; float* C; __half *Ch, *Cl;
    if      (blockIdx.z == 0) { bias = bq; C = g_y;     Ch = g_qh2; Cl = g_ql2; }
    else if (blockIdx.z == 1) { bias = bk; C = nullptr; Ch = g_kh2; Cl = nullptr; }
    else                      { bias = bv; C = nullptr; Ch = g_vh2; Cl = g_vl2; }
    gemm16_core(Ah, Al, WT + off, bias, nullptr, C, Ch, Cl, N, K, false);
}

// ---------------- qe = q @ Erel^T ----------------
__global__ void qe_kernel(const float* __restrict__ er)
{
    int idx = blockIdx.x * blockDim.x + threadIdx.x;
    const int total = Bq * Hh * Sq * NBb;
    if (idx >= total) return;
    int nb = idx % NBb;
    int s  = (idx / NBb) % Sq;
    int h  = (idx / (NBb * Sq)) % Hh;
    int b  =  idx / (NBb * Sq * Hh);
    const float* qr = g_y + ((size_t)(b * Sq + s)) * Dm + h * DHd;
    const float* e  = er + nb * DHd;
    float acc = 0.f;
#pragma unroll
    for (int d = 0; d < DHd; d++) acc = fmaf(qr[d], e[d], acc);
    g_qe[idx] = acc;
}

// =========================================================================
// MMA flash attention (fp16): S = Qh*K + Ql*K ; PV = P*Vh + P*Vl
// =========================================================================
#define APITCH 72

__global__ __launch_bounds__(128) void attn_kernel(const float* __restrict__ brel,
                                                   const int* __restrict__ rid)
{
    __shared__ __half Kh_s[64 * APITCH];
    __shared__ __half Vh_s[64 * APITCH];
    __shared__ __half Vl_s[64 * APITCH];
    __shared__ float Cb[64 * NBb];

    const int tid = threadIdx.x, lane = tid & 31, w = tid >> 5;
    const int g = lane >> 2, tig = lane & 3;
    const int b = blockIdx.z, h = blockIdx.y;
    const int q0 = blockIdx.x * 64;

    const uint32_t kh_b = s2u(Kh_s), vh_b = s2u(Vh_s), vl_b = s2u(Vl_s);
    const int mi = lane >> 3, li = lane & 7;

#pragma unroll
    for (int j = 0; j < 4; j++) {
        int chunk = tid + 128 * j;
        int r = chunk >> 3, c8 = chunk & 7;
        size_t go = ((size_t)(b * Sq + q0 + r)) * Dm + h * DHd + c8 * 8;
        uint32_t so = (uint32_t)(r * APITCH + c8 * 8) * 2;
        cp16s(kh_b + so, g_qh2 + go);
        cp16s(vh_b + so, g_ql2 + go);
    }
    asm volatile("cp.async.commit_group;\n cp.async.wait_group 0;\n");
    __syncthreads();

    uint32_t aqh[4][4], aql[4][4];
    {
        const int row = w * 16 + (mi & 1) * 8 + li;
#pragma unroll
        for (int ks = 0; ks < 4; ks++) {
            uint32_t off = (uint32_t)(row * APITCH + ks * 16 + (mi >> 1) * 8) * 2;
            ldsm4(aqh[ks], kh_b + off);
            ldsm4(aql[ks], vh_b + off);
        }
    }
    for (int i = tid; i < 64 * NBb; i += 128) {
        int r = i / NBb, nb = i - r * NBb;
        Cb[i] = g_qe[(((size_t)(b * Hh + h)) * Sq + q0 + r) * NBb + nb] + brel[h * NBb + nb];
    }
    __syncthreads();

    float m0 = -CUDART_INF_F, m1 = -CUDART_INF_F, l0 = 0.f, l1 = 0.f;
    float o[8][4];
#pragma unroll
    for (int i = 0; i < 8; i++)
#pragma unroll
        for (int c = 0; c < 4; c++) o[i][c] = 0.f;

    const int qr0 = w * 16 + g;
    const int grow0 = q0 + qr0;

    for (int k0 = 0; k0 < Sq; k0 += 64) {
#pragma unroll
        for (int j = 0; j < 4; j++) {
            int chunk = tid + 128 * j;
            int r = chunk >> 3, c8 = chunk & 7;
            size_t go = ((size_t)(b * Sq + k0 + r)) * Dm + h * DHd + c8 * 8;
            uint32_t so = (uint32_t)(r * APITCH + c8 * 8) * 2;
            cp16s(kh_b + so, g_kh2 + go);
            cp16s(vh_b + so, g_vh2 + go);
            cp16s(vl_b + so, g_vl2 + go);
        }
        asm volatile("cp.async.commit_group;\n cp.async.wait_group 0;\n");
        __syncthreads();

        float s[8][4];
#pragma unroll
        for (int i = 0; i < 8; i++)
#pragma unroll
            for (int c = 0; c < 4; c++) s[i][c] = 0.f;

#pragma unroll
        for (int ks = 0; ks < 4; ks++) {
#pragma unroll
            for (int ntp = 0; ntp < 4; ntp++) {
                uint32_t kb[4];
                uint32_t off = (uint32_t)((ntp * 16 + (mi >> 1) * 8 + li) * APITCH
                                          + ks * 16 + (mi & 1) * 8) * 2;
                ldsm4(kb, kh_b + off);
                mma_f16(s[2 * ntp],     aqh[ks], kb[0], kb[1]);
                mma_f16(s[2 * ntp],     aql[ks], kb[0], kb[1]);
                mma_f16(s[2 * ntp + 1], aqh[ks], kb[2], kb[3]);
                mma_f16(s[2 * ntp + 1], aql[ks], kb[2], kb[3]);
            }
        }

        float mt0 = -CUDART_INF_F, mt1 = -CUDART_INF_F;
#pragma unroll
        for (int nt = 0; nt < 8; nt++) {
            const int col = k0 + 8 * nt + 2 * tig;
            const int r0i = rid[(size_t)grow0 * Sq + col];
            const int r1i = rid[(size_t)grow0 * Sq + col + 1];
            const int r2i = rid[(size_t)(grow0 + 8) * Sq + col];
            const int r3i = rid[(size_t)(grow0 + 8) * Sq + col + 1];
            float v0 = (s[nt][0] + Cb[qr0 * NBb + r0i]) * SCALE_ATTN;
            float v1 = (s[nt][1] + Cb[qr0 * NBb + r1i]) * SCALE_ATTN;
            float v2 = (s[nt][2] + Cb[(qr0 + 8) * NBb + r2i]) * SCALE_ATTN;
            float v3 = (s[nt][3] + Cb[(qr0 + 8) * NBb + r3i]) * SCALE_ATTN;
            s[nt][0] = v0; s[nt][1] = v1; s[nt][2] = v2; s[nt][3] = v3;
            mt0 = fmaxf(mt0, fmaxf(v0, v1));
            mt1 = fmaxf(mt1, fmaxf(v2, v3));
        }
        mt0 = fmaxf(mt0, __shfl_xor_sync(0xffffffffu, mt0, 1));
        mt0 = fmaxf(mt0, __shfl_xor_sync(0xffffffffu, mt0, 2));
        mt1 = fmaxf(mt1, __shfl_xor_sync(0xffffffffu, mt1, 1));
        mt1 = fmaxf(mt1, __shfl_xor_sync(0xffffffffu, mt1, 2));

        const float mn0 = fmaxf(m0, mt0), mn1 = fmaxf(m1, mt1);
        const float fac0 = __expf(m0 - mn0), fac1 = __expf(m1 - mn1);
        float rs0 = 0.f, rs1 = 0.f;
#pragma unroll
        for (int nt = 0; nt < 8; nt++) {
            float p0 = __expf(s[nt][0] - mn0);
            float p1 = __expf(s[nt][1] - mn0);
            float p2 = __expf(s[nt][2] - mn1);
            float p3 = __expf(s[nt][3] - mn1);
            s[nt][0] = p0; s[nt][1] = p1; s[nt][2] = p2; s[nt][3] = p3;
            rs0 += p0 + p1; rs1 += p2 + p3;
        }
        rs0 += __shfl_xor_sync(0xffffffffu, rs0, 1);
        rs0 += __shfl_xor_sync(0xffffffffu, rs0, 2);
        rs1 += __shfl_xor_sync(0xffffffffu, rs1, 1);
        rs1 += __shfl_xor_sync(0xffffffffu, rs1, 2);
        l0 = l0 * fac0 + rs0;  m0 = mn0;
        l1 = l1 * fac1 + rs1;  m1 = mn1;
#pragma unroll
        for (int nt = 0; nt < 8; nt++) {
            o[nt][0] *= fac0; o[nt][1] *= fac0;
            o[nt][2] *= fac1; o[nt][3] *= fac1;
        }

#pragma unroll
        for (int ks = 0; ks < 4; ks++) {
            uint32_t ap[4];
            ap[0] = pk_h2(s[2 * ks][0],     s[2 * ks][1]);
            ap[1] = pk_h2(s[2 * ks][2],     s[2 * ks][3]);
            ap[2] = pk_h2(s[2 * ks + 1][0], s[2 * ks + 1][1]);
            ap[3] = pk_h2(s[2 * ks + 1][2], s[2 * ks + 1][3]);
#pragma unroll
            for (int ntp = 0; ntp < 4; ntp++) {
                uint32_t vh[4], vl[4];
                uint32_t off = (uint32_t)((ks * 16 + (mi & 1) * 8 + li) * APITCH
                                          + (2 * ntp + (mi >> 1)) * 8) * 2;
                ldsm4t(vh, vh_b + off);
                ldsm4t(vl, vl_b + off);
                mma_f16(o[2 * ntp],     ap, vh[0], vh[1]);
                mma_f16(o[2 * ntp],     ap, vl[0], vl[1]);
                mma_f16(o[2 * ntp + 1], ap, vh[2], vh[3]);
                mma_f16(o[2 * ntp + 1], ap, vl[2], vl[3]);
            }
        }
        __syncthreads();
    }

    // epilogue: normalize, split, store fp16 hi/lo
    const float inv0 = 1.f / l0, inv1 = 1.f / l1;
#pragma unroll
    for (int nt = 0; nt < 8; nt++) {
        const int col = h * DHd + 8 * nt + 2 * tig;
        size_t i0 = ((size_t)(b * Sq) + grow0) * Dm + col;
        size_t i1 = ((size_t)(b * Sq) + grow0 + 8) * Dm + col;
        float v0 = o[nt][0] * inv0, v1 = o[nt][1] * inv0;
        float v2 = o[nt][2] * inv1, v3 = o[nt][3] * inv1;
        __half h0, e0, h1, e1, h2, e2, h3, e3;
        hsplit(v0, h0, e0); hsplit(v1, h1, e1);
        hsplit(v2, h2, e2); hsplit(v3, h3, e3);
        *(__half2*)(g_ah + i0) = __half2(h0, h1);
        *(__half2*)(g_al + i0) = __half2(e0, e1);
        *(__half2*)(g_ah + i1) = __half2(h2, h3);
        *(__half2*)(g_al + i1) = __half2(e2, e3);
    }
}

// ---------------- layernorm ----------------
__device__ __forceinline__ float block_sum_256(float val, float* sh) {
#pragma unroll
    for (int off = 16; off; off >>= 1) val += __shfl_xor_sync(0xffffffffu, val, off);
    if ((threadIdx.x & 31) == 0) sh[threadIdx.x >> 5] = val;
    __syncthreads();
    float t = 0.f;
    if (threadIdx.x < 8) t = sh[threadIdx.x];
    if (threadIdx.x < 32) {
#pragma unroll
        for (int off = 4; off; off >>= 1) t += __shfl_xor_sync(0xffffffffu, t, off);
        if (threadIdx.x == 0) sh[0] = t;
    }
    __syncthreads();
    float r = sh[0];
    __syncthreads();
    return r;
}

__global__ void ln_kernel(const float* __restrict__ in, const float* __restrict__ gam,
                          const float* __restrict__ bet, float* __restrict__ out,
                          __half* __restrict__ oh, __half* __restrict__ ol)
{
    __shared__ float sh[8];
    int row = blockIdx.x, tid = threadIdx.x;
    float4 x4 = ((const float4*)(in + (size_t)row * Dm))[tid];
    float s = x4.x + x4.y + x4.z + x4.w;
    float mean = block_sum_256(s, sh) * (1.f / Dm);
    float dx = x4.x - mean, dy = x4.y - mean, dz = x4.z - mean, dw = x4.w - mean;
    float s2 = dx * dx + dy * dy + dz * dz + dw * dw;
    float var = block_sum_256(s2, sh) * (1.f / Dm);
    float inv = rsqrtf(var + 1e-6f);
    int c = tid * 4;
    float4 o;
    o.x = dx * inv * gam[c + 0] + bet[c + 0];
    o.y = dy * inv * gam[c + 1] + bet[c + 1];
    o.z = dz * inv * gam[c + 2] + bet[c + 2];
    o.w = dw * inv * gam[c + 3] + bet[c + 3];
    ((float4*)(out + (size_t)row * Dm))[tid] = o;
    if (oh) {
        size_t base = (size_t)row * Dm + c;
        __half h0, l0, h1, l1, h2, l2, h3, l3;
        hsplit(o.x, h0, l0); hsplit(o.y, h1, l1);
        hsplit(o.z, h2, l2); hsplit(o.w, h3, l3);
        *(__half2*)(oh + base)     = __half2(h0, h1);
        *(__half2*)(oh + base + 2) = __half2(h2, h3);
        *(__half2*)(ol + base)     = __half2(l0, l1);
        *(__half2*)(ol + base + 2) = __half2(l2, l3);
    }
}

// ---------------- launch ----------------
extern "C" void kernel_launch(void* const* d_in, const int* in_sizes, int n_in,
                              void* d_out, int out_size)
{
    const float* x_in = (const float*)d_in[0];
    const int*   rid  = (const int*)  d_in[1];
    const float* Wq   = (const float*)d_in[2];
    const float* bqp  = (const float*)d_in[3];
    const float* Wk   = (const float*)d_in[4];
    const float* bkp  = (const float*)d_in[5];
    const float* Wv   = (const float*)d_in[6];
    const float* bvp  = (const float*)d_in[7];
    const float* Wo   = (const float*)d_in[8];
    const float* bop  = (const float*)d_in[9];
    const float* Erel = (const float*)d_in[10];
    const float* Brel = (const float*)d_in[11];
    const float* g1   = (const float*)d_in[12];
    const float* be1  = (const float*)d_in[13];
    const float* g2   = (const float*)d_in[14];
    const float* be2  = (const float*)d_in[15];
    const float* W1   = (const float*)d_in[16];
    const float* b1   = (const float*)d_in[17];
    const float* W2   = (const float*)d_in[18];
    const float* b2   = (const float*)d_in[19];
    float* outp = (float*)d_out;

    float *x, *y, *k, *v;
    __half *xh, *xl, *ah, *al, *ffh, *ffl, *hh, *hl;
    __half *wT4, *w1T, *w2T;
    cudaGetSymbolAddress((void**)&x,  g_x);
    cudaGetSymbolAddress((void**)&y,  g_y);
    cudaGetSymbolAddress((void**)&k,  g_k);
    cudaGetSymbolAddress((void**)&v,  g_v);
    cudaGetSymbolAddress((void**)&xh, g_xh);  cudaGetSymbolAddress((void**)&xl, g_xl);
    cudaGetSymbolAddress((void**)&ah, g_ah);  cudaGetSymbolAddress((void**)&al, g_al);
    cudaGetSymbolAddress((void**)&ffh, g_ffh); cudaGetSymbolAddress((void**)&ffl, g_ffl);
    cudaGetSymbolAddress((void**)&hh, g_hh);  cudaGetSymbolAddress((void**)&hl, g_hl);
    cudaGetSymbolAddress((void**)&wT4, g_wT4);
    cudaGetSymbolAddress((void**)&w1T, g_w1T);
    cudaGetSymbolAddress((void**)&w2T, g_w2T);

    cudaFuncSetAttribute(gemm16_kernel,     cudaFuncAttributeMaxDynamicSharedMemorySize, GEMM_SMEM);
    cudaFuncSetAttribute(gemm16_qkv_kernel, cudaFuncAttributeMaxDynamicSharedMemorySize, GEMM_SMEM);

    // ---- preconvert all weights (transpose -> single fp16) ----
    const dim3 tb(32, 8);
    for (int l = 0; l < Ll; l++) {
        const size_t wdd = (size_t)l * Dm * Dm;
        const size_t o4  = (size_t)l * 4 * Dm * Dm;
        wconv_kernel<<<dim3(Dm / 32, Dm / 32), tb>>>(Wq + wdd, wT4 + o4,                   Dm, Dm);
        wconv_kernel<<<dim3(Dm / 32, Dm / 32), tb>>>(Wk + wdd, wT4 + o4 + (size_t)Dm*Dm,   Dm, Dm);
        wconv_kernel<<<dim3(Dm / 32, Dm / 32), tb>>>(Wv + wdd, wT4 + o4 + (size_t)2*Dm*Dm, Dm, Dm);
        wconv_kernel<<<dim3(Dm / 32, Dm / 32), tb>>>(Wo + wdd, wT4 + o4 + (size_t)3*Dm*Dm, Dm, Dm);
        wconv_kernel<<<dim3(Ff / 32, Dm / 32), tb>>>(W1 + (size_t)l * Dm * Ff, w1T + (size_t)l * Ff * Dm, Dm, Ff);
        wconv_kernel<<<dim3(Dm / 32, Ff / 32), tb>>>(W2 + (size_t)l * Ff * Dm, w2T + (size_t)l * Dm * Ff, Ff, Dm);
    }

    copy_split_kernel<<<(ROWS * Dm + 255) / 256, 256>>>(x_in, x, xh, xl, ROWS * Dm);

    for (int l = 0; l < Ll; l++) {
        const size_t o4 = (size_t)l * 4 * Dm * Dm;

        gemm16_qkv_kernel<<<dim3(Dm / 128, ROWS / 128, 3), 256, GEMM_SMEM>>>(
            xh, xl, wT4 + o4, bqp + l * Dm, bkp + l * Dm, bvp + l * Dm, Dm, Dm);

        const int qetot = Bq * Hh * Sq * NBb;
        qe_kernel<<<(qetot + 255) / 256, 256>>>(Erel + (size_t)l * NBb * DHd);

        attn_kernel<<<dim3(Sq / 64, Hh, Bq), 128>>>(Brel + (size_t)l * Hh * NBb, rid);

        gemm16_kernel<<<dim3(Dm / 128, ROWS / 128), 256, GEMM_SMEM>>>(
            ah, al, wT4 + o4 + (size_t)3 * Dm * Dm,
            bop + l * Dm, x, y, nullptr, nullptr, Dm, Dm, 0);

        ln_kernel<<<ROWS, 256>>>(y, g1 + l * Dm, be1 + l * Dm, k, ffh, ffl);

        gemm16_kernel<<<dim3(Ff / 128, ROWS / 128), 256, GEMM_SMEM>>>(
            ffh, ffl, w1T + (size_t)l * Ff * Dm,
            b1 + l * Ff, nullptr, nullptr, hh, hl, Ff, Dm, 1);

        gemm16_kernel<<<dim3(Dm / 128, ROWS / 128), 256, GEMM_SMEM>>>(
            hh, hl, w2T + (size_t)l * Dm * Ff,
            b2 + l * Dm, k, v, nullptr, nullptr, Dm, Ff, 0);

        ln_kernel<<<ROWS, 256>>>(v, g2 + l * Dm, be2 + l * Dm,
                                 (l == Ll - 1) ? outp : x, xh, xl);
    }
}

// round 12
// speedup vs baseline: 1.9612x; 1.2360x over previous
#include <cuda_runtime.h>
#include <cuda_fp16.h>
#include <math_constants.h>
#include <cstdint>

// Problem constants
#define Bq   4
#define Sq   1024
#define Dm   1024
#define Hh   16
#define DHd  64
#define Ff   4096
#define NBb  33
#define Ll   6
#define ROWS (Bq*Sq)
#define SCALE_ATTN 0.125f

// ---------------- scratch (device globals) ----------------
__device__ float g_x [ROWS*Dm];
__device__ float g_y [ROWS*Dm];
__device__ float g_k [ROWS*Dm];
__device__ float g_v [ROWS*Dm];
__device__ float g_qe[Bq*Hh*Sq*NBb];

// fp16 activations (single)
__device__ __half g_xh [ROWS*Dm];
__device__ __half g_ah [ROWS*Dm];
__device__ __half g_ffh[ROWS*Dm];
__device__ __half g_hh [ROWS*Ff];
__device__ __half g_qh2[ROWS*Dm];
__device__ __half g_kh2[ROWS*Dm];
__device__ __half g_vh2[ROWS*Dm];

// transposed fp16 weights: [N][K]
__device__ __half g_wT4[Ll*4*Dm*Dm];
__device__ __half g_w1T[Ll*Ff*Dm];
__device__ __half g_w2T[Ll*Dm*Ff];

// ---------------- common asm helpers ----------------
__device__ __forceinline__ uint32_t s2u(const void* p) {
    uint32_t a;
    asm("{ .reg .u64 t; cvta.to.shared.u64 t, %1; cvt.u32.u64 %0, t; }" : "=r"(a) : "l"(p));
    return a;
}
__device__ __forceinline__ void cp16s(uint32_t s, const void* g) {
    asm volatile("cp.async.cg.shared.global [%0], [%1], 16;\n" :: "r"(s), "l"(g));
}
__device__ __forceinline__ void mma_f16(float* c, const uint32_t* a, uint32_t b0, uint32_t b1) {
    asm volatile(
        "mma.sync.aligned.m16n8k16.row.col.f32.f16.f16.f32 "
        "{%0,%1,%2,%3}, {%4,%5,%6,%7}, {%8,%9}, {%0,%1,%2,%3};\n"
        : "+f"(c[0]), "+f"(c[1]), "+f"(c[2]), "+f"(c[3])
        : "r"(a[0]), "r"(a[1]), "r"(a[2]), "r"(a[3]), "r"(b0), "r"(b1));
}
__device__ __forceinline__ void ldsm4(uint32_t* r, uint32_t addr) {
    asm volatile("ldmatrix.sync.aligned.m8n8.x4.shared.b16 {%0,%1,%2,%3}, [%4];"
                 : "=r"(r[0]), "=r"(r[1]), "=r"(r[2]), "=r"(r[3]) : "r"(addr));
}
__device__ __forceinline__ void ldsm4t(uint32_t* r, uint32_t addr) {
    asm volatile("ldmatrix.sync.aligned.m8n8.x4.trans.shared.b16 {%0,%1,%2,%3}, [%4];"
                 : "=r"(r[0]), "=r"(r[1]), "=r"(r[2]), "=r"(r[3]) : "r"(addr));
}
__device__ __forceinline__ uint32_t pk_h2(float a, float b) {
    __half2 t = __floats2half2_rn(a, b);
    return *(uint32_t*)&t;
}

// ---------------- weight transpose -> single fp16 [N][K] ----------------
__global__ void wconv_kernel(const float* __restrict__ W,
                             __half* __restrict__ T, int K, int N)
{
    __shared__ float t[32][33];
    int n0 = blockIdx.x * 32, k0 = blockIdx.y * 32;
    int tx = threadIdx.x, ty = threadIdx.y;
#pragma unroll
    for (int i = 0; i < 4; i++)
        t[ty + 8 * i][tx] = W[(size_t)(k0 + ty + 8 * i) * N + n0 + tx];
    __syncthreads();
#pragma unroll
    for (int i = 0; i < 4; i++) {
        float f = t[tx][ty + 8 * i];
        int n = n0 + ty + 8 * i, k = k0 + tx;
        T[(size_t)n * K + k] = __float2half_rn(f);
    }
}

// ---------------- copy + convert ----------------
__global__ void copy_split_kernel(const float* __restrict__ in, float* __restrict__ out,
                                  __half* __restrict__ oh, int n)
{
    int i = blockIdx.x * blockDim.x + threadIdx.x;
    if (i < n) {
        float f = in[i];
        out[i] = f;
        oh[i] = __float2half_rn(f);
    }
}

// =========================================================================
// 1-MMA fp16 GEMM: C = A @ B^T + bias (+resid)(relu)
// A[M][K] fp16; B[N][K] fp16 (= W^T). CTA 128x128, BK=32, 2 stages.
// =========================================================================
#define PADk 40
#define STG  (128 * PADk)
#define GEMM_SMEM (2 * 2 * STG * 2)   // 40960 B

__device__ __forceinline__ void gemm16_core(
    const __half* __restrict__ A, const __half* __restrict__ B,
    const float* __restrict__ bias, const float* __restrict__ resid,
    float* __restrict__ C, __half* __restrict__ Ch,
    int N, int K, bool relu)
{
    extern __shared__ __half smem[];
    const uint32_t smb = s2u(smem);

    const int tid  = threadIdx.x;
    const int lane = tid & 31;
    const int warp = tid >> 5;
    const int wm   = warp >> 1;
    const int wn   = warp & 1;
    const int g    = lane >> 2;
    const int tig  = lane & 3;

    const int bm = blockIdx.y * 128, bn = blockIdx.x * 128;

    const int prow = tid >> 1, kh = (tid & 1) * 16;
    const uint32_t soff = (uint32_t)(prow * PADk + kh) * 2;

    const __half* gA = A + (size_t)(bm + prow) * K + kh;
    const __half* gB = B + (size_t)(bn + prow) * K + kh;

    const int mi = lane >> 3, li = lane & 7;
    const uint32_t aoff0 = (uint32_t)(((wm * 32 + (mi & 1) * 8 + li) * PADk) + (mi >> 1) * 8) * 2;
    const uint32_t boff0 = (uint32_t)(((wn * 64 + (mi >> 1) * 8 + li) * PADk) + (mi & 1) * 8) * 2;

    float acc[2][8][4];
#pragma unroll
    for (int i = 0; i < 2; i++)
#pragma unroll
        for (int j = 0; j < 8; j++)
#pragma unroll
            for (int c = 0; c < 4; c++) acc[i][j][c] = 0.f;

    const int nck = K >> 5;
    const uint32_t stageB = 2 * STG * 2;
    const uint32_t arrB   = STG * 2;

    {
        cp16s(smb + 0 * arrB + soff,      gA);
        cp16s(smb + 0 * arrB + soff + 16, gA + 8);
        cp16s(smb + 1 * arrB + soff,      gB);
        cp16s(smb + 1 * arrB + soff + 16, gB + 8);
        asm volatile("cp.async.commit_group;\n");
    }

    for (int kc = 0; kc < nck; kc++) {
        asm volatile("cp.async.wait_group 0;\n");
        __syncthreads();
        if (kc + 1 < nck) {
            const uint32_t sb = ((kc + 1) & 1) * stageB;
            const int go = (kc + 1) * 32;
            cp16s(smb + sb + 0 * arrB + soff,      gA + go);
            cp16s(smb + sb + 0 * arrB + soff + 16, gA + go + 8);
            cp16s(smb + sb + 1 * arrB + soff,      gB + go);
            cp16s(smb + sb + 1 * arrB + soff + 16, gB + go + 8);
            asm volatile("cp.async.commit_group;\n");
        }
        const uint32_t sb = (kc & 1) * stageB;
        const uint32_t aB = smb + sb + 0 * arrB + aoff0;
        const uint32_t bB = smb + sb + 1 * arrB + boff0;

#pragma unroll
        for (int ks = 0; ks < 2; ks++) {
            const uint32_t ko = ks * 32;
            uint32_t ah[2][4];
            ldsm4(ah[0], aB + ko);
            ldsm4(ah[1], aB + 16 * PADk * 2 + ko);
#pragma unroll
            for (int p = 0; p < 4; p++) {
                uint32_t bh[4];
                ldsm4(bh, bB + p * 16 * PADk * 2 + ko);
#pragma unroll
                for (int q = 0; q < 2; q++) {
                    const int nf = 2 * p + q;
#pragma unroll
                    for (int mf = 0; mf < 2; mf++)
                        mma_f16(acc[mf][nf], ah[mf], bh[2 * q], bh[2 * q + 1]);
                }
            }
        }
    }

    // ---- epilogue ----
#pragma unroll
    for (int mf = 0; mf < 2; mf++) {
#pragma unroll
        for (int nf = 0; nf < 8; nf++) {
            const int r0 = bm + wm * 32 + mf * 16 + g;
            const int cc = bn + wn * 64 + nf * 8 + 2 * tig;
            const float bs0 = bias[cc], bs1 = bias[cc + 1];
            float v0 = acc[mf][nf][0] + bs0;
            float v1 = acc[mf][nf][1] + bs1;
            float v2 = acc[mf][nf][2] + bs0;
            float v3 = acc[mf][nf][3] + bs1;
            const size_t i0 = (size_t)r0 * N + cc;
            const size_t i1 = (size_t)(r0 + 8) * N + cc;
            if (resid) {
                const float2 r0v = *(const float2*)(resid + i0);
                const float2 r1v = *(const float2*)(resid + i1);
                v0 += r0v.x; v1 += r0v.y; v2 += r1v.x; v3 += r1v.y;
            }
            if (relu) {
                v0 = fmaxf(v0, 0.f); v1 = fmaxf(v1, 0.f);
                v2 = fmaxf(v2, 0.f); v3 = fmaxf(v3, 0.f);
            }
            if (C) {
                *(float2*)(C + i0) = make_float2(v0, v1);
                *(float2*)(C + i1) = make_float2(v2, v3);
            }
            if (Ch) {
                *(__half2*)(Ch + i0) = __floats2half2_rn(v0, v1);
                *(__half2*)(Ch + i1) = __floats2half2_rn(v2, v3);
            }
        }
    }
}

__global__ __launch_bounds__(256) void gemm16_kernel(
    const __half* __restrict__ A, const __half* __restrict__ B,
    const float* __restrict__ bias, const float* __restrict__ resid,
    float* __restrict__ C, __half* __restrict__ Ch,
    int N, int K, int relu)
{
    gemm16_core(A, B, bias, resid, C, Ch, N, K, relu != 0);
}

// QKV: z=0 -> fp32 y + fp16 q ; z=1 -> fp16 k ; z=2 -> fp16 v
__global__ __launch_bounds__(256) void gemm16_qkv_kernel(
    const __half* __restrict__ A, const __half* __restrict__ WT,
    const float* __restrict__ bq, const float* __restrict__ bk, const float* __restrict__ bv,
    int N, int K)
{
    const size_t off = (size_t)blockIdx.z * Dm * Dm;
    const float* bias; float* C; __half* Ch;
    if      (blockIdx.z == 0) { bias = bq; C = g_y;     Ch = g_qh2; }
    else if (blockIdx.z == 1) { bias = bk; C = nullptr; Ch = g_kh2; }
    else                      { bias = bv; C = nullptr; Ch = g_vh2; }
    gemm16_core(A, WT + off, bias, nullptr, C, Ch, N, K, false);
}

// ---------------- qe = q @ Erel^T ----------------
__global__ void qe_kernel(const float* __restrict__ er)
{
    int idx = blockIdx.x * blockDim.x + threadIdx.x;
    const int total = Bq * Hh * Sq * NBb;
    if (idx >= total) return;
    int nb = idx % NBb;
    int s  = (idx / NBb) % Sq;
    int h  = (idx / (NBb * Sq)) % Hh;
    int b  =  idx / (NBb * Sq * Hh);
    const float* qr = g_y + ((size_t)(b * Sq + s)) * Dm + h * DHd;
    const float* e  = er + nb * DHd;
    float acc = 0.f;
#pragma unroll
    for (int d = 0; d < DHd; d++) acc = fmaf(qr[d], e[d], acc);
    g_qe[idx] = acc;
}

// =========================================================================
// MMA flash attention (single fp16): S = Q*K^T ; O += P*V
// 64q x 64k tiles, 4 warps.
// =========================================================================
#define APITCH 72

__global__ __launch_bounds__(128) void attn_kernel(const float* __restrict__ brel,
                                                   const int* __restrict__ rid)
{
    __shared__ __half K_s[64 * APITCH];   // K; also Q staging
    __shared__ __half V_s[64 * APITCH];
    __shared__ float Cb[64 * NBb];

    const int tid = threadIdx.x, lane = tid & 31, w = tid >> 5;
    const int g = lane >> 2, tig = lane & 3;
    const int b = blockIdx.z, h = blockIdx.y;
    const int q0 = blockIdx.x * 64;

    const uint32_t k_b = s2u(K_s), v_b = s2u(V_s);
    const int mi = lane >> 3, li = lane & 7;

    // ---- stage Q, build fragments ----
#pragma unroll
    for (int j = 0; j < 4; j++) {
        int chunk = tid + 128 * j;
        int r = chunk >> 3, c8 = chunk & 7;
        size_t go = ((size_t)(b * Sq + q0 + r)) * Dm + h * DHd + c8 * 8;
        uint32_t so = (uint32_t)(r * APITCH + c8 * 8) * 2;
        cp16s(k_b + so, g_qh2 + go);
    }
    asm volatile("cp.async.commit_group;\n cp.async.wait_group 0;\n");
    __syncthreads();

    uint32_t aq[4][4];
    {
        const int row = w * 16 + (mi & 1) * 8 + li;
#pragma unroll
        for (int ks = 0; ks < 4; ks++) {
            uint32_t off = (uint32_t)(row * APITCH + ks * 16 + (mi >> 1) * 8) * 2;
            ldsm4(aq[ks], k_b + off);
        }
    }
    for (int i = tid; i < 64 * NBb; i += 128) {
        int r = i / NBb, nb = i - r * NBb;
        Cb[i] = g_qe[(((size_t)(b * Hh + h)) * Sq + q0 + r) * NBb + nb] + brel[h * NBb + nb];
    }
    __syncthreads();

    float m0 = -CUDART_INF_F, m1 = -CUDART_INF_F, l0 = 0.f, l1 = 0.f;
    float o[8][4];
#pragma unroll
    for (int i = 0; i < 8; i++)
#pragma unroll
        for (int c = 0; c < 4; c++) o[i][c] = 0.f;

    const int qr0 = w * 16 + g;
    const int grow0 = q0 + qr0;

    for (int k0 = 0; k0 < Sq; k0 += 64) {
#pragma unroll
        for (int j = 0; j < 4; j++) {
            int chunk = tid + 128 * j;
            int r = chunk >> 3, c8 = chunk & 7;
            size_t go = ((size_t)(b * Sq + k0 + r)) * Dm + h * DHd + c8 * 8;
            uint32_t so = (uint32_t)(r * APITCH + c8 * 8) * 2;
            cp16s(k_b + so, g_kh2 + go);
            cp16s(v_b + so, g_vh2 + go);
        }
        asm volatile("cp.async.commit_group;\n cp.async.wait_group 0;\n");
        __syncthreads();

        // ---- S = Q K^T ----
        float s[8][4];
#pragma unroll
        for (int i = 0; i < 8; i++)
#pragma unroll
            for (int c = 0; c < 4; c++) s[i][c] = 0.f;

#pragma unroll
        for (int ks = 0; ks < 4; ks++) {
#pragma unroll
            for (int ntp = 0; ntp < 4; ntp++) {
                uint32_t kb[4];
                uint32_t off = (uint32_t)((ntp * 16 + (mi >> 1) * 8 + li) * APITCH
                                          + ks * 16 + (mi & 1) * 8) * 2;
                ldsm4(kb, k_b + off);
                mma_f16(s[2 * ntp],     aq[ks], kb[0], kb[1]);
                mma_f16(s[2 * ntp + 1], aq[ks], kb[2], kb[3]);
            }
        }

        // ---- rel terms + scale + online softmax ----
        float mt0 = -CUDART_INF_F, mt1 = -CUDART_INF_F;
#pragma unroll
        for (int nt = 0; nt < 8; nt++) {
            const int col = k0 + 8 * nt + 2 * tig;
            const int r0i = rid[(size_t)grow0 * Sq + col];
            const int r1i = rid[(size_t)grow0 * Sq + col + 1];
            const int r2i = rid[(size_t)(grow0 + 8) * Sq + col];
            const int r3i = rid[(size_t)(grow0 + 8) * Sq + col + 1];
            float v0 = (s[nt][0] + Cb[qr0 * NBb + r0i]) * SCALE_ATTN;
            float v1 = (s[nt][1] + Cb[qr0 * NBb + r1i]) * SCALE_ATTN;
            float v2 = (s[nt][2] + Cb[(qr0 + 8) * NBb + r2i]) * SCALE_ATTN;
            float v3 = (s[nt][3] + Cb[(qr0 + 8) * NBb + r3i]) * SCALE_ATTN;
            s[nt][0] = v0; s[nt][1] = v1; s[nt][2] = v2; s[nt][3] = v3;
            mt0 = fmaxf(mt0, fmaxf(v0, v1));
            mt1 = fmaxf(mt1, fmaxf(v2, v3));
        }
        mt0 = fmaxf(mt0, __shfl_xor_sync(0xffffffffu, mt0, 1));
        mt0 = fmaxf(mt0, __shfl_xor_sync(0xffffffffu, mt0, 2));
        mt1 = fmaxf(mt1, __shfl_xor_sync(0xffffffffu, mt1, 1));
        mt1 = fmaxf(mt1, __shfl_xor_sync(0xffffffffu, mt1, 2));

        const float mn0 = fmaxf(m0, mt0), mn1 = fmaxf(m1, mt1);
        const float fac0 = __expf(m0 - mn0), fac1 = __expf(m1 - mn1);
        float rs0 = 0.f, rs1 = 0.f;
#pragma unroll
        for (int nt = 0; nt < 8; nt++) {
            float p0 = __expf(s[nt][0] - mn0);
            float p1 = __expf(s[nt][1] - mn0);
            float p2 = __expf(s[nt][2] - mn1);
            float p3 = __expf(s[nt][3] - mn1);
            s[nt][0] = p0; s[nt][1] = p1; s[nt][2] = p2; s[nt][3] = p3;
            rs0 += p0 + p1; rs1 += p2 + p3;
        }
        rs0 += __shfl_xor_sync(0xffffffffu, rs0, 1);
        rs0 += __shfl_xor_sync(0xffffffffu, rs0, 2);
        rs1 += __shfl_xor_sync(0xffffffffu, rs1, 1);
        rs1 += __shfl_xor_sync(0xffffffffu, rs1, 2);
        l0 = l0 * fac0 + rs0;  m0 = mn0;
        l1 = l1 * fac1 + rs1;  m1 = mn1;
#pragma unroll
        for (int nt = 0; nt < 8; nt++) {
            o[nt][0] *= fac0; o[nt][1] *= fac0;
            o[nt][2] *= fac1; o[nt][3] *= fac1;
        }

        // ---- O += P V ----
#pragma unroll
        for (int ks = 0; ks < 4; ks++) {
            uint32_t ap[4];
            ap[0] = pk_h2(s[2 * ks][0],     s[2 * ks][1]);
            ap[1] = pk_h2(s[2 * ks][2],     s[2 * ks][3]);
            ap[2] = pk_h2(s[2 * ks + 1][0], s[2 * ks + 1][1]);
            ap[3] = pk_h2(s[2 * ks + 1][2], s[2 * ks + 1][3]);
#pragma unroll
            for (int ntp = 0; ntp < 4; ntp++) {
                uint32_t vv[4];
                uint32_t off = (uint32_t)((ks * 16 + (mi & 1) * 8 + li) * APITCH
                                          + (2 * ntp + (mi >> 1)) * 8) * 2;
                ldsm4t(vv, v_b + off);
                mma_f16(o[2 * ntp],     ap, vv[0], vv[1]);
                mma_f16(o[2 * ntp + 1], ap, vv[2], vv[3]);
            }
        }
        __syncthreads();
    }

    // ---- epilogue: normalize, store fp16 ----
    const float inv0 = 1.f / l0, inv1 = 1.f / l1;
#pragma unroll
    for (int nt = 0; nt < 8; nt++) {
        const int col = h * DHd + 8 * nt + 2 * tig;
        size_t i0 = ((size_t)(b * Sq) + grow0) * Dm + col;
        size_t i1 = ((size_t)(b * Sq) + grow0 + 8) * Dm + col;
        *(__half2*)(g_ah + i0) = __floats2half2_rn(o[nt][0] * inv0, o[nt][1] * inv0);
        *(__half2*)(g_ah + i1) = __floats2half2_rn(o[nt][2] * inv1, o[nt][3] * inv1);
    }
}

// ---------------- layernorm ----------------
__device__ __forceinline__ float block_sum_256(float val, float* sh) {
#pragma unroll
    for (int off = 16; off; off >>= 1) val += __shfl_xor_sync(0xffffffffu, val, off);
    if ((threadIdx.x & 31) == 0) sh[threadIdx.x >> 5] = val;
    __syncthreads();
    float t = 0.f;
    if (threadIdx.x < 8) t = sh[threadIdx.x];
    if (threadIdx.x < 32) {
#pragma unroll
        for (int off = 4; off; off >>= 1) t += __shfl_xor_sync(0xffffffffu, t, off);
        if (threadIdx.x == 0) sh[0] = t;
    }
    __syncthreads();
    float r = sh[0];
    __syncthreads();
    return r;
}

__global__ void ln_kernel(const float* __restrict__ in, const float* __restrict__ gam,
                          const float* __restrict__ bet, float* __restrict__ out,
                          __half* __restrict__ oh)
{
    __shared__ float sh[8];
    int row = blockIdx.x, tid = threadIdx.x;
    float4 x4 = ((const float4*)(in + (size_t)row * Dm))[tid];
    float s = x4.x + x4.y + x4.z + x4.w;
    float mean = block_sum_256(s, sh) * (1.f / Dm);
    float dx = x4.x - mean, dy = x4.y - mean, dz = x4.z - mean, dw = x4.w - mean;
    float s2 = dx * dx + dy * dy + dz * dz + dw * dw;
    float var = block_sum_256(s2, sh) * (1.f / Dm);
    float inv = rsqrtf(var + 1e-6f);
    int c = tid * 4;
    float4 o;
    o.x = dx * inv * gam[c + 0] + bet[c + 0];
    o.y = dy * inv * gam[c + 1] + bet[c + 1];
    o.z = dz * inv * gam[c + 2] + bet[c + 2];
    o.w = dw * inv * gam[c + 3] + bet[c + 3];
    ((float4*)(out + (size_t)row * Dm))[tid] = o;
    if (oh) {
        size_t base = (size_t)row * Dm + c;
        *(__half2*)(oh + base)     = __floats2half2_rn(o.x, o.y);
        *(__half2*)(oh + base + 2) = __floats2half2_rn(o.z, o.w);
    }
}

// ---------------- launch ----------------
extern "C" void kernel_launch(void* const* d_in, const int* in_sizes, int n_in,
                              void* d_out, int out_size)
{
    const float* x_in = (const float*)d_in[0];
    const int*   rid  = (const int*)  d_in[1];
    const float* Wq   = (const float*)d_in[2];
    const float* bqp  = (const float*)d_in[3];
    const float* Wk   = (const float*)d_in[4];
    const float* bkp  = (const float*)d_in[5];
    const float* Wv   = (const float*)d_in[6];
    const float* bvp  = (const float*)d_in[7];
    const float* Wo   = (const float*)d_in[8];
    const float* bop  = (const float*)d_in[9];
    const float* Erel = (const float*)d_in[10];
    const float* Brel = (const float*)d_in[11];
    const float* g1   = (const float*)d_in[12];
    const float* be1  = (const float*)d_in[13];
    const float* g2   = (const float*)d_in[14];
    const float* be2  = (const float*)d_in[15];
    const float* W1   = (const float*)d_in[16];
    const float* b1   = (const float*)d_in[17];
    const float* W2   = (const float*)d_in[18];
    const float* b2   = (const float*)d_in[19];
    float* outp = (float*)d_out;

    float *x, *y, *k, *v;
    __half *xh, *ah, *ffh, *hh;
    __half *wT4, *w1T, *w2T;
    cudaGetSymbolAddress((void**)&x,  g_x);
    cudaGetSymbolAddress((void**)&y,  g_y);
    cudaGetSymbolAddress((void**)&k,  g_k);
    cudaGetSymbolAddress((void**)&v,  g_v);
    cudaGetSymbolAddress((void**)&xh, g_xh);
    cudaGetSymbolAddress((void**)&ah, g_ah);
    cudaGetSymbolAddress((void**)&ffh, g_ffh);
    cudaGetSymbolAddress((void**)&hh, g_hh);
    cudaGetSymbolAddress((void**)&wT4, g_wT4);
    cudaGetSymbolAddress((void**)&w1T, g_w1T);
    cudaGetSymbolAddress((void**)&w2T, g_w2T);

    cudaFuncSetAttribute(gemm16_kernel,     cudaFuncAttributeMaxDynamicSharedMemorySize, GEMM_SMEM);
    cudaFuncSetAttribute(gemm16_qkv_kernel, cudaFuncAttributeMaxDynamicSharedMemorySize, GEMM_SMEM);

    // ---- preconvert all weights ----
    const dim3 tb(32, 8);
    for (int l = 0; l < Ll; l++) {
        const size_t wdd = (size_t)l * Dm * Dm;
        const size_t o4  = (size_t)l * 4 * Dm * Dm;
        wconv_kernel<<<dim3(Dm / 32, Dm / 32), tb>>>(Wq + wdd, wT4 + o4,                   Dm, Dm);
        wconv_kernel<<<dim3(Dm / 32, Dm / 32), tb>>>(Wk + wdd, wT4 + o4 + (size_t)Dm*Dm,   Dm, Dm);
        wconv_kernel<<<dim3(Dm / 32, Dm / 32), tb>>>(Wv + wdd, wT4 + o4 + (size_t)2*Dm*Dm, Dm, Dm);
        wconv_kernel<<<dim3(Dm / 32, Dm / 32), tb>>>(Wo + wdd, wT4 + o4 + (size_t)3*Dm*Dm, Dm, Dm);
        wconv_kernel<<<dim3(Ff / 32, Dm / 32), tb>>>(W1 + (size_t)l * Dm * Ff, w1T + (size_t)l * Ff * Dm, Dm, Ff);
        wconv_kernel<<<dim3(Dm / 32, Ff / 32), tb>>>(W2 + (size_t)l * Ff * Dm, w2T + (size_t)l * Dm * Ff, Ff, Dm);
    }

    copy_split_kernel<<<(ROWS * Dm + 255) / 256, 256>>>(x_in, x, xh, ROWS * Dm);

    for (int l = 0; l < Ll; l++) {
        const size_t o4 = (size_t)l * 4 * Dm * Dm;

        gemm16_qkv_kernel<<<dim3(Dm / 128, ROWS / 128, 3), 256, GEMM_SMEM>>>(
            xh, wT4 + o4, bqp + l * Dm, bkp + l * Dm, bvp + l * Dm, Dm, Dm);

        const int qetot = Bq * Hh * Sq * NBb;
        qe_kernel<<<(qetot + 255) / 256, 256>>>(Erel + (size_t)l * NBb * DHd);

        attn_kernel<<<dim3(Sq / 64, Hh, Bq), 128>>>(Brel + (size_t)l * Hh * NBb, rid);

        gemm16_kernel<<<dim3(Dm / 128, ROWS / 128), 256, GEMM_SMEM>>>(
            ah, wT4 + o4 + (size_t)3 * Dm * Dm,
            bop + l * Dm, x, y, nullptr, Dm, Dm, 0);

        ln_kernel<<<ROWS, 256>>>(y, g1 + l * Dm, be1 + l * Dm, k, ffh);

        gemm16_kernel<<<dim3(Ff / 128, ROWS / 128), 256, GEMM_SMEM>>>(
            ffh, w1T + (size_t)l * Ff * Dm,
            b1 + l * Ff, nullptr, nullptr, hh, Ff, Dm, 1);

        gemm16_kernel<<<dim3(Dm / 128, ROWS / 128), 256, GEMM_SMEM>>>(
            hh, w2T + (size_t)l * Dm * Ff,
            b2 + l * Dm, k, v, nullptr, Dm, Ff, 0);

        ln_kernel<<<ROWS, 256>>>(v, g2 + l * Dm, be2 + l * Dm,
                                 (l == Ll - 1) ? outp : x, xh);
    }
}

// round 13
// speedup vs baseline: 2.2339x; 1.1390x over previous
#include <cuda_runtime.h>
#include <cuda_fp16.h>
#include <math_constants.h>
#include <cstdint>

// Problem constants
#define Bq   4
#define Sq   1024
#define Dm   1024
#define Hh   16
#define DHd  64
#define Ff   4096
#define NBb  33
#define Ll   6
#define ROWS (Bq*Sq)
#define SCALE_ATTN 0.125f

// ---------------- scratch (device globals) ----------------
__device__ float g_x [ROWS*Dm];
__device__ float g_y [ROWS*Dm];
__device__ float g_k [ROWS*Dm];
__device__ float g_v [ROWS*Dm];
__device__ float g_qe[Bq*Hh*Sq*NBb];

// fp16 activations. GEMM A-operands (xh, ah, ffh, hh) are BLOCKED layout;
// attention operands (qh2, kh2, vh2) stay row-major.
__device__ __half g_xh [ROWS*Dm];
__device__ __half g_ah [ROWS*Dm];
__device__ __half g_ffh[ROWS*Dm];
__device__ __half g_hh [ROWS*Ff];
__device__ __half g_qh2[ROWS*Dm];
__device__ __half g_kh2[ROWS*Dm];
__device__ __half g_vh2[ROWS*Dm];

// transposed fp16 weights, BLOCKED: [nb][kc][128x64 swizzled tile]
__device__ __half g_wT4[Ll*4*Dm*Dm];
__device__ __half g_w1T[Ll*Ff*Dm];
__device__ __half g_w2T[Ll*Dm*Ff];

// ---------------- blocked layout: tile 128 rows x 64 cols, SW128 swizzle ---------
// element index of (row, col) in a [M][K]-logical blocked array
__device__ __forceinline__ size_t blk_idx(int row, int col, int K) {
    uint32_t byte = (uint32_t)((row & 127) * 128 + (col & 63) * 2);
    byte ^= ((byte >> 3) & 0x70);
    return ((size_t)(row >> 7) * (K >> 6) + (col >> 6)) * 8192 + (byte >> 1);
}

// ---------------- common asm helpers ----------------
__device__ __forceinline__ uint32_t s2u(const void* p) {
    uint32_t a;
    asm("{ .reg .u64 t; cvta.to.shared.u64 t, %1; cvt.u32.u64 %0, t; }" : "=r"(a) : "l"(p));
    return a;
}
__device__ __forceinline__ void cp16s(uint32_t s, const void* g) {
    asm volatile("cp.async.cg.shared.global [%0], [%1], 16;\n" :: "r"(s), "l"(g));
}
__device__ __forceinline__ void mma_f16(float* c, const uint32_t* a, uint32_t b0, uint32_t b1) {
    asm volatile(
        "mma.sync.aligned.m16n8k16.row.col.f32.f16.f16.f32 "
        "{%0,%1,%2,%3}, {%4,%5,%6,%7}, {%8,%9}, {%0,%1,%2,%3};\n"
        : "+f"(c[0]), "+f"(c[1]), "+f"(c[2]), "+f"(c[3])
        : "r"(a[0]), "r"(a[1]), "r"(a[2]), "r"(a[3]), "r"(b0), "r"(b1));
}
__device__ __forceinline__ void ldsm4(uint32_t* r, uint32_t addr) {
    asm volatile("ldmatrix.sync.aligned.m8n8.x4.shared.b16 {%0,%1,%2,%3}, [%4];"
                 : "=r"(r[0]), "=r"(r[1]), "=r"(r[2]), "=r"(r[3]) : "r"(addr));
}
__device__ __forceinline__ void ldsm4t(uint32_t* r, uint32_t addr) {
    asm volatile("ldmatrix.sync.aligned.m8n8.x4.trans.shared.b16 {%0,%1,%2,%3}, [%4];"
                 : "=r"(r[0]), "=r"(r[1]), "=r"(r[2]), "=r"(r[3]) : "r"(addr));
}
__device__ __forceinline__ uint32_t pk_h2(float a, float b) {
    __half2 t = __floats2half2_rn(a, b);
    return *(uint32_t*)&t;
}
// mbarrier + bulk copy
__device__ __forceinline__ void mbar_init(uint32_t a, uint32_t c) {
    asm volatile("mbarrier.init.shared.b64 [%0], %1;" :: "r"(a), "r"(c) : "memory");
}
__device__ __forceinline__ void mbar_expect(uint32_t a, uint32_t bytes) {
    asm volatile("mbarrier.arrive.expect_tx.shared.b64 _, [%0], %1;" :: "r"(a), "r"(bytes) : "memory");
}
__device__ __forceinline__ void mbar_wait(uint32_t a, uint32_t ph) {
    asm volatile(
        "{\n\t.reg .pred P;\n\t"
        "W%=:\n\t"
        "mbarrier.try_wait.parity.shared::cta.b64 P, [%0], %1, 0x989680;\n\t"
        "@!P bra W%=;\n\t}"
        :: "r"(a), "r"(ph) : "memory");
}
__device__ __forceinline__ void bulkcp(uint32_t dst, const void* src, uint32_t bytes, uint32_t mbar) {
    asm volatile(
        "cp.async.bulk.shared::cta.global.mbarrier::complete_tx::bytes [%0], [%1], %2, [%3];"
        :: "r"(dst), "l"(src), "r"(bytes), "r"(mbar) : "memory");
}

// ---------------- weight transpose -> blocked fp16 [N][K] ----------------
__global__ void wconv_kernel(const float* __restrict__ W,
                             __half* __restrict__ T, int K, int N)
{
    __shared__ float t[32][33];
    int n0 = blockIdx.x * 32, k0 = blockIdx.y * 32;
    int tx = threadIdx.x, ty = threadIdx.y;
#pragma unroll
    for (int i = 0; i < 4; i++)
        t[ty + 8 * i][tx] = W[(size_t)(k0 + ty + 8 * i) * N + n0 + tx];
    __syncthreads();
#pragma unroll
    for (int i = 0; i < 4; i++) {
        float f = t[tx][ty + 8 * i];
        int n = n0 + ty + 8 * i, k = k0 + tx;
        T[blk_idx(n, k, K)] = __float2half_rn(f);
    }
}

// ---------------- copy + convert (blocked fp16 out) ----------------
__global__ void copy_split_kernel(const float* __restrict__ in, float* __restrict__ out,
                                  __half* __restrict__ oh, int n)
{
    int i = blockIdx.x * blockDim.x + threadIdx.x;
    if (i < n) {
        float f = in[i];
        out[i] = f;
        oh[blk_idx(i / Dm, i % Dm, Dm)] = __float2half_rn(f);
    }
}

// =========================================================================
// 1-MMA fp16 GEMM with cp.async.bulk operand loading.
// A,B blocked [*][K/64][128x64 swz tiles]. BK=64 chunks, 3-stage mbarrier pipe.
// =========================================================================
#define TILE_B 16384                       // bytes per 128x64 fp16 tile
#define GEMM_SMEM (1024 + 6 * TILE_B)      // hdr + 3 stages x (A,B)

__device__ __forceinline__ void gemm_tma_core(
    const __half* __restrict__ Ablk, const __half* __restrict__ Bblk,
    const float* __restrict__ bias, const float* __restrict__ resid,
    float* __restrict__ C, __half* __restrict__ ChRow, __half* __restrict__ ChBlk,
    int N, int K, bool relu)
{
    extern __shared__ __align__(128) char smraw[];
    const uint32_t smb   = s2u(smraw);
    const uint32_t mbar  = smb;            // 3 barriers @ 0,8,16
    const uint32_t tiles = smb + 1024;

    const int tid  = threadIdx.x;
    const int lane = tid & 31;
    const int warp = tid >> 5;
    const int wm   = warp >> 1;
    const int wn   = warp & 1;
    const int g    = lane >> 2;
    const int tig  = lane & 3;
    const int mi   = lane >> 3, li = lane & 7;

    const int bm = blockIdx.y * 128, bn = blockIdx.x * 128;
    const int nck = K >> 6;

    if (tid == 0) {
        mbar_init(mbar + 0, 1);
        mbar_init(mbar + 8, 1);
        mbar_init(mbar + 16, 1);
    }
    __syncthreads();

    const char* gA = (const char*)Ablk + (size_t)(bm >> 7) * nck * TILE_B;
    const char* gB = (const char*)Bblk + (size_t)(bn >> 7) * nck * TILE_B;

    if (tid == 0) {
#pragma unroll
        for (int pc = 0; pc < 2; pc++) {
            if (pc < nck) {
                const uint32_t mb = mbar + 8 * pc;
                mbar_expect(mb, 2 * TILE_B);
                bulkcp(tiles + pc * 2 * TILE_B,          gA + (size_t)pc * TILE_B, TILE_B, mb);
                bulkcp(tiles + pc * 2 * TILE_B + TILE_B, gB + (size_t)pc * TILE_B, TILE_B, mb);
            }
        }
    }

    float acc[2][8][4];
#pragma unroll
    for (int i = 0; i < 2; i++)
#pragma unroll
        for (int j = 0; j < 8; j++)
#pragma unroll
            for (int c = 0; c < 4; c++) acc[i][j][c] = 0.f;

    const int rA0 = wm * 32 + (mi & 1) * 8 + li;
    const int rB0 = wn * 64 + (mi >> 1) * 8 + li;
    int ph[3] = {0, 0, 0};

    for (int kc = 0; kc < nck; kc++) {
        const int st = kc % 3;
        mbar_wait(mbar + 8 * st, (uint32_t)ph[st]);
        ph[st] ^= 1;
        const uint32_t aT = tiles + st * 2 * TILE_B;
        const uint32_t bT = aT + TILE_B;

#pragma unroll
        for (int ks = 0; ks < 4; ks++) {
            const uint32_t kA = ks * 32 + (mi >> 1) * 16;
            const uint32_t kB = ks * 32 + (mi & 1) * 16;
            uint32_t a0 = (uint32_t)(rA0 * 128) + kA;        a0 ^= (a0 >> 3) & 0x70;
            uint32_t a1 = (uint32_t)((rA0 + 16) * 128) + kA; a1 ^= (a1 >> 3) & 0x70;
            uint32_t ah0[4], ah1[4];
            ldsm4(ah0, aT + a0);
            ldsm4(ah1, aT + a1);
#pragma unroll
            for (int p = 0; p < 4; p++) {
                uint32_t bo = (uint32_t)((rB0 + p * 16) * 128) + kB; bo ^= (bo >> 3) & 0x70;
                uint32_t bh[4];
                ldsm4(bh, bT + bo);
#pragma unroll
                for (int q = 0; q < 2; q++) {
                    const int nf = 2 * p + q;
                    mma_f16(acc[0][nf], ah0, bh[2 * q], bh[2 * q + 1]);
                    mma_f16(acc[1][nf], ah1, bh[2 * q], bh[2 * q + 1]);
                }
            }
        }
        __syncthreads();
        if (kc + 2 < nck && tid == 0) {
            const int st2 = (kc + 2) % 3;
            const uint32_t mb = mbar + 8 * st2;
            mbar_expect(mb, 2 * TILE_B);
            bulkcp(tiles + st2 * 2 * TILE_B,          gA + (size_t)(kc + 2) * TILE_B, TILE_B, mb);
            bulkcp(tiles + st2 * 2 * TILE_B + TILE_B, gB + (size_t)(kc + 2) * TILE_B, TILE_B, mb);
        }
    }

    // ---- epilogue ----
#pragma unroll
    for (int mf = 0; mf < 2; mf++) {
#pragma unroll
        for (int nf = 0; nf < 8; nf++) {
            const int r0 = bm + wm * 32 + mf * 16 + g;
            const int cc = bn + wn * 64 + nf * 8 + 2 * tig;
            const float bs0 = bias[cc], bs1 = bias[cc + 1];
            float v0 = acc[mf][nf][0] + bs0;
            float v1 = acc[mf][nf][1] + bs1;
            float v2 = acc[mf][nf][2] + bs0;
            float v3 = acc[mf][nf][3] + bs1;
            const size_t i0 = (size_t)r0 * N + cc;
            const size_t i1 = (size_t)(r0 + 8) * N + cc;
            if (resid) {
                const float2 r0v = *(const float2*)(resid + i0);
                const float2 r1v = *(const float2*)(resid + i1);
                v0 += r0v.x; v1 += r0v.y; v2 += r1v.x; v3 += r1v.y;
            }
            if (relu) {
                v0 = fmaxf(v0, 0.f); v1 = fmaxf(v1, 0.f);
                v2 = fmaxf(v2, 0.f); v3 = fmaxf(v3, 0.f);
            }
            if (C) {
                *(float2*)(C + i0) = make_float2(v0, v1);
                *(float2*)(C + i1) = make_float2(v2, v3);
            }
            if (ChRow) {
                *(__half2*)(ChRow + i0) = __floats2half2_rn(v0, v1);
                *(__half2*)(ChRow + i1) = __floats2half2_rn(v2, v3);
            }
            if (ChBlk) {
                *(__half2*)(ChBlk + blk_idx(r0, cc, N))     = __floats2half2_rn(v0, v1);
                *(__half2*)(ChBlk + blk_idx(r0 + 8, cc, N)) = __floats2half2_rn(v2, v3);
            }
        }
    }
}

__global__ __launch_bounds__(256) void gemm16_kernel(
    const __half* __restrict__ Ablk, const __half* __restrict__ Bblk,
    const float* __restrict__ bias, const float* __restrict__ resid,
    float* __restrict__ C, __half* __restrict__ ChRow, __half* __restrict__ ChBlk,
    int N, int K, int relu)
{
    gemm_tma_core(Ablk, Bblk, bias, resid, C, ChRow, ChBlk, N, K, relu != 0);
}

// QKV: z=0 -> fp32 y + fp16 q (row) ; z=1 -> fp16 k (row) ; z=2 -> fp16 v (row)
__global__ __launch_bounds__(256) void gemm16_qkv_kernel(
    const __half* __restrict__ Ablk, const __half* __restrict__ WT,
    const float* __restrict__ bq, const float* __restrict__ bk, const float* __restrict__ bv,
    int N, int K)
{
    const size_t off = (size_t)blockIdx.z * Dm * Dm;
    const float* bias; float* C; __half* Ch;
    if      (blockIdx.z == 0) { bias = bq; C = g_y;     Ch = g_qh2; }
    else if (blockIdx.z == 1) { bias = bk; C = nullptr; Ch = g_kh2; }
    else                      { bias = bv; C = nullptr; Ch = g_vh2; }
    gemm_tma_core(Ablk, WT + off, bias, nullptr, C, Ch, nullptr, N, K, false);
}

// ---------------- qe = q @ Erel^T ----------------
__global__ void qe_kernel(const float* __restrict__ er)
{
    int idx = blockIdx.x * blockDim.x + threadIdx.x;
    const int total = Bq * Hh * Sq * NBb;
    if (idx >= total) return;
    int nb = idx % NBb;
    int s  = (idx / NBb) % Sq;
    int h  = (idx / (NBb * Sq)) % Hh;
    int b  =  idx / (NBb * Sq * Hh);
    const float* qr = g_y + ((size_t)(b * Sq + s)) * Dm + h * DHd;
    const float* e  = er + nb * DHd;
    float acc = 0.f;
#pragma unroll
    for (int d = 0; d < DHd; d++) acc = fmaf(qr[d], e[d], acc);
    g_qe[idx] = acc;
}

// =========================================================================
// MMA flash attention (single fp16). Output g_ah written BLOCKED.
// =========================================================================
#define APITCH 72

__global__ __launch_bounds__(128) void attn_kernel(const float* __restrict__ brel,
                                                   const int* __restrict__ rid)
{
    __shared__ __half K_s[64 * APITCH];
    __shared__ __half V_s[64 * APITCH];
    __shared__ float Cb[64 * NBb];

    const int tid = threadIdx.x, lane = tid & 31, w = tid >> 5;
    const int g = lane >> 2, tig = lane & 3;
    const int b = blockIdx.z, h = blockIdx.y;
    const int q0 = blockIdx.x * 64;

    const uint32_t k_b = s2u(K_s), v_b = s2u(V_s);
    const int mi = lane >> 3, li = lane & 7;

#pragma unroll
    for (int j = 0; j < 4; j++) {
        int chunk = tid + 128 * j;
        int r = chunk >> 3, c8 = chunk & 7;
        size_t go = ((size_t)(b * Sq + q0 + r)) * Dm + h * DHd + c8 * 8;
        uint32_t so = (uint32_t)(r * APITCH + c8 * 8) * 2;
        cp16s(k_b + so, g_qh2 + go);
    }
    asm volatile("cp.async.commit_group;\n cp.async.wait_group 0;\n");
    __syncthreads();

    uint32_t aq[4][4];
    {
        const int row = w * 16 + (mi & 1) * 8 + li;
#pragma unroll
        for (int ks = 0; ks < 4; ks++) {
            uint32_t off = (uint32_t)(row * APITCH + ks * 16 + (mi >> 1) * 8) * 2;
            ldsm4(aq[ks], k_b + off);
        }
    }
    for (int i = tid; i < 64 * NBb; i += 128) {
        int r = i / NBb, nb = i - r * NBb;
        Cb[i] = g_qe[(((size_t)(b * Hh + h)) * Sq + q0 + r) * NBb + nb] + brel[h * NBb + nb];
    }
    __syncthreads();

    float m0 = -CUDART_INF_F, m1 = -CUDART_INF_F, l0 = 0.f, l1 = 0.f;
    float o[8][4];
#pragma unroll
    for (int i = 0; i < 8; i++)
#pragma unroll
        for (int c = 0; c < 4; c++) o[i][c] = 0.f;

    const int qr0 = w * 16 + g;
    const int grow0 = q0 + qr0;

    for (int k0 = 0; k0 < Sq; k0 += 64) {
#pragma unroll
        for (int j = 0; j < 4; j++) {
            int chunk = tid + 128 * j;
            int r = chunk >> 3, c8 = chunk & 7;
            size_t go = ((size_t)(b * Sq + k0 + r)) * Dm + h * DHd + c8 * 8;
            uint32_t so = (uint32_t)(r * APITCH + c8 * 8) * 2;
            cp16s(k_b + so, g_kh2 + go);
            cp16s(v_b + so, g_vh2 + go);
        }
        asm volatile("cp.async.commit_group;\n cp.async.wait_group 0;\n");
        __syncthreads();

        float s[8][4];
#pragma unroll
        for (int i = 0; i < 8; i++)
#pragma unroll
            for (int c = 0; c < 4; c++) s[i][c] = 0.f;

#pragma unroll
        for (int ks = 0; ks < 4; ks++) {
#pragma unroll
            for (int ntp = 0; ntp < 4; ntp++) {
                uint32_t kb[4];
                uint32_t off = (uint32_t)((ntp * 16 + (mi >> 1) * 8 + li) * APITCH
                                          + ks * 16 + (mi & 1) * 8) * 2;
                ldsm4(kb, k_b + off);
                mma_f16(s[2 * ntp],     aq[ks], kb[0], kb[1]);
                mma_f16(s[2 * ntp + 1], aq[ks], kb[2], kb[3]);
            }
        }

        float mt0 = -CUDART_INF_F, mt1 = -CUDART_INF_F;
#pragma unroll
        for (int nt = 0; nt < 8; nt++) {
            const int col = k0 + 8 * nt + 2 * tig;
            const int r0i = rid[(size_t)grow0 * Sq + col];
            const int r1i = rid[(size_t)grow0 * Sq + col + 1];
            const int r2i = rid[(size_t)(grow0 + 8) * Sq + col];
            const int r3i = rid[(size_t)(grow0 + 8) * Sq + col + 1];
            float v0 = (s[nt][0] + Cb[qr0 * NBb + r0i]) * SCALE_ATTN;
            float v1 = (s[nt][1] + Cb[qr0 * NBb + r1i]) * SCALE_ATTN;
            float v2 = (s[nt][2] + Cb[(qr0 + 8) * NBb + r2i]) * SCALE_ATTN;
            float v3 = (s[nt][3] + Cb[(qr0 + 8) * NBb + r3i]) * SCALE_ATTN;
            s[nt][0] = v0; s[nt][1] = v1; s[nt][2] = v2; s[nt][3] = v3;
            mt0 = fmaxf(mt0, fmaxf(v0, v1));
            mt1 = fmaxf(mt1, fmaxf(v2, v3));
        }
        mt0 = fmaxf(mt0, __shfl_xor_sync(0xffffffffu, mt0, 1));
        mt0 = fmaxf(mt0, __shfl_xor_sync(0xffffffffu, mt0, 2));
        mt1 = fmaxf(mt1, __shfl_xor_sync(0xffffffffu, mt1, 1));
        mt1 = fmaxf(mt1, __shfl_xor_sync(0xffffffffu, mt1, 2));

        const float mn0 = fmaxf(m0, mt0), mn1 = fmaxf(m1, mt1);
        const float fac0 = __expf(m0 - mn0), fac1 = __expf(m1 - mn1);
        float rs0 = 0.f, rs1 = 0.f;
#pragma unroll
        for (int nt = 0; nt < 8; nt++) {
            float p0 = __expf(s[nt][0] - mn0);
            float p1 = __expf(s[nt][1] - mn0);
            float p2 = __expf(s[nt][2] - mn1);
            float p3 = __expf(s[nt][3] - mn1);
            s[nt][0] = p0; s[nt][1] = p1; s[nt][2] = p2; s[nt][3] = p3;
            rs0 += p0 + p1; rs1 += p2 + p3;
        }
        rs0 += __shfl_xor_sync(0xffffffffu, rs0, 1);
        rs0 += __shfl_xor_sync(0xffffffffu, rs0, 2);
        rs1 += __shfl_xor_sync(0xffffffffu, rs1, 1);
        rs1 += __shfl_xor_sync(0xffffffffu, rs1, 2);
        l0 = l0 * fac0 + rs0;  m0 = mn0;
        l1 = l1 * fac1 + rs1;  m1 = mn1;
#pragma unroll
        for (int nt = 0; nt < 8; nt++) {
            o[nt][0] *= fac0; o[nt][1] *= fac0;
            o[nt][2] *= fac1; o[nt][3] *= fac1;
        }

#pragma unroll
        for (int ks = 0; ks < 4; ks++) {
            uint32_t ap[4];
            ap[0] = pk_h2(s[2 * ks][0],     s[2 * ks][1]);
            ap[1] = pk_h2(s[2 * ks][2],     s[2 * ks][3]);
            ap[2] = pk_h2(s[2 * ks + 1][0], s[2 * ks + 1][1]);
            ap[3] = pk_h2(s[2 * ks + 1][2], s[2 * ks + 1][3]);
#pragma unroll
            for (int ntp = 0; ntp < 4; ntp++) {
                uint32_t vv[4];
                uint32_t off = (uint32_t)((ks * 16 + (mi & 1) * 8 + li) * APITCH
                                          + (2 * ntp + (mi >> 1)) * 8) * 2;
                ldsm4t(vv, v_b + off);
                mma_f16(o[2 * ntp],     ap, vv[0], vv[1]);
                mma_f16(o[2 * ntp + 1], ap, vv[2], vv[3]);
            }
        }
        __syncthreads();
    }

    // epilogue: normalize, store fp16 BLOCKED (K = Dm)
    const float inv0 = 1.f / l0, inv1 = 1.f / l1;
#pragma unroll
    for (int nt = 0; nt < 8; nt++) {
        const int col = h * DHd + 8 * nt + 2 * tig;
        const int row0 = b * Sq + grow0;
        *(__half2*)(g_ah + blk_idx(row0, col, Dm))     = __floats2half2_rn(o[nt][0] * inv0, o[nt][1] * inv0);
        *(__half2*)(g_ah + blk_idx(row0 + 8, col, Dm)) = __floats2half2_rn(o[nt][2] * inv1, o[nt][3] * inv1);
    }
}

// ---------------- layernorm (blocked fp16 out) ----------------
__device__ __forceinline__ float block_sum_256(float val, float* sh) {
#pragma unroll
    for (int off = 16; off; off >>= 1) val += __shfl_xor_sync(0xffffffffu, val, off);
    if ((threadIdx.x & 31) == 0) sh[threadIdx.x >> 5] = val;
    __syncthreads();
    float t = 0.f;
    if (threadIdx.x < 8) t = sh[threadIdx.x];
    if (threadIdx.x < 32) {
#pragma unroll
        for (int off = 4; off; off >>= 1) t += __shfl_xor_sync(0xffffffffu, t, off);
        if (threadIdx.x == 0) sh[0] = t;
    }
    __syncthreads();
    float r = sh[0];
    __syncthreads();
    return r;
}

__global__ void ln_kernel(const float* __restrict__ in, const float* __restrict__ gam,
                          const float* __restrict__ bet, float* __restrict__ out,
                          __half* __restrict__ oh)
{
    __shared__ float sh[8];
    int row = blockIdx.x, tid = threadIdx.x;
    float4 x4 = ((const float4*)(in + (size_t)row * Dm))[tid];
    float s = x4.x + x4.y + x4.z + x4.w;
    float mean = block_sum_256(s, sh) * (1.f / Dm);
    float dx = x4.x - mean, dy = x4.y - mean, dz = x4.z - mean, dw = x4.w - mean;
    float s2 = dx * dx + dy * dy + dz * dz + dw * dw;
    float var = block_sum_256(s2, sh) * (1.f / Dm);
    float inv = rsqrtf(var + 1e-6f);
    int c = tid * 4;
    float4 o;
    o.x = dx * inv * gam[c + 0] + bet[c + 0];
    o.y = dy * inv * gam[c + 1] + bet[c + 1];
    o.z = dz * inv * gam[c + 2] + bet[c + 2];
    o.w = dw * inv * gam[c + 3] + bet[c + 3];
    ((float4*)(out + (size_t)row * Dm))[tid] = o;
    if (oh) {
        *(__half2*)(oh + blk_idx(row, c, Dm))     = __floats2half2_rn(o.x, o.y);
        *(__half2*)(oh + blk_idx(row, c + 2, Dm)) = __floats2half2_rn(o.z, o.w);
    }
}

// ---------------- launch ----------------
extern "C" void kernel_launch(void* const* d_in, const int* in_sizes, int n_in,
                              void* d_out, int out_size)
{
    const float* x_in = (const float*)d_in[0];
    const int*   rid  = (const int*)  d_in[1];
    const float* Wq   = (const float*)d_in[2];
    const float* bqp  = (const float*)d_in[3];
    const float* Wk   = (const float*)d_in[4];
    const float* bkp  = (const float*)d_in[5];
    const float* Wv   = (const float*)d_in[6];
    const float* bvp  = (const float*)d_in[7];
    const float* Wo   = (const float*)d_in[8];
    const float* bop  = (const float*)d_in[9];
    const float* Erel = (const float*)d_in[10];
    const float* Brel = (const float*)d_in[11];
    const float* g1   = (const float*)d_in[12];
    const float* be1  = (const float*)d_in[13];
    const float* g2   = (const float*)d_in[14];
    const float* be2  = (const float*)d_in[15];
    const float* W1   = (const float*)d_in[16];
    const float* b1   = (const float*)d_in[17];
    const float* W2   = (const float*)d_in[18];
    const float* b2   = (const float*)d_in[19];
    float* outp = (float*)d_out;

    float *x, *y, *k, *v;
    __half *xh, *ah, *ffh, *hh;
    __half *wT4, *w1T, *w2T;
    cudaGetSymbolAddress((void**)&x,  g_x);
    cudaGetSymbolAddress((void**)&y,  g_y);
    cudaGetSymbolAddress((void**)&k,  g_k);
    cudaGetSymbolAddress((void**)&v,  g_v);
    cudaGetSymbolAddress((void**)&xh, g_xh);
    cudaGetSymbolAddress((void**)&ah, g_ah);
    cudaGetSymbolAddress((void**)&ffh, g_ffh);
    cudaGetSymbolAddress((void**)&hh, g_hh);
    cudaGetSymbolAddress((void**)&wT4, g_wT4);
    cudaGetSymbolAddress((void**)&w1T, g_w1T);
    cudaGetSymbolAddress((void**)&w2T, g_w2T);

    cudaFuncSetAttribute(gemm16_kernel,     cudaFuncAttributeMaxDynamicSharedMemorySize, GEMM_SMEM);
    cudaFuncSetAttribute(gemm16_qkv_kernel, cudaFuncAttributeMaxDynamicSharedMemorySize, GEMM_SMEM);

    // ---- preconvert all weights (transpose -> blocked fp16) ----
    const dim3 tb(32, 8);
    for (int l = 0; l < Ll; l++) {
        const size_t wdd = (size_t)l * Dm * Dm;
        const size_t o4  = (size_t)l * 4 * Dm * Dm;
        wconv_kernel<<<dim3(Dm / 32, Dm / 32), tb>>>(Wq + wdd, wT4 + o4,                   Dm, Dm);
        wconv_kernel<<<dim3(Dm / 32, Dm / 32), tb>>>(Wk + wdd, wT4 + o4 + (size_t)Dm*Dm,   Dm, Dm);
        wconv_kernel<<<dim3(Dm / 32, Dm / 32), tb>>>(Wv + wdd, wT4 + o4 + (size_t)2*Dm*Dm, Dm, Dm);
        wconv_kernel<<<dim3(Dm / 32, Dm / 32), tb>>>(Wo + wdd, wT4 + o4 + (size_t)3*Dm*Dm, Dm, Dm);
        wconv_kernel<<<dim3(Ff / 32, Dm / 32), tb>>>(W1 + (size_t)l * Dm * Ff, w1T + (size_t)l * Ff * Dm, Dm, Ff);
        wconv_kernel<<<dim3(Dm / 32, Ff / 32), tb>>>(W2 + (size_t)l * Ff * Dm, w2T + (size_t)l * Dm * Ff, Ff, Dm);
    }

    copy_split_kernel<<<(ROWS * Dm + 255) / 256, 256>>>(x_in, x, xh, ROWS * Dm);

    for (int l = 0; l < Ll; l++) {
        const size_t o4 = (size_t)l * 4 * Dm * Dm;

        gemm16_qkv_kernel<<<dim3(Dm / 128, ROWS / 128, 3), 256, GEMM_SMEM>>>(
            xh, wT4 + o4, bqp + l * Dm, bkp + l * Dm, bvp + l * Dm, Dm, Dm);

        const int qetot = Bq * Hh * Sq * NBb;
        qe_kernel<<<(qetot + 255) / 256, 256>>>(Erel + (size_t)l * NBb * DHd);

        attn_kernel<<<dim3(Sq / 64, Hh, Bq), 128>>>(Brel + (size_t)l * Hh * NBb, rid);

        gemm16_kernel<<<dim3(Dm / 128, ROWS / 128), 256, GEMM_SMEM>>>(
            ah, wT4 + o4 + (size_t)3 * Dm * Dm,
            bop + l * Dm, x, y, nullptr, nullptr, Dm, Dm, 0);

        ln_kernel<<<ROWS, 256>>>(y, g1 + l * Dm, be1 + l * Dm, k, ffh);

        gemm16_kernel<<<dim3(Ff / 128, ROWS / 128), 256, GEMM_SMEM>>>(
            ffh, w1T + (size_t)l * Ff * Dm,
            b1 + l * Ff, nullptr, nullptr, nullptr, hh, Ff, Dm, 1);

        gemm16_kernel<<<dim3(Dm / 128, ROWS / 128), 256, GEMM_SMEM>>>(
            hh, w2T + (size_t)l * Dm * Ff,
            b2 + l * Dm, k, v, nullptr, nullptr, Dm, Ff, 0);

        ln_kernel<<<ROWS, 256>>>(v, g2 + l * Dm, be2 + l * Dm,
                                 (l == Ll - 1) ? outp : x, xh);
    }
}

// round 14
// speedup vs baseline: 2.2609x; 1.0121x over previous
#include <cuda_runtime.h>
#include <cuda_fp16.h>
#include <math_constants.h>
#include <cstdint>

// Problem constants
#define Bq   4
#define Sq   1024
#define Dm   1024
#define Hh   16
#define DHd  64
#define Ff   4096
#define NBb  33
#define Ll   6
#define ROWS (Bq*Sq)
#define SCALE_ATTN 0.125f

// ---------------- scratch (device globals) ----------------
__device__ float g_x [ROWS*Dm];
__device__ float g_y [ROWS*Dm];
__device__ float g_k [ROWS*Dm];
__device__ float g_v [ROWS*Dm];
__device__ float g_qe[Bq*Hh*Sq*NBb];
__device__ unsigned char g_rid8[Sq*Sq];

// fp16 activations. GEMM A-operands blocked; attention operands row-major.
__device__ __half g_xh [ROWS*Dm];
__device__ __half g_ah [ROWS*Dm];
__device__ __half g_ffh[ROWS*Dm];
__device__ __half g_hh [ROWS*Ff];
__device__ __half g_qh2[ROWS*Dm];
__device__ __half g_kh2[ROWS*Dm];
__device__ __half g_vh2[ROWS*Dm];

// transposed fp16 weights, BLOCKED: [nb][kc][128x64 swizzled tile]
__device__ __half g_wT4[Ll*4*Dm*Dm];
__device__ __half g_w1T[Ll*Ff*Dm];
__device__ __half g_w2T[Ll*Dm*Ff];

// ---------------- blocked layout: tile 128 rows x 64 cols, SW128 swizzle ---------
__device__ __forceinline__ size_t blk_idx(int row, int col, int K) {
    uint32_t byte = (uint32_t)((row & 127) * 128 + (col & 63) * 2);
    byte ^= ((byte >> 3) & 0x70);
    return ((size_t)(row >> 7) * (K >> 6) + (col >> 6)) * 8192 + (byte >> 1);
}

// ---------------- common asm helpers ----------------
__device__ __forceinline__ uint32_t s2u(const void* p) {
    uint32_t a;
    asm("{ .reg .u64 t; cvta.to.shared.u64 t, %1; cvt.u32.u64 %0, t; }" : "=r"(a) : "l"(p));
    return a;
}
__device__ __forceinline__ void cp16s(uint32_t s, const void* g) {
    asm volatile("cp.async.cg.shared.global [%0], [%1], 16;\n" :: "r"(s), "l"(g));
}
__device__ __forceinline__ void mma_f16(float* c, const uint32_t* a, uint32_t b0, uint32_t b1) {
    asm volatile(
        "mma.sync.aligned.m16n8k16.row.col.f32.f16.f16.f32 "
        "{%0,%1,%2,%3}, {%4,%5,%6,%7}, {%8,%9}, {%0,%1,%2,%3};\n"
        : "+f"(c[0]), "+f"(c[1]), "+f"(c[2]), "+f"(c[3])
        : "r"(a[0]), "r"(a[1]), "r"(a[2]), "r"(a[3]), "r"(b0), "r"(b1));
}
__device__ __forceinline__ void ldsm4(uint32_t* r, uint32_t addr) {
    asm volatile("ldmatrix.sync.aligned.m8n8.x4.shared.b16 {%0,%1,%2,%3}, [%4];"
                 : "=r"(r[0]), "=r"(r[1]), "=r"(r[2]), "=r"(r[3]) : "r"(addr));
}
__device__ __forceinline__ void ldsm4t(uint32_t* r, uint32_t addr) {
    asm volatile("ldmatrix.sync.aligned.m8n8.x4.trans.shared.b16 {%0,%1,%2,%3}, [%4];"
                 : "=r"(r[0]), "=r"(r[1]), "=r"(r[2]), "=r"(r[3]) : "r"(addr));
}
__device__ __forceinline__ uint32_t pk_h2(float a, float b) {
    __half2 t = __floats2half2_rn(a, b);
    return *(uint32_t*)&t;
}
__device__ __forceinline__ void mbar_init(uint32_t a, uint32_t c) {
    asm volatile("mbarrier.init.shared.b64 [%0], %1;" :: "r"(a), "r"(c) : "memory");
}
__device__ __forceinline__ void mbar_expect(uint32_t a, uint32_t bytes) {
    asm volatile("mbarrier.arrive.expect_tx.shared.b64 _, [%0], %1;" :: "r"(a), "r"(bytes) : "memory");
}
__device__ __forceinline__ void mbar_wait(uint32_t a, uint32_t ph) {
    asm volatile(
        "{\n\t.reg .pred P;\n\t"
        "W%=:\n\t"
        "mbarrier.try_wait.parity.shared::cta.b64 P, [%0], %1, 0x989680;\n\t"
        "@!P bra W%=;\n\t}"
        :: "r"(a), "r"(ph) : "memory");
}
__device__ __forceinline__ void bulkcp(uint32_t dst, const void* src, uint32_t bytes, uint32_t mbar) {
    asm volatile(
        "cp.async.bulk.shared::cta.global.mbarrier::complete_tx::bytes [%0], [%1], %2, [%3];"
        :: "r"(dst), "l"(src), "r"(bytes), "r"(mbar) : "memory");
}

// ---------------- weight transpose -> blocked fp16 [N][K] ----------------
__global__ void wconv_kernel(const float* __restrict__ W,
                             __half* __restrict__ T, int K, int N)
{
    __shared__ float t[32][33];
    int n0 = blockIdx.x * 32, k0 = blockIdx.y * 32;
    int tx = threadIdx.x, ty = threadIdx.y;
#pragma unroll
    for (int i = 0; i < 4; i++)
        t[ty + 8 * i][tx] = W[(size_t)(k0 + ty + 8 * i) * N + n0 + tx];
    __syncthreads();
#pragma unroll
    for (int i = 0; i < 4; i++) {
        float f = t[tx][ty + 8 * i];
        int n = n0 + ty + 8 * i, k = k0 + tx;
        T[blk_idx(n, k, K)] = __float2half_rn(f);
    }
}

// ---------------- rid -> uint8 ----------------
__global__ void rid8_kernel(const int* __restrict__ rid, int n)
{
    int i = blockIdx.x * blockDim.x + threadIdx.x;
    if (i < n) g_rid8[i] = (unsigned char)rid[i];
}

// ---------------- copy + convert (blocked fp16 out) ----------------
__global__ void copy_split_kernel(const float* __restrict__ in, float* __restrict__ out,
                                  __half* __restrict__ oh, int n)
{
    int i = blockIdx.x * blockDim.x + threadIdx.x;
    if (i < n) {
        float f = in[i];
        out[i] = f;
        oh[blk_idx(i / Dm, i % Dm, Dm)] = __float2half_rn(f);
    }
}

// =========================================================================
// 1-MMA fp16 GEMM with cp.async.bulk, prefetch hoisted before compute.
// =========================================================================
#define TILE_B 16384
#define GEMM_SMEM (1024 + 6 * TILE_B)

__device__ __forceinline__ void gemm_tma_core(
    const __half* __restrict__ Ablk, const __half* __restrict__ Bblk,
    const float* __restrict__ bias, const float* __restrict__ resid,
    float* __restrict__ C, __half* __restrict__ ChRow, __half* __restrict__ ChBlk,
    int N, int K, bool relu)
{
    extern __shared__ __align__(128) char smraw[];
    const uint32_t smb   = s2u(smraw);
    const uint32_t mbar  = smb;
    const uint32_t tiles = smb + 1024;

    const int tid  = threadIdx.x;
    const int lane = tid & 31;
    const int warp = tid >> 5;
    const int wm   = warp >> 1;
    const int wn   = warp & 1;
    const int g    = lane >> 2;
    const int tig  = lane & 3;
    const int mi   = lane >> 3, li = lane & 7;

    const int bm = blockIdx.y * 128, bn = blockIdx.x * 128;
    const int nck = K >> 6;

    if (tid == 0) {
        mbar_init(mbar + 0, 1);
        mbar_init(mbar + 8, 1);
        mbar_init(mbar + 16, 1);
    }
    __syncthreads();

    const char* gA = (const char*)Ablk + (size_t)(bm >> 7) * nck * TILE_B;
    const char* gB = (const char*)Bblk + (size_t)(bn >> 7) * nck * TILE_B;

    if (tid == 0) {
#pragma unroll
        for (int pc = 0; pc < 2; pc++) {
            if (pc < nck) {
                const uint32_t mb = mbar + 8 * pc;
                mbar_expect(mb, 2 * TILE_B);
                bulkcp(tiles + pc * 2 * TILE_B,          gA + (size_t)pc * TILE_B, TILE_B, mb);
                bulkcp(tiles + pc * 2 * TILE_B + TILE_B, gB + (size_t)pc * TILE_B, TILE_B, mb);
            }
        }
    }

    float acc[2][8][4];
#pragma unroll
    for (int i = 0; i < 2; i++)
#pragma unroll
        for (int j = 0; j < 8; j++)
#pragma unroll
            for (int c = 0; c < 4; c++) acc[i][j][c] = 0.f;

    const int rA0 = wm * 32 + (mi & 1) * 8 + li;
    const int rB0 = wn * 64 + (mi >> 1) * 8 + li;
    int ph[3] = {0, 0, 0};

    for (int kc = 0; kc < nck; kc++) {
        const int st = kc % 3;
        mbar_wait(mbar + 8 * st, (uint32_t)ph[st]);
        ph[st] ^= 1;
        // hoisted prefetch: buffer (kc+2)%3 was freed by sync at end of kc-1
        if (kc + 2 < nck && tid == 0) {
            const int st2 = (kc + 2) % 3;
            const uint32_t mb = mbar + 8 * st2;
            mbar_expect(mb, 2 * TILE_B);
            bulkcp(tiles + st2 * 2 * TILE_B,          gA + (size_t)(kc + 2) * TILE_B, TILE_B, mb);
            bulkcp(tiles + st2 * 2 * TILE_B + TILE_B, gB + (size_t)(kc + 2) * TILE_B, TILE_B, mb);
        }
        const uint32_t aT = tiles + st * 2 * TILE_B;
        const uint32_t bT = aT + TILE_B;

#pragma unroll
        for (int ks = 0; ks < 4; ks++) {
            const uint32_t kA = ks * 32 + (mi >> 1) * 16;
            const uint32_t kB = ks * 32 + (mi & 1) * 16;
            uint32_t a0 = (uint32_t)(rA0 * 128) + kA;        a0 ^= (a0 >> 3) & 0x70;
            uint32_t a1 = (uint32_t)((rA0 + 16) * 128) + kA; a1 ^= (a1 >> 3) & 0x70;
            uint32_t ah0[4], ah1[4];
            ldsm4(ah0, aT + a0);
            ldsm4(ah1, aT + a1);
#pragma unroll
            for (int p = 0; p < 4; p++) {
                uint32_t bo = (uint32_t)((rB0 + p * 16) * 128) + kB; bo ^= (bo >> 3) & 0x70;
                uint32_t bh[4];
                ldsm4(bh, bT + bo);
#pragma unroll
                for (int q = 0; q < 2; q++) {
                    const int nf = 2 * p + q;
                    mma_f16(acc[0][nf], ah0, bh[2 * q], bh[2 * q + 1]);
                    mma_f16(acc[1][nf], ah1, bh[2 * q], bh[2 * q + 1]);
                }
            }
        }
        __syncthreads();
    }

    // ---- epilogue ----
#pragma unroll
    for (int mf = 0; mf < 2; mf++) {
#pragma unroll
        for (int nf = 0; nf < 8; nf++) {
            const int r0 = bm + wm * 32 + mf * 16 + g;
            const int cc = bn + wn * 64 + nf * 8 + 2 * tig;
            const float bs0 = bias[cc], bs1 = bias[cc + 1];
            float v0 = acc[mf][nf][0] + bs0;
            float v1 = acc[mf][nf][1] + bs1;
            float v2 = acc[mf][nf][2] + bs0;
            float v3 = acc[mf][nf][3] + bs1;
            const size_t i0 = (size_t)r0 * N + cc;
            const size_t i1 = (size_t)(r0 + 8) * N + cc;
            if (resid) {
                const float2 r0v = *(const float2*)(resid + i0);
                const float2 r1v = *(const float2*)(resid + i1);
                v0 += r0v.x; v1 += r0v.y; v2 += r1v.x; v3 += r1v.y;
            }
            if (relu) {
                v0 = fmaxf(v0, 0.f); v1 = fmaxf(v1, 0.f);
                v2 = fmaxf(v2, 0.f); v3 = fmaxf(v3, 0.f);
            }
            if (C) {
                *(float2*)(C + i0) = make_float2(v0, v1);
                *(float2*)(C + i1) = make_float2(v2, v3);
            }
            if (ChRow) {
                *(__half2*)(ChRow + i0) = __floats2half2_rn(v0, v1);
                *(__half2*)(ChRow + i1) = __floats2half2_rn(v2, v3);
            }
            if (ChBlk) {
                *(__half2*)(ChBlk + blk_idx(r0, cc, N))     = __floats2half2_rn(v0, v1);
                *(__half2*)(ChBlk + blk_idx(r0 + 8, cc, N)) = __floats2half2_rn(v2, v3);
            }
        }
    }
}

__global__ __launch_bounds__(256) void gemm16_kernel(
    const __half* __restrict__ Ablk, const __half* __restrict__ Bblk,
    const float* __restrict__ bias, const float* __restrict__ resid,
    float* __restrict__ C, __half* __restrict__ ChRow, __half* __restrict__ ChBlk,
    int N, int K, int relu)
{
    gemm_tma_core(Ablk, Bblk, bias, resid, C, ChRow, ChBlk, N, K, relu != 0);
}

// QKV: z=0 -> fp16 q ; z=1 -> fp16 k ; z=2 -> fp16 v  (no fp32 output)
__global__ __launch_bounds__(256) void gemm16_qkv_kernel(
    const __half* __restrict__ Ablk, const __half* __restrict__ WT,
    const float* __restrict__ bq, const float* __restrict__ bk, const float* __restrict__ bv,
    int N, int K)
{
    const size_t off = (size_t)blockIdx.z * Dm * Dm;
    const float* bias; __half* Ch;
    if      (blockIdx.z == 0) { bias = bq; Ch = g_qh2; }
    else if (blockIdx.z == 1) { bias = bk; Ch = g_kh2; }
    else                      { bias = bv; Ch = g_vh2; }
    gemm_tma_core(Ablk, WT + off, bias, nullptr, nullptr, Ch, nullptr, N, K, false);
}

// ---------------- qe = q @ Erel^T  (q read as fp16) ----------------
__global__ void qe_kernel(const float* __restrict__ er)
{
    int idx = blockIdx.x * blockDim.x + threadIdx.x;
    const int total = Bq * Hh * Sq * NBb;
    if (idx >= total) return;
    int nb = idx % NBb;
    int s  = (idx / NBb) % Sq;
    int h  = (idx / (NBb * Sq)) % Hh;
    int b  =  idx / (NBb * Sq * Hh);
    const __half* qr = g_qh2 + ((size_t)(b * Sq + s)) * Dm + h * DHd;
    const float* e  = er + nb * DHd;
    float acc = 0.f;
#pragma unroll
    for (int d = 0; d < DHd; d++) acc = fmaf(__half2float(qr[d]), e[d], acc);
    g_qe[idx] = acc;
}

// =========================================================================
// MMA flash attention (single fp16), rid tile staged in smem as uint8.
// =========================================================================
#define APITCH 72

__global__ __launch_bounds__(128) void attn_kernel(const float* __restrict__ brel)
{
    __shared__ __half K_s[64 * APITCH];
    __shared__ __half V_s[64 * APITCH];
    __shared__ unsigned char R_s[64 * 64];
    __shared__ float Cb[64 * NBb];

    const int tid = threadIdx.x, lane = tid & 31, w = tid >> 5;
    const int g = lane >> 2, tig = lane & 3;
    const int b = blockIdx.z, h = blockIdx.y;
    const int q0 = blockIdx.x * 64;

    const uint32_t k_b = s2u(K_s), v_b = s2u(V_s), r_b = s2u(R_s);
    const int mi = lane >> 3, li = lane & 7;

    // ---- stage Q, build fragments ----
#pragma unroll
    for (int j = 0; j < 4; j++) {
        int chunk = tid + 128 * j;
        int r = chunk >> 3, c8 = chunk & 7;
        size_t go = ((size_t)(b * Sq + q0 + r)) * Dm + h * DHd + c8 * 8;
        uint32_t so = (uint32_t)(r * APITCH + c8 * 8) * 2;
        cp16s(k_b + so, g_qh2 + go);
    }
    asm volatile("cp.async.commit_group;\n cp.async.wait_group 0;\n");
    __syncthreads();

    uint32_t aq[4][4];
    {
        const int row = w * 16 + (mi & 1) * 8 + li;
#pragma unroll
        for (int ks = 0; ks < 4; ks++) {
            uint32_t off = (uint32_t)(row * APITCH + ks * 16 + (mi >> 1) * 8) * 2;
            ldsm4(aq[ks], k_b + off);
        }
    }
    for (int i = tid; i < 64 * NBb; i += 128) {
        int r = i / NBb, nb = i - r * NBb;
        Cb[i] = g_qe[(((size_t)(b * Hh + h)) * Sq + q0 + r) * NBb + nb] + brel[h * NBb + nb];
    }
    __syncthreads();

    float m0 = -CUDART_INF_F, m1 = -CUDART_INF_F, l0 = 0.f, l1 = 0.f;
    float o[8][4];
#pragma unroll
    for (int i = 0; i < 8; i++)
#pragma unroll
        for (int c = 0; c < 4; c++) o[i][c] = 0.f;

    const int qr0 = w * 16 + g;
    const int grow0 = q0 + qr0;

    for (int k0 = 0; k0 < Sq; k0 += 64) {
        // K, V tiles + rid uint8 tile
#pragma unroll
        for (int j = 0; j < 4; j++) {
            int chunk = tid + 128 * j;
            int r = chunk >> 3, c8 = chunk & 7;
            size_t go = ((size_t)(b * Sq + k0 + r)) * Dm + h * DHd + c8 * 8;
            uint32_t so = (uint32_t)(r * APITCH + c8 * 8) * 2;
            cp16s(k_b + so, g_kh2 + go);
            cp16s(v_b + so, g_vh2 + go);
        }
#pragma unroll
        for (int j = 0; j < 2; j++) {
            int c2 = tid + 128 * j;
            int r = c2 >> 2, c16 = (c2 & 3) * 16;
            cp16s(r_b + (uint32_t)(r * 64 + c16),
                  g_rid8 + (size_t)(q0 + r) * Sq + k0 + c16);
        }
        asm volatile("cp.async.commit_group;\n cp.async.wait_group 0;\n");
        __syncthreads();

        // ---- S = Q K^T ----
        float s[8][4];
#pragma unroll
        for (int i = 0; i < 8; i++)
#pragma unroll
            for (int c = 0; c < 4; c++) s[i][c] = 0.f;

#pragma unroll
        for (int ks = 0; ks < 4; ks++) {
#pragma unroll
            for (int ntp = 0; ntp < 4; ntp++) {
                uint32_t kb[4];
                uint32_t off = (uint32_t)((ntp * 16 + (mi >> 1) * 8 + li) * APITCH
                                          + ks * 16 + (mi & 1) * 8) * 2;
                ldsm4(kb, k_b + off);
                mma_f16(s[2 * ntp],     aq[ks], kb[0], kb[1]);
                mma_f16(s[2 * ntp + 1], aq[ks], kb[2], kb[3]);
            }
        }

        // ---- rel terms (rid from smem) + scale + online softmax ----
        float mt0 = -CUDART_INF_F, mt1 = -CUDART_INF_F;
#pragma unroll
        for (int nt = 0; nt < 8; nt++) {
            const int colL = 8 * nt + 2 * tig;
            uchar2 rr0 = *(const uchar2*)(R_s + qr0 * 64 + colL);
            uchar2 rr1 = *(const uchar2*)(R_s + (qr0 + 8) * 64 + colL);
            float v0 = (s[nt][0] + Cb[qr0 * NBb + rr0.x]) * SCALE_ATTN;
            float v1 = (s[nt][1] + Cb[qr0 * NBb + rr0.y]) * SCALE_ATTN;
            float v2 = (s[nt][2] + Cb[(qr0 + 8) * NBb + rr1.x]) * SCALE_ATTN;
            float v3 = (s[nt][3] + Cb[(qr0 + 8) * NBb + rr1.y]) * SCALE_ATTN;
            s[nt][0] = v0; s[nt][1] = v1; s[nt][2] = v2; s[nt][3] = v3;
            mt0 = fmaxf(mt0, fmaxf(v0, v1));
            mt1 = fmaxf(mt1, fmaxf(v2, v3));
        }
        mt0 = fmaxf(mt0, __shfl_xor_sync(0xffffffffu, mt0, 1));
        mt0 = fmaxf(mt0, __shfl_xor_sync(0xffffffffu, mt0, 2));
        mt1 = fmaxf(mt1, __shfl_xor_sync(0xffffffffu, mt1, 1));
        mt1 = fmaxf(mt1, __shfl_xor_sync(0xffffffffu, mt1, 2));

        const float mn0 = fmaxf(m0, mt0), mn1 = fmaxf(m1, mt1);
        const float fac0 = __expf(m0 - mn0), fac1 = __expf(m1 - mn1);
        float rs0 = 0.f, rs1 = 0.f;
#pragma unroll
        for (int nt = 0; nt < 8; nt++) {
            float p0 = __expf(s[nt][0] - mn0);
            float p1 = __expf(s[nt][1] - mn0);
            float p2 = __expf(s[nt][2] - mn1);
            float p3 = __expf(s[nt][3] - mn1);
            s[nt][0] = p0; s[nt][1] = p1; s[nt][2] = p2; s[nt][3] = p3;
            rs0 += p0 + p1; rs1 += p2 + p3;
        }
        rs0 += __shfl_xor_sync(0xffffffffu, rs0, 1);
        rs0 += __shfl_xor_sync(0xffffffffu, rs0, 2);
        rs1 += __shfl_xor_sync(0xffffffffu, rs1, 1);
        rs1 += __shfl_xor_sync(0xffffffffu, rs1, 2);
        l0 = l0 * fac0 + rs0;  m0 = mn0;
        l1 = l1 * fac1 + rs1;  m1 = mn1;
#pragma unroll
        for (int nt = 0; nt < 8; nt++) {
            o[nt][0] *= fac0; o[nt][1] *= fac0;
            o[nt][2] *= fac1; o[nt][3] *= fac1;
        }

        // ---- O += P V ----
#pragma unroll
        for (int ks = 0; ks < 4; ks++) {
            uint32_t ap[4];
            ap[0] = pk_h2(s[2 * ks][0],     s[2 * ks][1]);
            ap[1] = pk_h2(s[2 * ks][2],     s[2 * ks][3]);
            ap[2] = pk_h2(s[2 * ks + 1][0], s[2 * ks + 1][1]);
            ap[3] = pk_h2(s[2 * ks + 1][2], s[2 * ks + 1][3]);
#pragma unroll
            for (int ntp = 0; ntp < 4; ntp++) {
                uint32_t vv[4];
                uint32_t off = (uint32_t)((ks * 16 + (mi & 1) * 8 + li) * APITCH
                                          + (2 * ntp + (mi >> 1)) * 8) * 2;
                ldsm4t(vv, v_b + off);
                mma_f16(o[2 * ntp],     ap, vv[0], vv[1]);
                mma_f16(o[2 * ntp + 1], ap, vv[2], vv[3]);
            }
        }
        __syncthreads();
    }

    // epilogue: normalize, store fp16 BLOCKED (K = Dm)
    const float inv0 = 1.f / l0, inv1 = 1.f / l1;
#pragma unroll
    for (int nt = 0; nt < 8; nt++) {
        const int col = h * DHd + 8 * nt + 2 * tig;
        const int row0 = b * Sq + grow0;
        *(__half2*)(g_ah + blk_idx(row0, col, Dm))     = __floats2half2_rn(o[nt][0] * inv0, o[nt][1] * inv0);
        *(__half2*)(g_ah + blk_idx(row0 + 8, col, Dm)) = __floats2half2_rn(o[nt][2] * inv1, o[nt][3] * inv1);
    }
}

// ---------------- layernorm (blocked fp16 out) ----------------
__device__ __forceinline__ float block_sum_256(float val, float* sh) {
#pragma unroll
    for (int off = 16; off; off >>= 1) val += __shfl_xor_sync(0xffffffffu, val, off);
    if ((threadIdx.x & 31) == 0) sh[threadIdx.x >> 5] = val;
    __syncthreads();
    float t = 0.f;
    if (threadIdx.x < 8) t = sh[threadIdx.x];
    if (threadIdx.x < 32) {
#pragma unroll
        for (int off = 4; off; off >>= 1) t += __shfl_xor_sync(0xffffffffu, t, off);
        if (threadIdx.x == 0) sh[0] = t;
    }
    __syncthreads();
    float r = sh[0];
    __syncthreads();
    return r;
}

__global__ void ln_kernel(const float* __restrict__ in, const float* __restrict__ gam,
                          const float* __restrict__ bet, float* __restrict__ out,
                          __half* __restrict__ oh)
{
    __shared__ float sh[8];
    int row = blockIdx.x, tid = threadIdx.x;
    float4 x4 = ((const float4*)(in + (size_t)row * Dm))[tid];
    float s = x4.x + x4.y + x4.z + x4.w;
    float mean = block_sum_256(s, sh) * (1.f / Dm);
    float dx = x4.x - mean, dy = x4.y - mean, dz = x4.z - mean, dw = x4.w - mean;
    float s2 = dx * dx + dy * dy + dz * dz + dw * dw;
    float var = block_sum_256(s2, sh) * (1.f / Dm);
    float inv = rsqrtf(var + 1e-6f);
    int c = tid * 4;
    float4 o;
    o.x = dx * inv * gam[c + 0] + bet[c + 0];
    o.y = dy * inv * gam[c + 1] + bet[c + 1];
    o.z = dz * inv * gam[c + 2] + bet[c + 2];
    o.w = dw * inv * gam[c + 3] + bet[c + 3];
    ((float4*)(out + (size_t)row * Dm))[tid] = o;
    if (oh) {
        *(__half2*)(oh + blk_idx(row, c, Dm))     = __floats2half2_rn(o.x, o.y);
        *(__half2*)(oh + blk_idx(row, c + 2, Dm)) = __floats2half2_rn(o.z, o.w);
    }
}

// ---------------- launch ----------------
extern "C" void kernel_launch(void* const* d_in, const int* in_sizes, int n_in,
                              void* d_out, int out_size)
{
    const float* x_in = (const float*)d_in[0];
    const int*   rid  = (const int*)  d_in[1];
    const float* Wq   = (const float*)d_in[2];
    const float* bqp  = (const float*)d_in[3];
    const float* Wk   = (const float*)d_in[4];
    const float* bkp  = (const float*)d_in[5];
    const float* Wv   = (const float*)d_in[6];
    const float* bvp  = (const float*)d_in[7];
    const float* Wo   = (const float*)d_in[8];
    const float* bop  = (const float*)d_in[9];
    const float* Erel = (const float*)d_in[10];
    const float* Brel = (const float*)d_in[11];
    const float* g1   = (const float*)d_in[12];
    const float* be1  = (const float*)d_in[13];
    const float* g2   = (const float*)d_in[14];
    const float* be2  = (const float*)d_in[15];
    const float* W1   = (const float*)d_in[16];
    const float* b1   = (const float*)d_in[17];
    const float* W2   = (const float*)d_in[18];
    const float* b2   = (const float*)d_in[19];
    float* outp = (float*)d_out;

    float *x, *y, *k, *v;
    __half *xh, *ah, *ffh, *hh;
    __half *wT4, *w1T, *w2T;
    cudaGetSymbolAddress((void**)&x,  g_x);
    cudaGetSymbolAddress((void**)&y,  g_y);
    cudaGetSymbolAddress((void**)&k,  g_k);
    cudaGetSymbolAddress((void**)&v,  g_v);
    cudaGetSymbolAddress((void**)&xh, g_xh);
    cudaGetSymbolAddress((void**)&ah, g_ah);
    cudaGetSymbolAddress((void**)&ffh, g_ffh);
    cudaGetSymbolAddress((void**)&hh, g_hh);
    cudaGetSymbolAddress((void**)&wT4, g_wT4);
    cudaGetSymbolAddress((void**)&w1T, g_w1T);
    cudaGetSymbolAddress((void**)&w2T, g_w2T);

    cudaFuncSetAttribute(gemm16_kernel,     cudaFuncAttributeMaxDynamicSharedMemorySize, GEMM_SMEM);
    cudaFuncSetAttribute(gemm16_qkv_kernel, cudaFuncAttributeMaxDynamicSharedMemorySize, GEMM_SMEM);

    // ---- preconvert weights + rid ----
    const dim3 tb(32, 8);
    for (int l = 0; l < Ll; l++) {
        const size_t wdd = (size_t)l * Dm * Dm;
        const size_t o4  = (size_t)l * 4 * Dm * Dm;
        wconv_kernel<<<dim3(Dm / 32, Dm / 32), tb>>>(Wq + wdd, wT4 + o4,                   Dm, Dm);
        wconv_kernel<<<dim3(Dm / 32, Dm / 32), tb>>>(Wk + wdd, wT4 + o4 + (size_t)Dm*Dm,   Dm, Dm);
        wconv_kernel<<<dim3(Dm / 32, Dm / 32), tb>>>(Wv + wdd, wT4 + o4 + (size_t)2*Dm*Dm, Dm, Dm);
        wconv_kernel<<<dim3(Dm / 32, Dm / 32), tb>>>(Wo + wdd, wT4 + o4 + (size_t)3*Dm*Dm, Dm, Dm);
        wconv_kernel<<<dim3(Ff / 32, Dm / 32), tb>>>(W1 + (size_t)l * Dm * Ff, w1T + (size_t)l * Ff * Dm, Dm, Ff);
        wconv_kernel<<<dim3(Dm / 32, Ff / 32), tb>>>(W2 + (size_t)l * Ff * Dm, w2T + (size_t)l * Dm * Ff, Ff, Dm);
    }
    rid8_kernel<<<(Sq * Sq + 255) / 256, 256>>>(rid, Sq * Sq);

    copy_split_kernel<<<(ROWS * Dm + 255) / 256, 256>>>(x_in, x, xh, ROWS * Dm);

    for (int l = 0; l < Ll; l++) {
        const size_t o4 = (size_t)l * 4 * Dm * Dm;

        gemm16_qkv_kernel<<<dim3(Dm / 128, ROWS / 128, 3), 256, GEMM_SMEM>>>(
            xh, wT4 + o4, bqp + l * Dm, bkp + l * Dm, bvp + l * Dm, Dm, Dm);

        const int qetot = Bq * Hh * Sq * NBb;
        qe_kernel<<<(qetot + 255) / 256, 256>>>(Erel + (size_t)l * NBb * DHd);

        attn_kernel<<<dim3(Sq / 64, Hh, Bq), 128>>>(Brel + (size_t)l * Hh * NBb);

        gemm16_kernel<<<dim3(Dm / 128, ROWS / 128), 256, GEMM_SMEM>>>(
            ah, wT4 + o4 + (size_t)3 * Dm * Dm,
            bop + l * Dm, x, y, nullptr, nullptr, Dm, Dm, 0);

        ln_kernel<<<ROWS, 256>>>(y, g1 + l * Dm, be1 + l * Dm, k, ffh);

        gemm16_kernel<<<dim3(Ff / 128, ROWS / 128), 256, GEMM_SMEM>>>(
            ffh, w1T + (size_t)l * Ff * Dm,
            b1 + l * Ff, nullptr, nullptr, nullptr, hh, Ff, Dm, 1);

        gemm16_kernel<<<dim3(Dm / 128, ROWS / 128), 256, GEMM_SMEM>>>(
            hh, w2T + (size_t)l * Dm * Ff,
            b2 + l * Dm, k, v, nullptr, nullptr, Dm, Ff, 0);

        ln_kernel<<<ROWS, 256>>>(v, g2 + l * Dm, be2 + l * Dm,
                                 (l == Ll - 1) ? outp : x, xh);
    }
}

// round 15
// speedup vs baseline: 2.4273x; 1.0736x over previous
#include <cuda_runtime.h>
#include <cuda_fp16.h>
#include <math_constants.h>
#include <cstdint>

// Problem constants
#define Bq   4
#define Sq   1024
#define Dm   1024
#define Hh   16
#define DHd  64
#define Ff   4096
#define NBb  33
#define Ll   6
#define ROWS (Bq*Sq)
#define SCALE_ATTN 0.125f

// ---------------- scratch (device globals) ----------------
__device__ float g_x [ROWS*Dm];
__device__ float g_y [ROWS*Dm];
__device__ float g_k [ROWS*Dm];
__device__ float g_v [ROWS*Dm];
__device__ float g_qe[Bq*Hh*Sq*NBb];
__device__ unsigned char g_rid8[Sq*Sq];

__device__ __half g_xh [ROWS*Dm];
__device__ __half g_ah [ROWS*Dm];
__device__ __half g_ffh[ROWS*Dm];
__device__ __half g_hh [ROWS*Ff];
__device__ __half g_qh2[ROWS*Dm];
__device__ __half g_kh2[ROWS*Dm];
__device__ __half g_vh2[ROWS*Dm];

// transposed fp16 weights, BLOCKED: [nb][kc][128x64 swizzled tile]
__device__ __half g_wT4[Ll*4*Dm*Dm];
__device__ __half g_w1T[Ll*Ff*Dm];
__device__ __half g_w2T[Ll*Dm*Ff];

// ---------------- blocked layout ----------------
__device__ __forceinline__ size_t blk_idx(int row, int col, int K) {
    uint32_t byte = (uint32_t)((row & 127) * 128 + (col & 63) * 2);
    byte ^= ((byte >> 3) & 0x70);
    return ((size_t)(row >> 7) * (K >> 6) + (col >> 6)) * 8192 + (byte >> 1);
}

// ---------------- common asm helpers ----------------
__device__ __forceinline__ uint32_t s2u(const void* p) {
    uint32_t a;
    asm("{ .reg .u64 t; cvta.to.shared.u64 t, %1; cvt.u32.u64 %0, t; }" : "=r"(a) : "l"(p));
    return a;
}
__device__ __forceinline__ void cp16s(uint32_t s, const void* g) {
    asm volatile("cp.async.cg.shared.global [%0], [%1], 16;\n" :: "r"(s), "l"(g));
}
__device__ __forceinline__ void mma_f16(float* c, const uint32_t* a, uint32_t b0, uint32_t b1) {
    asm volatile(
        "mma.sync.aligned.m16n8k16.row.col.f32.f16.f16.f32 "
        "{%0,%1,%2,%3}, {%4,%5,%6,%7}, {%8,%9}, {%0,%1,%2,%3};\n"
        : "+f"(c[0]), "+f"(c[1]), "+f"(c[2]), "+f"(c[3])
        : "r"(a[0]), "r"(a[1]), "r"(a[2]), "r"(a[3]), "r"(b0), "r"(b1));
}
__device__ __forceinline__ void ldsm4(uint32_t* r, uint32_t addr) {
    asm volatile("ldmatrix.sync.aligned.m8n8.x4.shared.b16 {%0,%1,%2,%3}, [%4];"
                 : "=r"(r[0]), "=r"(r[1]), "=r"(r[2]), "=r"(r[3]) : "r"(addr));
}
__device__ __forceinline__ void ldsm4t(uint32_t* r, uint32_t addr) {
    asm volatile("ldmatrix.sync.aligned.m8n8.x4.trans.shared.b16 {%0,%1,%2,%3}, [%4];"
                 : "=r"(r[0]), "=r"(r[1]), "=r"(r[2]), "=r"(r[3]) : "r"(addr));
}
__device__ __forceinline__ uint32_t pk_h2(float a, float b) {
    __half2 t = __floats2half2_rn(a, b);
    return *(uint32_t*)&t;
}
__device__ __forceinline__ void mbar_init(uint32_t a, uint32_t c) {
    asm volatile("mbarrier.init.shared.b64 [%0], %1;" :: "r"(a), "r"(c) : "memory");
}
__device__ __forceinline__ void mbar_expect(uint32_t a, uint32_t bytes) {
    asm volatile("mbarrier.arrive.expect_tx.shared.b64 _, [%0], %1;" :: "r"(a), "r"(bytes) : "memory");
}
__device__ __forceinline__ void mbar_wait(uint32_t a, uint32_t ph) {
    asm volatile(
        "{\n\t.reg .pred P;\n\t"
        "W%=:\n\t"
        "mbarrier.try_wait.parity.shared::cta.b64 P, [%0], %1, 0x989680;\n\t"
        "@!P bra W%=;\n\t}"
        :: "r"(a), "r"(ph) : "memory");
}
__device__ __forceinline__ void bulkcp(uint32_t dst, const void* src, uint32_t bytes, uint32_t mbar) {
    asm volatile(
        "cp.async.bulk.shared::cta.global.mbarrier::complete_tx::bytes [%0], [%1], %2, [%3];"
        :: "r"(dst), "l"(src), "r"(bytes), "r"(mbar) : "memory");
}

// ---------------- weight transpose -> blocked fp16 [N][K] ----------------
__global__ void wconv_kernel(const float* __restrict__ W,
                             __half* __restrict__ T, int K, int N)
{
    __shared__ float t[32][33];
    int n0 = blockIdx.x * 32, k0 = blockIdx.y * 32;
    int tx = threadIdx.x, ty = threadIdx.y;
#pragma unroll
    for (int i = 0; i < 4; i++)
        t[ty + 8 * i][tx] = W[(size_t)(k0 + ty + 8 * i) * N + n0 + tx];
    __syncthreads();
#pragma unroll
    for (int i = 0; i < 4; i++) {
        float f = t[tx][ty + 8 * i];
        int n = n0 + ty + 8 * i, k = k0 + tx;
        T[blk_idx(n, k, K)] = __float2half_rn(f);
    }
}

// ---------------- rid -> uint8 ----------------
__global__ void rid8_kernel(const int* __restrict__ rid, int n)
{
    int i = blockIdx.x * blockDim.x + threadIdx.x;
    if (i < n) g_rid8[i] = (unsigned char)rid[i];
}

// ---------------- copy + convert (blocked fp16 out) ----------------
__global__ void copy_split_kernel(const float* __restrict__ in, float* __restrict__ out,
                                  __half* __restrict__ oh, int n)
{
    int i = blockIdx.x * blockDim.x + threadIdx.x;
    if (i < n) {
        float f = in[i];
        out[i] = f;
        oh[blk_idx(i / Dm, i % Dm, Dm)] = __float2half_rn(f);
    }
}

// =========================================================================
// 1-MMA fp16 GEMM, cp.async.bulk, 3-stage; min 2 CTAs/SM for overlap.
// =========================================================================
#define TILE_B 16384
#define GEMM_SMEM (1024 + 6 * TILE_B)

__device__ __forceinline__ void gemm_tma_core(
    const __half* __restrict__ Ablk, const __half* __restrict__ Bblk,
    const float* __restrict__ bias, const float* __restrict__ resid,
    float* __restrict__ C, __half* __restrict__ ChRow, __half* __restrict__ ChBlk,
    int N, int K, bool relu)
{
    extern __shared__ __align__(128) char smraw[];
    const uint32_t smb   = s2u(smraw);
    const uint32_t mbar  = smb;
    const uint32_t tiles = smb + 1024;

    const int tid  = threadIdx.x;
    const int lane = tid & 31;
    const int warp = tid >> 5;
    const int wm   = warp >> 1;
    const int wn   = warp & 1;
    const int g    = lane >> 2;
    const int tig  = lane & 3;
    const int mi   = lane >> 3, li = lane & 7;

    const int bm = blockIdx.y * 128, bn = blockIdx.x * 128;
    const int nck = K >> 6;

    if (tid == 0) {
        mbar_init(mbar + 0, 1);
        mbar_init(mbar + 8, 1);
        mbar_init(mbar + 16, 1);
    }
    __syncthreads();

    const char* gA = (const char*)Ablk + (size_t)(bm >> 7) * nck * TILE_B;
    const char* gB = (const char*)Bblk + (size_t)(bn >> 7) * nck * TILE_B;

    if (tid == 0) {
#pragma unroll
        for (int pc = 0; pc < 2; pc++) {
            if (pc < nck) {
                const uint32_t mb = mbar + 8 * pc;
                mbar_expect(mb, 2 * TILE_B);
                bulkcp(tiles + pc * 2 * TILE_B,          gA + (size_t)pc * TILE_B, TILE_B, mb);
                bulkcp(tiles + pc * 2 * TILE_B + TILE_B, gB + (size_t)pc * TILE_B, TILE_B, mb);
            }
        }
    }

    float acc[2][8][4];
#pragma unroll
    for (int i = 0; i < 2; i++)
#pragma unroll
        for (int j = 0; j < 8; j++)
#pragma unroll
            for (int c = 0; c < 4; c++) acc[i][j][c] = 0.f;

    const int rA0 = wm * 32 + (mi & 1) * 8 + li;
    const int rB0 = wn * 64 + (mi >> 1) * 8 + li;
    int ph[3] = {0, 0, 0};

    for (int kc = 0; kc < nck; kc++) {
        const int st = kc % 3;
        mbar_wait(mbar + 8 * st, (uint32_t)ph[st]);
        ph[st] ^= 1;
        if (kc + 2 < nck && tid == 0) {
            const int st2 = (kc + 2) % 3;
            const uint32_t mb = mbar + 8 * st2;
            mbar_expect(mb, 2 * TILE_B);
            bulkcp(tiles + st2 * 2 * TILE_B,          gA + (size_t)(kc + 2) * TILE_B, TILE_B, mb);
            bulkcp(tiles + st2 * 2 * TILE_B + TILE_B, gB + (size_t)(kc + 2) * TILE_B, TILE_B, mb);
        }
        const uint32_t aT = tiles + st * 2 * TILE_B;
        const uint32_t bT = aT + TILE_B;

#pragma unroll
        for (int ks = 0; ks < 4; ks++) {
            const uint32_t kA = ks * 32 + (mi >> 1) * 16;
            const uint32_t kB = ks * 32 + (mi & 1) * 16;
            uint32_t a0 = (uint32_t)(rA0 * 128) + kA;        a0 ^= (a0 >> 3) & 0x70;
            uint32_t a1 = (uint32_t)((rA0 + 16) * 128) + kA; a1 ^= (a1 >> 3) & 0x70;
            uint32_t ah0[4], ah1[4];
            ldsm4(ah0, aT + a0);
            ldsm4(ah1, aT + a1);
#pragma unroll
            for (int p = 0; p < 4; p++) {
                uint32_t bo = (uint32_t)((rB0 + p * 16) * 128) + kB; bo ^= (bo >> 3) & 0x70;
                uint32_t bh[4];
                ldsm4(bh, bT + bo);
#pragma unroll
                for (int q = 0; q < 2; q++) {
                    const int nf = 2 * p + q;
                    mma_f16(acc[0][nf], ah0, bh[2 * q], bh[2 * q + 1]);
                    mma_f16(acc[1][nf], ah1, bh[2 * q], bh[2 * q + 1]);
                }
            }
        }
        __syncthreads();
    }

    // ---- epilogue ----
#pragma unroll
    for (int mf = 0; mf < 2; mf++) {
#pragma unroll
        for (int nf = 0; nf < 8; nf++) {
            const int r0 = bm + wm * 32 + mf * 16 + g;
            const int cc = bn + wn * 64 + nf * 8 + 2 * tig;
            const float bs0 = bias[cc], bs1 = bias[cc + 1];
            float v0 = acc[mf][nf][0] + bs0;
            float v1 = acc[mf][nf][1] + bs1;
            float v2 = acc[mf][nf][2] + bs0;
            float v3 = acc[mf][nf][3] + bs1;
            const size_t i0 = (size_t)r0 * N + cc;
            const size_t i1 = (size_t)(r0 + 8) * N + cc;
            if (resid) {
                const float2 r0v = *(const float2*)(resid + i0);
                const float2 r1v = *(const float2*)(resid + i1);
                v0 += r0v.x; v1 += r0v.y; v2 += r1v.x; v3 += r1v.y;
            }
            if (relu) {
                v0 = fmaxf(v0, 0.f); v1 = fmaxf(v1, 0.f);
                v2 = fmaxf(v2, 0.f); v3 = fmaxf(v3, 0.f);
            }
            if (C) {
                *(float2*)(C + i0) = make_float2(v0, v1);
                *(float2*)(C + i1) = make_float2(v2, v3);
            }
            if (ChRow) {
                *(__half2*)(ChRow + i0) = __floats2half2_rn(v0, v1);
                *(__half2*)(ChRow + i1) = __floats2half2_rn(v2, v3);
            }
            if (ChBlk) {
                *(__half2*)(ChBlk + blk_idx(r0, cc, N))     = __floats2half2_rn(v0, v1);
                *(__half2*)(ChBlk + blk_idx(r0 + 8, cc, N)) = __floats2half2_rn(v2, v3);
            }
        }
    }
}

__global__ __launch_bounds__(256, 2) void gemm16_kernel(
    const __half* __restrict__ Ablk, const __half* __restrict__ Bblk,
    const float* __restrict__ bias, const float* __restrict__ resid,
    float* __restrict__ C, __half* __restrict__ ChRow, __half* __restrict__ ChBlk,
    int N, int K, int relu)
{
    gemm_tma_core(Ablk, Bblk, bias, resid, C, ChRow, ChBlk, N, K, relu != 0);
}

__global__ __launch_bounds__(256, 2) void gemm16_qkv_kernel(
    const __half* __restrict__ Ablk, const __half* __restrict__ WT,
    const float* __restrict__ bq, const float* __restrict__ bk, const float* __restrict__ bv,
    int N, int K)
{
    const size_t off = (size_t)blockIdx.z * Dm * Dm;
    const float* bias; __half* Ch;
    if      (blockIdx.z == 0) { bias = bq; Ch = g_qh2; }
    else if (blockIdx.z == 1) { bias = bk; Ch = g_kh2; }
    else                      { bias = bv; Ch = g_vh2; }
    gemm_tma_core(Ablk, WT + off, bias, nullptr, nullptr, Ch, nullptr, N, K, false);
}

// ---------------- qe = q @ Erel^T  (q read as fp16) ----------------
__global__ void qe_kernel(const float* __restrict__ er)
{
    int idx = blockIdx.x * blockDim.x + threadIdx.x;
    const int total = Bq * Hh * Sq * NBb;
    if (idx >= total) return;
    int nb = idx % NBb;
    int s  = (idx / NBb) % Sq;
    int h  = (idx / (NBb * Sq)) % Hh;
    int b  =  idx / (NBb * Sq * Hh);
    const __half* qr = g_qh2 + ((size_t)(b * Sq + s)) * Dm + h * DHd;
    const float* e  = er + nb * DHd;
    float acc = 0.f;
#pragma unroll
    for (int d = 0; d < DHd; d++) acc = fmaf(__half2float(qr[d]), e[d], acc);
    g_qe[idx] = acc;
}

// =========================================================================
// MMA flash attention, double-buffered K/V/rid tiles.
// dyn smem: 2 x (K 9216 + V 9216 + R 4096) + Cb 8448 = 53504 B
// =========================================================================
#define APITCH 72
#define ABUF   (9216 * 2 + 4096)          // per-buffer bytes
#define ATTN_SMEM (2 * ABUF + 64 * NBb * 4)

__global__ __launch_bounds__(128) void attn_kernel(const float* __restrict__ brel)
{
    extern __shared__ __align__(128) char asm_[];
    const uint32_t smb = s2u(asm_);
    float* Cb = (float*)(asm_ + 2 * ABUF);

    const int tid = threadIdx.x, lane = tid & 31, w = tid >> 5;
    const int g = lane >> 2, tig = lane & 3;
    const int b = blockIdx.z, h = blockIdx.y;
    const int q0 = blockIdx.x * 64;
    const int mi = lane >> 3, li = lane & 7;

    // ---- stage Q into buf0 K-region, build fragments ----
#pragma unroll
    for (int j = 0; j < 4; j++) {
        int chunk = tid + 128 * j;
        int r = chunk >> 3, c8 = chunk & 7;
        size_t go = ((size_t)(b * Sq + q0 + r)) * Dm + h * DHd + c8 * 8;
        uint32_t so = (uint32_t)(r * APITCH + c8 * 8) * 2;
        cp16s(smb + so, g_qh2 + go);
    }
    asm volatile("cp.async.commit_group;\n cp.async.wait_group 0;\n");
    __syncthreads();

    uint32_t aq[4][4];
    {
        const int row = w * 16 + (mi & 1) * 8 + li;
#pragma unroll
        for (int ks = 0; ks < 4; ks++) {
            uint32_t off = (uint32_t)(row * APITCH + ks * 16 + (mi >> 1) * 8) * 2;
            ldsm4(aq[ks], smb + off);
        }
    }
    for (int i = tid; i < 64 * NBb; i += 128) {
        int r = i / NBb, nb = i - r * NBb;
        Cb[i] = g_qe[(((size_t)(b * Hh + h)) * Sq + q0 + r) * NBb + nb] + brel[h * NBb + nb];
    }
    __syncthreads();   // Q frags extracted; buffers free

    float m0 = -CUDART_INF_F, m1 = -CUDART_INF_F, l0 = 0.f, l1 = 0.f;
    float o[8][4];
#pragma unroll
    for (int i = 0; i < 8; i++)
#pragma unroll
        for (int c = 0; c < 4; c++) o[i][c] = 0.f;

    const int qr0 = w * 16 + g;
    const int grow0 = q0 + qr0;
    const int NT = Sq / 64;

    // tile loader (one cp.async group per call)
    auto load_tile = [&](int t, uint32_t buf) {
        const int k0 = t * 64;
#pragma unroll
        for (int j = 0; j < 4; j++) {
            int chunk = tid + 128 * j;
            int r = chunk >> 3, c8 = chunk & 7;
            size_t go = ((size_t)(b * Sq + k0 + r)) * Dm + h * DHd + c8 * 8;
            uint32_t so = (uint32_t)(r * APITCH + c8 * 8) * 2;
            cp16s(buf + so, g_kh2 + go);
            cp16s(buf + 9216 + so, g_vh2 + go);
        }
#pragma unroll
        for (int j = 0; j < 2; j++) {
            int c2 = tid + 128 * j;
            int r = c2 >> 2, c16 = (c2 & 3) * 16;
            cp16s(buf + 18432 + (uint32_t)(r * 64 + c16),
                  g_rid8 + (size_t)(q0 + r) * Sq + k0 + c16);
        }
        asm volatile("cp.async.commit_group;\n");
    };

    load_tile(0, smb);

    for (int t = 0; t < NT; t++) {
        if (t + 1 < NT) {
            load_tile(t + 1, smb + ((t + 1) & 1) * ABUF);
            asm volatile("cp.async.wait_group 1;\n");
        } else {
            asm volatile("cp.async.wait_group 0;\n");
        }
        __syncthreads();
        const uint32_t k_b = smb + (t & 1) * ABUF;
        const uint32_t v_b = k_b + 9216;
        const unsigned char* R_s = (const unsigned char*)asm_ + (t & 1) * ABUF + 18432;

        // ---- S = Q K^T ----
        float s[8][4];
#pragma unroll
        for (int i = 0; i < 8; i++)
#pragma unroll
            for (int c = 0; c < 4; c++) s[i][c] = 0.f;

#pragma unroll
        for (int ks = 0; ks < 4; ks++) {
#pragma unroll
            for (int ntp = 0; ntp < 4; ntp++) {
                uint32_t kb[4];
                uint32_t off = (uint32_t)((ntp * 16 + (mi >> 1) * 8 + li) * APITCH
                                          + ks * 16 + (mi & 1) * 8) * 2;
                ldsm4(kb, k_b + off);
                mma_f16(s[2 * ntp],     aq[ks], kb[0], kb[1]);
                mma_f16(s[2 * ntp + 1], aq[ks], kb[2], kb[3]);
            }
        }

        // ---- rel terms + scale + online softmax ----
        float mt0 = -CUDART_INF_F, mt1 = -CUDART_INF_F;
#pragma unroll
        for (int nt = 0; nt < 8; nt++) {
            const int colL = 8 * nt + 2 * tig;
            uchar2 rr0 = *(const uchar2*)(R_s + qr0 * 64 + colL);
            uchar2 rr1 = *(const uchar2*)(R_s + (qr0 + 8) * 64 + colL);
            float v0 = (s[nt][0] + Cb[qr0 * NBb + rr0.x]) * SCALE_ATTN;
            float v1 = (s[nt][1] + Cb[qr0 * NBb + rr0.y]) * SCALE_ATTN;
            float v2 = (s[nt][2] + Cb[(qr0 + 8) * NBb + rr1.x]) * SCALE_ATTN;
            float v3 = (s[nt][3] + Cb[(qr0 + 8) * NBb + rr1.y]) * SCALE_ATTN;
            s[nt][0] = v0; s[nt][1] = v1; s[nt][2] = v2; s[nt][3] = v3;
            mt0 = fmaxf(mt0, fmaxf(v0, v1));
            mt1 = fmaxf(mt1, fmaxf(v2, v3));
        }
        mt0 = fmaxf(mt0, __shfl_xor_sync(0xffffffffu, mt0, 1));
        mt0 = fmaxf(mt0, __shfl_xor_sync(0xffffffffu, mt0, 2));
        mt1 = fmaxf(mt1, __shfl_xor_sync(0xffffffffu, mt1, 1));
        mt1 = fmaxf(mt1, __shfl_xor_sync(0xffffffffu, mt1, 2));

        const float mn0 = fmaxf(m0, mt0), mn1 = fmaxf(m1, mt1);
        const float fac0 = __expf(m0 - mn0), fac1 = __expf(m1 - mn1);
        float rs0 = 0.f, rs1 = 0.f;
#pragma unroll
        for (int nt = 0; nt < 8; nt++) {
            float p0 = __expf(s[nt][0] - mn0);
            float p1 = __expf(s[nt][1] - mn0);
            float p2 = __expf(s[nt][2] - mn1);
            float p3 = __expf(s[nt][3] - mn1);
            s[nt][0] = p0; s[nt][1] = p1; s[nt][2] = p2; s[nt][3] = p3;
            rs0 += p0 + p1; rs1 += p2 + p3;
        }
        rs0 += __shfl_xor_sync(0xffffffffu, rs0, 1);
        rs0 += __shfl_xor_sync(0xffffffffu, rs0, 2);
        rs1 += __shfl_xor_sync(0xffffffffu, rs1, 1);
        rs1 += __shfl_xor_sync(0xffffffffu, rs1, 2);
        l0 = l0 * fac0 + rs0;  m0 = mn0;
        l1 = l1 * fac1 + rs1;  m1 = mn1;
#pragma unroll
        for (int nt = 0; nt < 8; nt++) {
            o[nt][0] *= fac0; o[nt][1] *= fac0;
            o[nt][2] *= fac1; o[nt][3] *= fac1;
        }

        // ---- O += P V ----
#pragma unroll
        for (int ks = 0; ks < 4; ks++) {
            uint32_t ap[4];
            ap[0] = pk_h2(s[2 * ks][0],     s[2 * ks][1]);
            ap[1] = pk_h2(s[2 * ks][2],     s[2 * ks][3]);
            ap[2] = pk_h2(s[2 * ks + 1][0], s[2 * ks + 1][1]);
            ap[3] = pk_h2(s[2 * ks + 1][2], s[2 * ks + 1][3]);
#pragma unroll
            for (int ntp = 0; ntp < 4; ntp++) {
                uint32_t vv[4];
                uint32_t off = (uint32_t)((ks * 16 + (mi & 1) * 8 + li) * APITCH
                                          + (2 * ntp + (mi >> 1)) * 8) * 2;
                ldsm4t(vv, v_b + off);
                mma_f16(o[2 * ntp],     ap, vv[0], vv[1]);
                mma_f16(o[2 * ntp + 1], ap, vv[2], vv[3]);
            }
        }
        __syncthreads();
    }

    // epilogue: normalize, store fp16 BLOCKED (K = Dm)
    const float inv0 = 1.f / l0, inv1 = 1.f / l1;
#pragma unroll
    for (int nt = 0; nt < 8; nt++) {
        const int col = h * DHd + 8 * nt + 2 * tig;
        const int row0 = b * Sq + grow0;
        *(__half2*)(g_ah + blk_idx(row0, col, Dm))     = __floats2half2_rn(o[nt][0] * inv0, o[nt][1] * inv0);
        *(__half2*)(g_ah + blk_idx(row0 + 8, col, Dm)) = __floats2half2_rn(o[nt][2] * inv1, o[nt][3] * inv1);
    }
}

// ---------------- layernorm (blocked fp16 out) ----------------
__device__ __forceinline__ float block_sum_256(float val, float* sh) {
#pragma unroll
    for (int off = 16; off; off >>= 1) val += __shfl_xor_sync(0xffffffffu, val, off);
    if ((threadIdx.x & 31) == 0) sh[threadIdx.x >> 5] = val;
    __syncthreads();
    float t = 0.f;
    if (threadIdx.x < 8) t = sh[threadIdx.x];
    if (threadIdx.x < 32) {
#pragma unroll
        for (int off = 4; off; off >>= 1) t += __shfl_xor_sync(0xffffffffu, t, off);
        if (threadIdx.x == 0) sh[0] = t;
    }
    __syncthreads();
    float r = sh[0];
    __syncthreads();
    return r;
}

__global__ void ln_kernel(const float* __restrict__ in, const float* __restrict__ gam,
                          const float* __restrict__ bet, float* __restrict__ out,
                          __half* __restrict__ oh)
{
    __shared__ float sh[8];
    int row = blockIdx.x, tid = threadIdx.x;
    float4 x4 = ((const float4*)(in + (size_t)row * Dm))[tid];
    float s = x4.x + x4.y + x4.z + x4.w;
    float mean = block_sum_256(s, sh) * (1.f / Dm);
    float dx = x4.x - mean, dy = x4.y - mean, dz = x4.z - mean, dw = x4.w - mean;
    float s2 = dx * dx + dy * dy + dz * dz + dw * dw;
    float var = block_sum_256(s2, sh) * (1.f / Dm);
    float inv = rsqrtf(var + 1e-6f);
    int c = tid * 4;
    float4 o;
    o.x = dx * inv * gam[c + 0] + bet[c + 0];
    o.y = dy * inv * gam[c + 1] + bet[c + 1];
    o.z = dz * inv * gam[c + 2] + bet[c + 2];
    o.w = dw * inv * gam[c + 3] + bet[c + 3];
    ((float4*)(out + (size_t)row * Dm))[tid] = o;
    if (oh) {
        *(__half2*)(oh + blk_idx(row, c, Dm))     = __floats2half2_rn(o.x, o.y);
        *(__half2*)(oh + blk_idx(row, c + 2, Dm)) = __floats2half2_rn(o.z, o.w);
    }
}

// ---------------- launch ----------------
extern "C" void kernel_launch(void* const* d_in, const int* in_sizes, int n_in,
                              void* d_out, int out_size)
{
    const float* x_in = (const float*)d_in[0];
    const int*   rid  = (const int*)  d_in[1];
    const float* Wq   = (const float*)d_in[2];
    const float* bqp  = (const float*)d_in[3];
    const float* Wk   = (const float*)d_in[4];
    const float* bkp  = (const float*)d_in[5];
    const float* Wv   = (const float*)d_in[6];
    const float* bvp  = (const float*)d_in[7];
    const float* Wo   = (const float*)d_in[8];
    const float* bop  = (const float*)d_in[9];
    const float* Erel = (const float*)d_in[10];
    const float* Brel = (const float*)d_in[11];
    const float* g1   = (const float*)d_in[12];
    const float* be1  = (const float*)d_in[13];
    const float* g2   = (const float*)d_in[14];
    const float* be2  = (const float*)d_in[15];
    const float* W1   = (const float*)d_in[16];
    const float* b1   = (const float*)d_in[17];
    const float* W2   = (const float*)d_in[18];
    const float* b2   = (const float*)d_in[19];
    float* outp = (float*)d_out;

    float *x, *y, *k, *v;
    __half *xh, *ah, *ffh, *hh;
    __half *wT4, *w1T, *w2T;
    cudaGetSymbolAddress((void**)&x,  g_x);
    cudaGetSymbolAddress((void**)&y,  g_y);
    cudaGetSymbolAddress((void**)&k,  g_k);
    cudaGetSymbolAddress((void**)&v,  g_v);
    cudaGetSymbolAddress((void**)&xh, g_xh);
    cudaGetSymbolAddress((void**)&ah, g_ah);
    cudaGetSymbolAddress((void**)&ffh, g_ffh);
    cudaGetSymbolAddress((void**)&hh, g_hh);
    cudaGetSymbolAddress((void**)&wT4, g_wT4);
    cudaGetSymbolAddress((void**)&w1T, g_w1T);
    cudaGetSymbolAddress((void**)&w2T, g_w2T);

    cudaFuncSetAttribute(gemm16_kernel,     cudaFuncAttributeMaxDynamicSharedMemorySize, GEMM_SMEM);
    cudaFuncSetAttribute(gemm16_qkv_kernel, cudaFuncAttributeMaxDynamicSharedMemorySize, GEMM_SMEM);
    cudaFuncSetAttribute(attn_kernel,       cudaFuncAttributeMaxDynamicSharedMemorySize, ATTN_SMEM);

    // ---- preconvert weights + rid ----
    const dim3 tb(32, 8);
    for (int l = 0; l < Ll; l++) {
        const size_t wdd = (size_t)l * Dm * Dm;
        const size_t o4  = (size_t)l * 4 * Dm * Dm;
        wconv_kernel<<<dim3(Dm / 32, Dm / 32), tb>>>(Wq + wdd, wT4 + o4,                   Dm, Dm);
        wconv_kernel<<<dim3(Dm / 32, Dm / 32), tb>>>(Wk + wdd, wT4 + o4 + (size_t)Dm*Dm,   Dm, Dm);
        wconv_kernel<<<dim3(Dm / 32, Dm / 32), tb>>>(Wv + wdd, wT4 + o4 + (size_t)2*Dm*Dm, Dm, Dm);
        wconv_kernel<<<dim3(Dm / 32, Dm / 32), tb>>>(Wo + wdd, wT4 + o4 + (size_t)3*Dm*Dm, Dm, Dm);
        wconv_kernel<<<dim3(Ff / 32, Dm / 32), tb>>>(W1 + (size_t)l * Dm * Ff, w1T + (size_t)l * Ff * Dm, Dm, Ff);
        wconv_kernel<<<dim3(Dm / 32, Ff / 32), tb>>>(W2 + (size_t)l * Ff * Dm, w2T + (size_t)l * Dm * Ff, Ff, Dm);
    }
    rid8_kernel<<<(Sq * Sq + 255) / 256, 256>>>(rid, Sq * Sq);

    copy_split_kernel<<<(ROWS * Dm + 255) / 256, 256>>>(x_in, x, xh, ROWS * Dm);

    for (int l = 0; l < Ll; l++) {
        const size_t o4 = (size_t)l * 4 * Dm * Dm;

        gemm16_qkv_kernel<<<dim3(Dm / 128, ROWS / 128, 3), 256, GEMM_SMEM>>>(
            xh, wT4 + o4, bqp + l * Dm, bkp + l * Dm, bvp + l * Dm, Dm, Dm);

        const int qetot = Bq * Hh * Sq * NBb;
        qe_kernel<<<(qetot + 255) / 256, 256>>>(Erel + (size_t)l * NBb * DHd);

        attn_kernel<<<dim3(Sq / 64, Hh, Bq), 128, ATTN_SMEM>>>(Brel + (size_t)l * Hh * NBb);

        gemm16_kernel<<<dim3(Dm / 128, ROWS / 128), 256, GEMM_SMEM>>>(
            ah, wT4 + o4 + (size_t)3 * Dm * Dm,
            bop + l * Dm, x, y, nullptr, nullptr, Dm, Dm, 0);

        ln_kernel<<<ROWS, 256>>>(y, g1 + l * Dm, be1 + l * Dm, k, ffh);

        gemm16_kernel<<<dim3(Ff / 128, ROWS / 128), 256, GEMM_SMEM>>>(
            ffh, w1T + (size_t)l * Ff * Dm,
            b1 + l * Ff, nullptr, nullptr, nullptr, hh, Ff, Dm, 1);

        gemm16_kernel<<<dim3(Dm / 128, ROWS / 128), 256, GEMM_SMEM>>>(
            hh, w2T + (size_t)l * Dm * Ff,
            b2 + l * Dm, k, v, nullptr, nullptr, Dm, Ff, 0);

        ln_kernel<<<ROWS, 256>>>(v, g2 + l * Dm, be2 + l * Dm,
                                 (l == Ll - 1) ? outp : x, xh);
    }
}

// round 16
// speedup vs baseline: 4.7516x; 1.9576x over previous
#include <cuda_runtime.h>
#include <cuda_fp16.h>
#include <math_constants.h>
#include <cstdint>

// Problem constants
#define Bq   4
#define Sq   1024
#define Dm   1024
#define Hh   16
#define DHd  64
#define Ff   4096
#define NBb  33
#define Ll   6
#define ROWS (Bq*Sq)
#define SCALE_ATTN 0.125f

// ---------------- scratch (device globals) ----------------
__device__ float g_x [ROWS*Dm];
__device__ float g_y [ROWS*Dm];
__device__ float g_k [ROWS*Dm];
__device__ float g_v [ROWS*Dm];
__device__ unsigned char g_rid8[Sq*Sq];

__device__ __half g_xh [ROWS*Dm];
__device__ __half g_ah [ROWS*Dm];
__device__ __half g_ffh[ROWS*Dm];
__device__ __half g_hh [ROWS*Ff];
__device__ __half g_qh2[ROWS*Dm];
__device__ __half g_kh2[ROWS*Dm];
__device__ __half g_vh2[ROWS*Dm];

// transposed fp16 weights, BLOCKED: [nb][kc][128x64 swizzled tile]
__device__ __half g_wT4[Ll*4*Dm*Dm];
__device__ __half g_w1T[Ll*Ff*Dm];
__device__ __half g_w2T[Ll*Dm*Ff];

// ---------------- blocked layout ----------------
__device__ __forceinline__ size_t blk_idx(int row, int col, int K) {
    uint32_t byte = (uint32_t)((row & 127) * 128 + (col & 63) * 2);
    byte ^= ((byte >> 3) & 0x70);
    return ((size_t)(row >> 7) * (K >> 6) + (col >> 6)) * 8192 + (byte >> 1);
}

// ---------------- common asm helpers ----------------
__device__ __forceinline__ uint32_t s2u(const void* p) {
    uint32_t a;
    asm("{ .reg .u64 t; cvta.to.shared.u64 t, %1; cvt.u32.u64 %0, t; }" : "=r"(a) : "l"(p));
    return a;
}
__device__ __forceinline__ void cp16s(uint32_t s, const void* g) {
    asm volatile("cp.async.cg.shared.global [%0], [%1], 16;\n" :: "r"(s), "l"(g));
}
__device__ __forceinline__ void mma_f16(float* c, const uint32_t* a, uint32_t b0, uint32_t b1) {
    asm volatile(
        "mma.sync.aligned.m16n8k16.row.col.f32.f16.f16.f32 "
        "{%0,%1,%2,%3}, {%4,%5,%6,%7}, {%8,%9}, {%0,%1,%2,%3};\n"
        : "+f"(c[0]), "+f"(c[1]), "+f"(c[2]), "+f"(c[3])
        : "r"(a[0]), "r"(a[1]), "r"(a[2]), "r"(a[3]), "r"(b0), "r"(b1));
}
__device__ __forceinline__ void ldsm4(uint32_t* r, uint32_t addr) {
    asm volatile("ldmatrix.sync.aligned.m8n8.x4.shared.b16 {%0,%1,%2,%3}, [%4];"
                 : "=r"(r[0]), "=r"(r[1]), "=r"(r[2]), "=r"(r[3]) : "r"(addr));
}
__device__ __forceinline__ void ldsm4t(uint32_t* r, uint32_t addr) {
    asm volatile("ldmatrix.sync.aligned.m8n8.x4.trans.shared.b16 {%0,%1,%2,%3}, [%4];"
                 : "=r"(r[0]), "=r"(r[1]), "=r"(r[2]), "=r"(r[3]) : "r"(addr));
}
__device__ __forceinline__ uint32_t pk_h2(float a, float b) {
    __half2 t = __floats2half2_rn(a, b);
    return *(uint32_t*)&t;
}
__device__ __forceinline__ void mbar_init(uint32_t a, uint32_t c) {
    asm volatile("mbarrier.init.shared.b64 [%0], %1;" :: "r"(a), "r"(c) : "memory");
}
__device__ __forceinline__ void mbar_expect(uint32_t a, uint32_t bytes) {
    asm volatile("mbarrier.arrive.expect_tx.shared.b64 _, [%0], %1;" :: "r"(a), "r"(bytes) : "memory");
}
__device__ __forceinline__ void mbar_wait(uint32_t a, uint32_t ph) {
    asm volatile(
        "{\n\t.reg .pred P;\n\t"
        "W%=:\n\t"
        "mbarrier.try_wait.parity.shared::cta.b64 P, [%0], %1, 0x989680;\n\t"
        "@!P bra W%=;\n\t}"
        :: "r"(a), "r"(ph) : "memory");
}
__device__ __forceinline__ void bulkcp(uint32_t dst, const void* src, uint32_t bytes, uint32_t mbar) {
    asm volatile(
        "cp.async.bulk.shared::cta.global.mbarrier::complete_tx::bytes [%0], [%1], %2, [%3];"
        :: "r"(dst), "l"(src), "r"(bytes), "r"(mbar) : "memory");
}

// ---------------- weight transpose -> blocked fp16 [N][K] ----------------
__global__ void wconv_kernel(const float* __restrict__ W,
                             __half* __restrict__ T, int K, int N)
{
    __shared__ float t[32][33];
    int n0 = blockIdx.x * 32, k0 = blockIdx.y * 32;
    int tx = threadIdx.x, ty = threadIdx.y;
#pragma unroll
    for (int i = 0; i < 4; i++)
        t[ty + 8 * i][tx] = W[(size_t)(k0 + ty + 8 * i) * N + n0 + tx];
    __syncthreads();
#pragma unroll
    for (int i = 0; i < 4; i++) {
        float f = t[tx][ty + 8 * i];
        int n = n0 + ty + 8 * i, k = k0 + tx;
        T[blk_idx(n, k, K)] = __float2half_rn(f);
    }
}

// ---------------- rid -> uint8 ----------------
__global__ void rid8_kernel(const int* __restrict__ rid, int n)
{
    int i = blockIdx.x * blockDim.x + threadIdx.x;
    if (i < n) g_rid8[i] = (unsigned char)rid[i];
}

// ---------------- copy + convert (blocked fp16 out) ----------------
__global__ void copy_split_kernel(const float* __restrict__ in, float* __restrict__ out,
                                  __half* __restrict__ oh, int n)
{
    int i = blockIdx.x * blockDim.x + threadIdx.x;
    if (i < n) {
        float f = in[i];
        out[i] = f;
        oh[blk_idx(i / Dm, i % Dm, Dm)] = __float2half_rn(f);
    }
}

// =========================================================================
// 1-MMA fp16 GEMM, cp.async.bulk, 3-stage; min 2 CTAs/SM for overlap.
// =========================================================================
#define TILE_B 16384
#define GEMM_SMEM (1024 + 6 * TILE_B)

__device__ __forceinline__ void gemm_tma_core(
    const __half* __restrict__ Ablk, const __half* __restrict__ Bblk,
    const float* __restrict__ bias, const float* __restrict__ resid,
    float* __restrict__ C, __half* __restrict__ ChRow, __half* __restrict__ ChBlk,
    int N, int K, bool relu)
{
    extern __shared__ __align__(128) char smraw[];
    const uint32_t smb   = s2u(smraw);
    const uint32_t mbar  = smb;
    const uint32_t tiles = smb + 1024;

    const int tid  = threadIdx.x;
    const int lane = tid & 31;
    const int warp = tid >> 5;
    const int wm   = warp >> 1;
    const int wn   = warp & 1;
    const int g    = lane >> 2;
    const int tig  = lane & 3;
    const int mi   = lane >> 3, li = lane & 7;

    const int bm = blockIdx.y * 128, bn = blockIdx.x * 128;
    const int nck = K >> 6;

    if (tid == 0) {
        mbar_init(mbar + 0, 1);
        mbar_init(mbar + 8, 1);
        mbar_init(mbar + 16, 1);
    }
    __syncthreads();

    const char* gA = (const char*)Ablk + (size_t)(bm >> 7) * nck * TILE_B;
    const char* gB = (const char*)Bblk + (size_t)(bn >> 7) * nck * TILE_B;

    if (tid == 0) {
#pragma unroll
        for (int pc = 0; pc < 2; pc++) {
            if (pc < nck) {
                const uint32_t mb = mbar + 8 * pc;
                mbar_expect(mb, 2 * TILE_B);
                bulkcp(tiles + pc * 2 * TILE_B,          gA + (size_t)pc * TILE_B, TILE_B, mb);
                bulkcp(tiles + pc * 2 * TILE_B + TILE_B, gB + (size_t)pc * TILE_B, TILE_B, mb);
            }
        }
    }

    float acc[2][8][4];
#pragma unroll
    for (int i = 0; i < 2; i++)
#pragma unroll
        for (int j = 0; j < 8; j++)
#pragma unroll
            for (int c = 0; c < 4; c++) acc[i][j][c] = 0.f;

    const int rA0 = wm * 32 + (mi & 1) * 8 + li;
    const int rB0 = wn * 64 + (mi >> 1) * 8 + li;
    int ph[3] = {0, 0, 0};

    for (int kc = 0; kc < nck; kc++) {
        const int st = kc % 3;
        mbar_wait(mbar + 8 * st, (uint32_t)ph[st]);
        ph[st] ^= 1;
        if (kc + 2 < nck && tid == 0) {
            const int st2 = (kc + 2) % 3;
            const uint32_t mb = mbar + 8 * st2;
            mbar_expect(mb, 2 * TILE_B);
            bulkcp(tiles + st2 * 2 * TILE_B,          gA + (size_t)(kc + 2) * TILE_B, TILE_B, mb);
            bulkcp(tiles + st2 * 2 * TILE_B + TILE_B, gB + (size_t)(kc + 2) * TILE_B, TILE_B, mb);
        }
        const uint32_t aT = tiles + st * 2 * TILE_B;
        const uint32_t bT = aT + TILE_B;

#pragma unroll
        for (int ks = 0; ks < 4; ks++) {
            const uint32_t kA = ks * 32 + (mi >> 1) * 16;
            const uint32_t kB = ks * 32 + (mi & 1) * 16;
            uint32_t a0 = (uint32_t)(rA0 * 128) + kA;        a0 ^= (a0 >> 3) & 0x70;
            uint32_t a1 = (uint32_t)((rA0 + 16) * 128) + kA; a1 ^= (a1 >> 3) & 0x70;
            uint32_t ah0[4], ah1[4];
            ldsm4(ah0, aT + a0);
            ldsm4(ah1, aT + a1);
#pragma unroll
            for (int p = 0; p < 4; p++) {
                uint32_t bo = (uint32_t)((rB0 + p * 16) * 128) + kB; bo ^= (bo >> 3) & 0x70;
                uint32_t bh[4];
                ldsm4(bh, bT + bo);
#pragma unroll
                for (int q = 0; q < 2; q++) {
                    const int nf = 2 * p + q;
                    mma_f16(acc[0][nf], ah0, bh[2 * q], bh[2 * q + 1]);
                    mma_f16(acc[1][nf], ah1, bh[2 * q], bh[2 * q + 1]);
                }
            }
        }
        __syncthreads();
    }

    // ---- epilogue ----
#pragma unroll
    for (int mf = 0; mf < 2; mf++) {
#pragma unroll
        for (int nf = 0; nf < 8; nf++) {
            const int r0 = bm + wm * 32 + mf * 16 + g;
            const int cc = bn + wn * 64 + nf * 8 + 2 * tig;
            const float bs0 = bias[cc], bs1 = bias[cc + 1];
            float v0 = acc[mf][nf][0] + bs0;
            float v1 = acc[mf][nf][1] + bs1;
            float v2 = acc[mf][nf][2] + bs0;
            float v3 = acc[mf][nf][3] + bs1;
            const size_t i0 = (size_t)r0 * N + cc;
            const size_t i1 = (size_t)(r0 + 8) * N + cc;
            if (resid) {
                const float2 r0v = *(const float2*)(resid + i0);
                const float2 r1v = *(const float2*)(resid + i1);
                v0 += r0v.x; v1 += r0v.y; v2 += r1v.x; v3 += r1v.y;
            }
            if (relu) {
                v0 = fmaxf(v0, 0.f); v1 = fmaxf(v1, 0.f);
                v2 = fmaxf(v2, 0.f); v3 = fmaxf(v3, 0.f);
            }
            if (C) {
                *(float2*)(C + i0) = make_float2(v0, v1);
                *(float2*)(C + i1) = make_float2(v2, v3);
            }
            if (ChRow) {
                *(__half2*)(ChRow + i0) = __floats2half2_rn(v0, v1);
                *(__half2*)(ChRow + i1) = __floats2half2_rn(v2, v3);
            }
            if (ChBlk) {
                *(__half2*)(ChBlk + blk_idx(r0, cc, N))     = __floats2half2_rn(v0, v1);
                *(__half2*)(ChBlk + blk_idx(r0 + 8, cc, N)) = __floats2half2_rn(v2, v3);
            }
        }
    }
}

__global__ __launch_bounds__(256, 2) void gemm16_kernel(
    const __half* __restrict__ Ablk, const __half* __restrict__ Bblk,
    const float* __restrict__ bias, const float* __restrict__ resid,
    float* __restrict__ C, __half* __restrict__ ChRow, __half* __restrict__ ChBlk,
    int N, int K, int relu)
{
    gemm_tma_core(Ablk, Bblk, bias, resid, C, ChRow, ChBlk, N, K, relu != 0);
}

__global__ __launch_bounds__(256, 2) void gemm16_qkv_kernel(
    const __half* __restrict__ Ablk, const __half* __restrict__ WT,
    const float* __restrict__ bq, const float* __restrict__ bk, const float* __restrict__ bv,
    int N, int K)
{
    const size_t off = (size_t)blockIdx.z * Dm * Dm;
    const float* bias; __half* Ch;
    if      (blockIdx.z == 0) { bias = bq; Ch = g_qh2; }
    else if (blockIdx.z == 1) { bias = bk; Ch = g_kh2; }
    else                      { bias = bv; Ch = g_vh2; }
    gemm_tma_core(Ablk, WT + off, bias, nullptr, nullptr, Ch, nullptr, N, K, false);
}

// =========================================================================
// MMA flash attention, double-buffered K/V/rid tiles, fused qe (Cb computed
// in prologue from staged Q tile + smem-staged Erel).
// dyn smem: 2 x ABUF + Cb 8448 = 53504 B.  Erel staging aliases buf1.
// =========================================================================
#define APITCH 72
#define ABUF   (9216 * 2 + 4096)
#define ATTN_SMEM (2 * ABUF + 64 * NBb * 4)
#define EPITCH 66   // fp32 per Erel smem row (64 + 2 pad; kills nb-stride conflicts)

__global__ __launch_bounds__(128) void attn_kernel(const float* __restrict__ brel,
                                                   const float* __restrict__ erel)
{
    extern __shared__ __align__(128) char asm_[];
    const uint32_t smb = s2u(asm_);
    float* Cb = (float*)(asm_ + 2 * ABUF);
    float* Es = (float*)(asm_ + ABUF);        // aliases buf1 (free until tile 1)

    const int tid = threadIdx.x, lane = tid & 31, w = tid >> 5;
    const int g = lane >> 2, tig = lane & 3;
    const int b = blockIdx.z, h = blockIdx.y;
    const int q0 = blockIdx.x * 64;
    const int mi = lane >> 3, li = lane & 7;

    // ---- stage Q into buf0 (cp.async) + Erel into buf1 region (plain stores) ----
#pragma unroll
    for (int j = 0; j < 4; j++) {
        int chunk = tid + 128 * j;
        int r = chunk >> 3, c8 = chunk & 7;
        size_t go = ((size_t)(b * Sq + q0 + r)) * Dm + h * DHd + c8 * 8;
        uint32_t so = (uint32_t)(r * APITCH + c8 * 8) * 2;
        cp16s(smb + so, g_qh2 + go);
    }
    for (int i = tid; i < NBb * DHd; i += 128) {
        int nb = i >> 6, d = i & 63;
        Es[nb * EPITCH + d] = erel[i];
    }
    asm volatile("cp.async.commit_group;\n cp.async.wait_group 0;\n");
    __syncthreads();

    // Q fragments
    uint32_t aq[4][4];
    {
        const int row = w * 16 + (mi & 1) * 8 + li;
#pragma unroll
        for (int ks = 0; ks < 4; ks++) {
            uint32_t off = (uint32_t)(row * APITCH + ks * 16 + (mi >> 1) * 8) * 2;
            ldsm4(aq[ks], smb + off);
        }
    }
    // fused qe: Cb[r][nb] = sum_d Q[r][d]*Erel[nb][d] + brel[h][nb]
    const __half* Qs = (const __half*)asm_;
    for (int i = tid; i < 64 * NBb; i += 128) {
        int r = i / NBb, nb = i - r * NBb;
        const __half2* qrow = (const __half2*)(Qs + r * APITCH);
        const float2*  erow = (const float2*)(Es + nb * EPITCH);
        float acc = 0.f;
#pragma unroll
        for (int d2 = 0; d2 < 32; d2++) {
            float2 qf = __half22float2(qrow[d2]);
            float2 ef = erow[d2];
            acc = fmaf(qf.x, ef.x, acc);
            acc = fmaf(qf.y, ef.y, acc);
        }
        Cb[i] = acc + brel[h * NBb + nb];
    }
    __syncthreads();   // Q frags + Cb done; buffers free

    float m0 = -CUDART_INF_F, m1 = -CUDART_INF_F, l0 = 0.f, l1 = 0.f;
    float o[8][4];
#pragma unroll
    for (int i = 0; i < 8; i++)
#pragma unroll
        for (int c = 0; c < 4; c++) o[i][c] = 0.f;

    const int qr0 = w * 16 + g;
    const int grow0 = q0 + qr0;
    const int NT = Sq / 64;

    auto load_tile = [&](int t, uint32_t buf) {
        const int k0 = t * 64;
#pragma unroll
        for (int j = 0; j < 4; j++) {
            int chunk = tid + 128 * j;
            int r = chunk >> 3, c8 = chunk & 7;
            size_t go = ((size_t)(b * Sq + k0 + r)) * Dm + h * DHd + c8 * 8;
            uint32_t so = (uint32_t)(r * APITCH + c8 * 8) * 2;
            cp16s(buf + so, g_kh2 + go);
            cp16s(buf + 9216 + so, g_vh2 + go);
        }
#pragma unroll
        for (int j = 0; j < 2; j++) {
            int c2 = tid + 128 * j;
            int r = c2 >> 2, c16 = (c2 & 3) * 16;
            cp16s(buf + 18432 + (uint32_t)(r * 64 + c16),
                  g_rid8 + (size_t)(q0 + r) * Sq + k0 + c16);
        }
        asm volatile("cp.async.commit_group;\n");
    };

    load_tile(0, smb);

    for (int t = 0; t < NT; t++) {
        if (t + 1 < NT) {
            load_tile(t + 1, smb + ((t + 1) & 1) * ABUF);
            asm volatile("cp.async.wait_group 1;\n");
        } else {
            asm volatile("cp.async.wait_group 0;\n");
        }
        __syncthreads();
        const uint32_t k_b = smb + (t & 1) * ABUF;
        const uint32_t v_b = k_b + 9216;
        const unsigned char* R_s = (const unsigned char*)asm_ + (t & 1) * ABUF + 18432;

        // ---- S = Q K^T ----
        float s[8][4];
#pragma unroll
        for (int i = 0; i < 8; i++)
#pragma unroll
            for (int c = 0; c < 4; c++) s[i][c] = 0.f;

#pragma unroll
        for (int ks = 0; ks < 4; ks++) {
#pragma unroll
            for (int ntp = 0; ntp < 4; ntp++) {
                uint32_t kb[4];
                uint32_t off = (uint32_t)((ntp * 16 + (mi >> 1) * 8 + li) * APITCH
                                          + ks * 16 + (mi & 1) * 8) * 2;
                ldsm4(kb, k_b + off);
                mma_f16(s[2 * ntp],     aq[ks], kb[0], kb[1]);
                mma_f16(s[2 * ntp + 1], aq[ks], kb[2], kb[3]);
            }
        }

        // ---- rel terms + scale + online softmax ----
        float mt0 = -CUDART_INF_F, mt1 = -CUDART_INF_F;
#pragma unroll
        for (int nt = 0; nt < 8; nt++) {
            const int colL = 8 * nt + 2 * tig;
            uchar2 rr0 = *(const uchar2*)(R_s + qr0 * 64 + colL);
            uchar2 rr1 = *(const uchar2*)(R_s + (qr0 + 8) * 64 + colL);
            float v0 = (s[nt][0] + Cb[qr0 * NBb + rr0.x]) * SCALE_ATTN;
            float v1 = (s[nt][1] + Cb[qr0 * NBb + rr0.y]) * SCALE_ATTN;
            float v2 = (s[nt][2] + Cb[(qr0 + 8) * NBb + rr1.x]) * SCALE_ATTN;
            float v3 = (s[nt][3] + Cb[(qr0 + 8) * NBb + rr1.y]) * SCALE_ATTN;
            s[nt][0] = v0; s[nt][1] = v1; s[nt][2] = v2; s[nt][3] = v3;
            mt0 = fmaxf(mt0, fmaxf(v0, v1));
            mt1 = fmaxf(mt1, fmaxf(v2, v3));
        }
        mt0 = fmaxf(mt0, __shfl_xor_sync(0xffffffffu, mt0, 1));
        mt0 = fmaxf(mt0, __shfl_xor_sync(0xffffffffu, mt0, 2));
        mt1 = fmaxf(mt1, __shfl_xor_sync(0xffffffffu, mt1, 1));
        mt1 = fmaxf(mt1, __shfl_xor_sync(0xffffffffu, mt1, 2));

        const float mn0 = fmaxf(m0, mt0), mn1 = fmaxf(m1, mt1);
        const float fac0 = __expf(m0 - mn0), fac1 = __expf(m1 - mn1);
        float rs0 = 0.f, rs1 = 0.f;
#pragma unroll
        for (int nt = 0; nt < 8; nt++) {
            float p0 = __expf(s[nt][0] - mn0);
            float p1 = __expf(s[nt][1] - mn0);
            float p2 = __expf(s[nt][2] - mn1);
            float p3 = __expf(s[nt][3] - mn1);
            s[nt][0] = p0; s[nt][1] = p1; s[nt][2] = p2; s[nt][3] = p3;
            rs0 += p0 + p1; rs1 += p2 + p3;
        }
        rs0 += __shfl_xor_sync(0xffffffffu, rs0, 1);
        rs0 += __shfl_xor_sync(0xffffffffu, rs0, 2);
        rs1 += __shfl_xor_sync(0xffffffffu, rs1, 1);
        rs1 += __shfl_xor_sync(0xffffffffu, rs1, 2);
        l0 = l0 * fac0 + rs0;  m0 = mn0;
        l1 = l1 * fac1 + rs1;  m1 = mn1;
#pragma unroll
        for (int nt = 0; nt < 8; nt++) {
            o[nt][0] *= fac0; o[nt][1] *= fac0;
            o[nt][2] *= fac1; o[nt][3] *= fac1;
        }

        // ---- O += P V ----
#pragma unroll
        for (int ks = 0; ks < 4; ks++) {
            uint32_t ap[4];
            ap[0] = pk_h2(s[2 * ks][0],     s[2 * ks][1]);
            ap[1] = pk_h2(s[2 * ks][2],     s[2 * ks][3]);
            ap[2] = pk_h2(s[2 * ks + 1][0], s[2 * ks + 1][1]);
            ap[3] = pk_h2(s[2 * ks + 1][2], s[2 * ks + 1][3]);
#pragma unroll
            for (int ntp = 0; ntp < 4; ntp++) {
                uint32_t vv[4];
                uint32_t off = (uint32_t)((ks * 16 + (mi & 1) * 8 + li) * APITCH
                                          + (2 * ntp + (mi >> 1)) * 8) * 2;
                ldsm4t(vv, v_b + off);
                mma_f16(o[2 * ntp],     ap, vv[0], vv[1]);
                mma_f16(o[2 * ntp + 1], ap, vv[2], vv[3]);
            }
        }
        __syncthreads();
    }

    // epilogue: normalize, store fp16 BLOCKED (K = Dm)
    const float inv0 = 1.f / l0, inv1 = 1.f / l1;
#pragma unroll
    for (int nt = 0; nt < 8; nt++) {
        const int col = h * DHd + 8 * nt + 2 * tig;
        const int row0 = b * Sq + grow0;
        *(__half2*)(g_ah + blk_idx(row0, col, Dm))     = __floats2half2_rn(o[nt][0] * inv0, o[nt][1] * inv0);
        *(__half2*)(g_ah + blk_idx(row0 + 8, col, Dm)) = __floats2half2_rn(o[nt][2] * inv1, o[nt][3] * inv1);
    }
}

// ---------------- layernorm (blocked fp16 out) ----------------
__device__ __forceinline__ float block_sum_256(float val, float* sh) {
#pragma unroll
    for (int off = 16; off; off >>= 1) val += __shfl_xor_sync(0xffffffffu, val, off);
    if ((threadIdx.x & 31) == 0) sh[threadIdx.x >> 5] = val;
    __syncthreads();
    float t = 0.f;
    if (threadIdx.x < 8) t = sh[threadIdx.x];
    if (threadIdx.x < 32) {
#pragma unroll
        for (int off = 4; off; off >>= 1) t += __shfl_xor_sync(0xffffffffu, t, off);
        if (threadIdx.x == 0) sh[0] = t;
    }
    __syncthreads();
    float r = sh[0];
    __syncthreads();
    return r;
}

__global__ void ln_kernel(const float* __restrict__ in, const float* __restrict__ gam,
                          const float* __restrict__ bet, float* __restrict__ out,
                          __half* __restrict__ oh)
{
    __shared__ float sh[8];
    int row = blockIdx.x, tid = threadIdx.x;
    float4 x4 = ((const float4*)(in + (size_t)row * Dm))[tid];
    float s = x4.x + x4.y + x4.z + x4.w;
    float mean = block_sum_256(s, sh) * (1.f / Dm);
    float dx = x4.x - mean, dy = x4.y - mean, dz = x4.z - mean, dw = x4.w - mean;
    float s2 = dx * dx + dy * dy + dz * dz + dw * dw;
    float var = block_sum_256(s2, sh) * (1.f / Dm);
    float inv = rsqrtf(var + 1e-6f);
    int c = tid * 4;
    float4 o;
    o.x = dx * inv * gam[c + 0] + bet[c + 0];
    o.y = dy * inv * gam[c + 1] + bet[c + 1];
    o.z = dz * inv * gam[c + 2] + bet[c + 2];
    o.w = dw * inv * gam[c + 3] + bet[c + 3];
    ((float4*)(out + (size_t)row * Dm))[tid] = o;
    if (oh) {
        *(__half2*)(oh + blk_idx(row, c, Dm))     = __floats2half2_rn(o.x, o.y);
        *(__half2*)(oh + blk_idx(row, c + 2, Dm)) = __floats2half2_rn(o.z, o.w);
    }
}

// ---------------- launch ----------------
extern "C" void kernel_launch(void* const* d_in, const int* in_sizes, int n_in,
                              void* d_out, int out_size)
{
    const float* x_in = (const float*)d_in[0];
    const int*   rid  = (const int*)  d_in[1];
    const float* Wq   = (const float*)d_in[2];
    const float* bqp  = (const float*)d_in[3];
    const float* Wk   = (const float*)d_in[4];
    const float* bkp  = (const float*)d_in[5];
    const float* Wv   = (const float*)d_in[6];
    const float* bvp  = (const float*)d_in[7];
    const float* Wo   = (const float*)d_in[8];
    const float* bop  = (const float*)d_in[9];
    const float* Erel = (const float*)d_in[10];
    const float* Brel = (const float*)d_in[11];
    const float* g1   = (const float*)d_in[12];
    const float* be1  = (const float*)d_in[13];
    const float* g2   = (const float*)d_in[14];
    const float* be2  = (const float*)d_in[15];
    const float* W1   = (const float*)d_in[16];
    const float* b1   = (const float*)d_in[17];
    const float* W2   = (const float*)d_in[18];
    const float* b2   = (const float*)d_in[19];
    float* outp = (float*)d_out;

    float *x, *y, *k, *v;
    __half *xh, *ah, *ffh, *hh;
    __half *wT4, *w1T, *w2T;
    cudaGetSymbolAddress((void**)&x,  g_x);
    cudaGetSymbolAddress((void**)&y,  g_y);
    cudaGetSymbolAddress((void**)&k,  g_k);
    cudaGetSymbolAddress((void**)&v,  g_v);
    cudaGetSymbolAddress((void**)&xh, g_xh);
    cudaGetSymbolAddress((void**)&ah, g_ah);
    cudaGetSymbolAddress((void**)&ffh, g_ffh);
    cudaGetSymbolAddress((void**)&hh, g_hh);
    cudaGetSymbolAddress((void**)&wT4, g_wT4);
    cudaGetSymbolAddress((void**)&w1T, g_w1T);
    cudaGetSymbolAddress((void**)&w2T, g_w2T);

    cudaFuncSetAttribute(gemm16_kernel,     cudaFuncAttributeMaxDynamicSharedMemorySize, GEMM_SMEM);
    cudaFuncSetAttribute(gemm16_qkv_kernel, cudaFuncAttributeMaxDynamicSharedMemorySize, GEMM_SMEM);
    cudaFuncSetAttribute(attn_kernel,       cudaFuncAttributeMaxDynamicSharedMemorySize, ATTN_SMEM);

    // ---- preconvert weights + rid ----
    const dim3 tb(32, 8);
    for (int l = 0; l < Ll; l++) {
        const size_t wdd = (size_t)l * Dm * Dm;
        const size_t o4  = (size_t)l * 4 * Dm * Dm;
        wconv_kernel<<<dim3(Dm / 32, Dm / 32), tb>>>(Wq + wdd, wT4 + o4,                   Dm, Dm);
        wconv_kernel<<<dim3(Dm / 32, Dm / 32), tb>>>(Wk + wdd, wT4 + o4 + (size_t)Dm*Dm,   Dm, Dm);
        wconv_kernel<<<dim3(Dm / 32, Dm / 32), tb>>>(Wv + wdd, wT4 + o4 + (size_t)2*Dm*Dm, Dm, Dm);
        wconv_kernel<<<dim3(Dm / 32, Dm / 32), tb>>>(Wo + wdd, wT4 + o4 + (size_t)3*Dm*Dm, Dm, Dm);
        wconv_kernel<<<dim3(Ff / 32, Dm / 32), tb>>>(W1 + (size_t)l * Dm * Ff, w1T + (size_t)l * Ff * Dm, Dm, Ff);
        wconv_kernel<<<dim3(Dm / 32, Ff / 32), tb>>>(W2 + (size_t)l * Ff * Dm, w2T + (size_t)l * Dm * Ff, Ff, Dm);
    }
    rid8_kernel<<<(Sq * Sq + 255) / 256, 256>>>(rid, Sq * Sq);

    copy_split_kernel<<<(ROWS * Dm + 255) / 256, 256>>>(x_in, x, xh, ROWS * Dm);

    for (int l = 0; l < Ll; l++) {
        const size_t o4 = (size_t)l * 4 * Dm * Dm;

        gemm16_qkv_kernel<<<dim3(Dm / 128, ROWS / 128, 3), 256, GEMM_SMEM>>>(
            xh, wT4 + o4, bqp + l * Dm, bkp + l * Dm, bvp + l * Dm, Dm, Dm);

        attn_kernel<<<dim3(Sq / 64, Hh, Bq), 128, ATTN_SMEM>>>(
            Brel + (size_t)l * Hh * NBb, Erel + (size_t)l * NBb * DHd);

        gemm16_kernel<<<dim3(Dm / 128, ROWS / 128), 256, GEMM_SMEM>>>(
            ah, wT4 + o4 + (size_t)3 * Dm * Dm,
            bop + l * Dm, x, y, nullptr, nullptr, Dm, Dm, 0);

        ln_kernel<<<ROWS, 256>>>(y, g1 + l * Dm, be1 + l * Dm, k, ffh);

        gemm16_kernel<<<dim3(Ff / 128, ROWS / 128), 256, GEMM_SMEM>>>(
            ffh, w1T + (size_t)l * Ff * Dm,
            b1 + l * Ff, nullptr, nullptr, nullptr, hh, Ff, Dm, 1);

        gemm16_kernel<<<dim3(Dm / 128, ROWS / 128), 256, GEMM_SMEM>>>(
            hh, w2T + (size_t)l * Dm * Ff,
            b2 + l * Dm, k, v, nullptr, nullptr, Dm, Ff, 0);

        ln_kernel<<<ROWS, 256>>>(v, g2 + l * Dm, be2 + l * Dm,
                                 (l == Ll - 1) ? outp : x, xh);
    }
}

// round 17
// speedup vs baseline: 4.8669x; 1.0243x over previous
#include <cuda_runtime.h>
#include <cuda_fp16.h>
#include <math_constants.h>
#include <cstdint>

// Problem constants
#define Bq   4
#define Sq   1024
#define Dm   1024
#define Hh   16
#define DHd  64
#define Ff   4096
#define NBb  33
#define Ll   6
#define ROWS (Bq*Sq)
#define SCALE_ATTN 0.125f

// ---------------- scratch (device globals) ----------------
__device__ float g_x [ROWS*Dm];
__device__ float g_y [ROWS*Dm];
__device__ float g_k [ROWS*Dm];
__device__ float g_v [ROWS*Dm];
__device__ unsigned char g_rid8[Sq*Sq];

__device__ __half g_xh [ROWS*Dm];
__device__ __half g_ah [ROWS*Dm];
__device__ __half g_ffh[ROWS*Dm];
__device__ __half g_hh [ROWS*Ff];
__device__ __half g_qh2[ROWS*Dm];
__device__ __half g_kh2[ROWS*Dm];
__device__ __half g_vh2[ROWS*Dm];

// transposed fp16 weights, BLOCKED: [nb][kc][128x64 swizzled tile]
__device__ __half g_wT4[Ll*4*Dm*Dm];
__device__ __half g_w1T[Ll*Ff*Dm];
__device__ __half g_w2T[Ll*Dm*Ff];

// ---------------- blocked layout ----------------
__device__ __forceinline__ size_t blk_idx(int row, int col, int K) {
    uint32_t byte = (uint32_t)((row & 127) * 128 + (col & 63) * 2);
    byte ^= ((byte >> 3) & 0x70);
    return ((size_t)(row >> 7) * (K >> 6) + (col >> 6)) * 8192 + (byte >> 1);
}

// ---------------- common asm helpers ----------------
__device__ __forceinline__ uint32_t s2u(const void* p) {
    uint32_t a;
    asm("{ .reg .u64 t; cvta.to.shared.u64 t, %1; cvt.u32.u64 %0, t; }" : "=r"(a) : "l"(p));
    return a;
}
__device__ __forceinline__ void cp16s(uint32_t s, const void* g) {
    asm volatile("cp.async.cg.shared.global [%0], [%1], 16;\n" :: "r"(s), "l"(g));
}
__device__ __forceinline__ void mma_f16(float* c, const uint32_t* a, uint32_t b0, uint32_t b1) {
    asm volatile(
        "mma.sync.aligned.m16n8k16.row.col.f32.f16.f16.f32 "
        "{%0,%1,%2,%3}, {%4,%5,%6,%7}, {%8,%9}, {%0,%1,%2,%3};\n"
        : "+f"(c[0]), "+f"(c[1]), "+f"(c[2]), "+f"(c[3])
        : "r"(a[0]), "r"(a[1]), "r"(a[2]), "r"(a[3]), "r"(b0), "r"(b1));
}
__device__ __forceinline__ void ldsm4(uint32_t* r, uint32_t addr) {
    asm volatile("ldmatrix.sync.aligned.m8n8.x4.shared.b16 {%0,%1,%2,%3}, [%4];"
                 : "=r"(r[0]), "=r"(r[1]), "=r"(r[2]), "=r"(r[3]) : "r"(addr));
}
__device__ __forceinline__ void ldsm4t(uint32_t* r, uint32_t addr) {
    asm volatile("ldmatrix.sync.aligned.m8n8.x4.trans.shared.b16 {%0,%1,%2,%3}, [%4];"
                 : "=r"(r[0]), "=r"(r[1]), "=r"(r[2]), "=r"(r[3]) : "r"(addr));
}
__device__ __forceinline__ uint32_t pk_h2(float a, float b) {
    __half2 t = __floats2half2_rn(a, b);
    return *(uint32_t*)&t;
}
__device__ __forceinline__ void mbar_init(uint32_t a, uint32_t c) {
    asm volatile("mbarrier.init.shared.b64 [%0], %1;" :: "r"(a), "r"(c) : "memory");
}
__device__ __forceinline__ void mbar_expect(uint32_t a, uint32_t bytes) {
    asm volatile("mbarrier.arrive.expect_tx.shared.b64 _, [%0], %1;" :: "r"(a), "r"(bytes) : "memory");
}
__device__ __forceinline__ void mbar_wait(uint32_t a, uint32_t ph) {
    asm volatile(
        "{\n\t.reg .pred P;\n\t"
        "W%=:\n\t"
        "mbarrier.try_wait.parity.shared::cta.b64 P, [%0], %1, 0x989680;\n\t"
        "@!P bra W%=;\n\t}"
        :: "r"(a), "r"(ph) : "memory");
}
__device__ __forceinline__ void bulkcp(uint32_t dst, const void* src, uint32_t bytes, uint32_t mbar) {
    asm volatile(
        "cp.async.bulk.shared::cta.global.mbarrier::complete_tx::bytes [%0], [%1], %2, [%3];"
        :: "r"(dst), "l"(src), "r"(bytes), "r"(mbar) : "memory");
}

// ---------------- batched weight transpose -> blocked fp16 ----------------
// core: one 32x32 tile of one [K][N] matrix -> blocked [N][K]
__device__ __forceinline__ void wconv_tile(const float* __restrict__ W,
                                           __half* __restrict__ T, int K, int N)
{
    __shared__ float t[32][33];
    int n0 = blockIdx.x * 32, k0 = blockIdx.y * 32;
    int tx = threadIdx.x, ty = threadIdx.y;
#pragma unroll
    for (int i = 0; i < 4; i++)
        t[ty + 8 * i][tx] = W[(size_t)(k0 + ty + 8 * i) * N + n0 + tx];
    __syncthreads();
#pragma unroll
    for (int i = 0; i < 4; i++) {
        float f = t[tx][ty + 8 * i];
        int n = n0 + ty + 8 * i, k = k0 + tx;
        T[blk_idx(n, k, K)] = __float2half_rn(f);
    }
}

// all layers x {Wq,Wk,Wv,Wo}: grid.z = 4*Ll  (z>>2 = layer, z&3 = which)
__global__ void wconv4_kernel(const float* __restrict__ Wq, const float* __restrict__ Wk,
                              const float* __restrict__ Wv, const float* __restrict__ Wo,
                              __half* __restrict__ T4)
{
    const int z = blockIdx.z, l = z >> 2, wi = z & 3;
    const float* src;
    if      (wi == 0) src = Wq;
    else if (wi == 1) src = Wk;
    else if (wi == 2) src = Wv;
    else              src = Wo;
    wconv_tile(src + (size_t)l * Dm * Dm, T4 + (size_t)z * Dm * Dm, Dm, Dm);
}
// all layers W1 [Dm][Ff] -> [Ff][Dm] blocked: grid.z = Ll
__global__ void wconv1_kernel(const float* __restrict__ W1, __half* __restrict__ T)
{
    const int l = blockIdx.z;
    wconv_tile(W1 + (size_t)l * Dm * Ff, T + (size_t)l * Ff * Dm, Dm, Ff);
}
// all layers W2 [Ff][Dm] -> [Dm][Ff] blocked: grid.z = Ll
__global__ void wconv2_kernel(const float* __restrict__ W2, __half* __restrict__ T)
{
    const int l = blockIdx.z;
    wconv_tile(W2 + (size_t)l * Ff * Dm, T + (size_t)l * Dm * Ff, Ff, Dm);
}

// ---------------- rid -> uint8 ----------------
__global__ void rid8_kernel(const int* __restrict__ rid, int n)
{
    int i = blockIdx.x * blockDim.x + threadIdx.x;
    if (i < n) g_rid8[i] = (unsigned char)rid[i];
}

// ---------------- copy + convert (blocked fp16 out) ----------------
__global__ void copy_split_kernel(const float* __restrict__ in, float* __restrict__ out,
                                  __half* __restrict__ oh, int n)
{
    int i = blockIdx.x * blockDim.x + threadIdx.x;
    if (i < n) {
        float f = in[i];
        out[i] = f;
        oh[blk_idx(i / Dm, i % Dm, Dm)] = __float2half_rn(f);
    }
}

// =========================================================================
// 1-MMA fp16 GEMM, cp.async.bulk, 3-stage; min 2 CTAs/SM for overlap.
// =========================================================================
#define TILE_B 16384
#define GEMM_SMEM (1024 + 6 * TILE_B)

__device__ __forceinline__ void gemm_tma_core(
    const __half* __restrict__ Ablk, const __half* __restrict__ Bblk,
    const float* __restrict__ bias, const float* __restrict__ resid,
    float* __restrict__ C, __half* __restrict__ ChRow, __half* __restrict__ ChBlk,
    int N, int K, bool relu)
{
    extern __shared__ __align__(128) char smraw[];
    const uint32_t smb   = s2u(smraw);
    const uint32_t mbar  = smb;
    const uint32_t tiles = smb + 1024;

    const int tid  = threadIdx.x;
    const int lane = tid & 31;
    const int warp = tid >> 5;
    const int wm   = warp >> 1;
    const int wn   = warp & 1;
    const int g    = lane >> 2;
    const int tig  = lane & 3;
    const int mi   = lane >> 3, li = lane & 7;

    const int bm = blockIdx.y * 128, bn = blockIdx.x * 128;
    const int nck = K >> 6;

    if (tid == 0) {
        mbar_init(mbar + 0, 1);
        mbar_init(mbar + 8, 1);
        mbar_init(mbar + 16, 1);
    }
    __syncthreads();

    const char* gA = (const char*)Ablk + (size_t)(bm >> 7) * nck * TILE_B;
    const char* gB = (const char*)Bblk + (size_t)(bn >> 7) * nck * TILE_B;

    if (tid == 0) {
#pragma unroll
        for (int pc = 0; pc < 2; pc++) {
            if (pc < nck) {
                const uint32_t mb = mbar + 8 * pc;
                mbar_expect(mb, 2 * TILE_B);
                bulkcp(tiles + pc * 2 * TILE_B,          gA + (size_t)pc * TILE_B, TILE_B, mb);
                bulkcp(tiles + pc * 2 * TILE_B + TILE_B, gB + (size_t)pc * TILE_B, TILE_B, mb);
            }
        }
    }

    float acc[2][8][4];
#pragma unroll
    for (int i = 0; i < 2; i++)
#pragma unroll
        for (int j = 0; j < 8; j++)
#pragma unroll
            for (int c = 0; c < 4; c++) acc[i][j][c] = 0.f;

    const int rA0 = wm * 32 + (mi & 1) * 8 + li;
    const int rB0 = wn * 64 + (mi >> 1) * 8 + li;
    int ph[3] = {0, 0, 0};

    for (int kc = 0; kc < nck; kc++) {
        const int st = kc % 3;
        mbar_wait(mbar + 8 * st, (uint32_t)ph[st]);
        ph[st] ^= 1;
        if (kc + 2 < nck && tid == 0) {
            const int st2 = (kc + 2) % 3;
            const uint32_t mb = mbar + 8 * st2;
            mbar_expect(mb, 2 * TILE_B);
            bulkcp(tiles + st2 * 2 * TILE_B,          gA + (size_t)(kc + 2) * TILE_B, TILE_B, mb);
            bulkcp(tiles + st2 * 2 * TILE_B + TILE_B, gB + (size_t)(kc + 2) * TILE_B, TILE_B, mb);
        }
        const uint32_t aT = tiles + st * 2 * TILE_B;
        const uint32_t bT = aT + TILE_B;

#pragma unroll
        for (int ks = 0; ks < 4; ks++) {
            const uint32_t kA = ks * 32 + (mi >> 1) * 16;
            const uint32_t kB = ks * 32 + (mi & 1) * 16;
            uint32_t a0 = (uint32_t)(rA0 * 128) + kA;        a0 ^= (a0 >> 3) & 0x70;
            uint32_t a1 = (uint32_t)((rA0 + 16) * 128) + kA; a1 ^= (a1 >> 3) & 0x70;
            uint32_t ah0[4], ah1[4];
            ldsm4(ah0, aT + a0);
            ldsm4(ah1, aT + a1);
#pragma unroll
            for (int p = 0; p < 4; p++) {
                uint32_t bo = (uint32_t)((rB0 + p * 16) * 128) + kB; bo ^= (bo >> 3) & 0x70;
                uint32_t bh[4];
                ldsm4(bh, bT + bo);
#pragma unroll
                for (int q = 0; q < 2; q++) {
                    const int nf = 2 * p + q;
                    mma_f16(acc[0][nf], ah0, bh[2 * q], bh[2 * q + 1]);
                    mma_f16(acc[1][nf], ah1, bh[2 * q], bh[2 * q + 1]);
                }
            }
        }
        __syncthreads();
    }

    // ---- epilogue ----
#pragma unroll
    for (int mf = 0; mf < 2; mf++) {
#pragma unroll
        for (int nf = 0; nf < 8; nf++) {
            const int r0 = bm + wm * 32 + mf * 16 + g;
            const int cc = bn + wn * 64 + nf * 8 + 2 * tig;
            const float bs0 = bias[cc], bs1 = bias[cc + 1];
            float v0 = acc[mf][nf][0] + bs0;
            float v1 = acc[mf][nf][1] + bs1;
            float v2 = acc[mf][nf][2] + bs0;
            float v3 = acc[mf][nf][3] + bs1;
            const size_t i0 = (size_t)r0 * N + cc;
            const size_t i1 = (size_t)(r0 + 8) * N + cc;
            if (resid) {
                const float2 r0v = *(const float2*)(resid + i0);
                const float2 r1v = *(const float2*)(resid + i1);
                v0 += r0v.x; v1 += r0v.y; v2 += r1v.x; v3 += r1v.y;
            }
            if (relu) {
                v0 = fmaxf(v0, 0.f); v1 = fmaxf(v1, 0.f);
                v2 = fmaxf(v2, 0.f); v3 = fmaxf(v3, 0.f);
            }
            if (C) {
                *(float2*)(C + i0) = make_float2(v0, v1);
                *(float2*)(C + i1) = make_float2(v2, v3);
            }
            if (ChRow) {
                *(__half2*)(ChRow + i0) = __floats2half2_rn(v0, v1);
                *(__half2*)(ChRow + i1) = __floats2half2_rn(v2, v3);
            }
            if (ChBlk) {
                *(__half2*)(ChBlk + blk_idx(r0, cc, N))     = __floats2half2_rn(v0, v1);
                *(__half2*)(ChBlk + blk_idx(r0 + 8, cc, N)) = __floats2half2_rn(v2, v3);
            }
        }
    }
}

__global__ __launch_bounds__(256, 2) void gemm16_kernel(
    const __half* __restrict__ Ablk, const __half* __restrict__ Bblk,
    const float* __restrict__ bias, const float* __restrict__ resid,
    float* __restrict__ C, __half* __restrict__ ChRow, __half* __restrict__ ChBlk,
    int N, int K, int relu)
{
    gemm_tma_core(Ablk, Bblk, bias, resid, C, ChRow, ChBlk, N, K, relu != 0);
}

__global__ __launch_bounds__(256, 2) void gemm16_qkv_kernel(
    const __half* __restrict__ Ablk, const __half* __restrict__ WT,
    const float* __restrict__ bq, const float* __restrict__ bk, const float* __restrict__ bv,
    int N, int K)
{
    const size_t off = (size_t)blockIdx.z * Dm * Dm;
    const float* bias; __half* Ch;
    if      (blockIdx.z == 0) { bias = bq; Ch = g_qh2; }
    else if (blockIdx.z == 1) { bias = bk; Ch = g_kh2; }
    else                      { bias = bv; Ch = g_vh2; }
    gemm_tma_core(Ablk, WT + off, bias, nullptr, nullptr, Ch, nullptr, N, K, false);
}

// =========================================================================
// MMA flash attention, double-buffered K/V/rid tiles, fused qe.
// =========================================================================
#define APITCH 72
#define ABUF   (9216 * 2 + 4096)
#define ATTN_SMEM (2 * ABUF + 64 * NBb * 4)
#define EPITCH 66

__global__ __launch_bounds__(128) void attn_kernel(const float* __restrict__ brel,
                                                   const float* __restrict__ erel)
{
    extern __shared__ __align__(128) char asm_[];
    const uint32_t smb = s2u(asm_);
    float* Cb = (float*)(asm_ + 2 * ABUF);
    float* Es = (float*)(asm_ + ABUF);

    const int tid = threadIdx.x, lane = tid & 31, w = tid >> 5;
    const int g = lane >> 2, tig = lane & 3;
    const int b = blockIdx.z, h = blockIdx.y;
    const int q0 = blockIdx.x * 64;
    const int mi = lane >> 3, li = lane & 7;

#pragma unroll
    for (int j = 0; j < 4; j++) {
        int chunk = tid + 128 * j;
        int r = chunk >> 3, c8 = chunk & 7;
        size_t go = ((size_t)(b * Sq + q0 + r)) * Dm + h * DHd + c8 * 8;
        uint32_t so = (uint32_t)(r * APITCH + c8 * 8) * 2;
        cp16s(smb + so, g_qh2 + go);
    }
    for (int i = tid; i < NBb * DHd; i += 128) {
        int nb = i >> 6, d = i & 63;
        Es[nb * EPITCH + d] = erel[i];
    }
    asm volatile("cp.async.commit_group;\n cp.async.wait_group 0;\n");
    __syncthreads();

    uint32_t aq[4][4];
    {
        const int row = w * 16 + (mi & 1) * 8 + li;
#pragma unroll
        for (int ks = 0; ks < 4; ks++) {
            uint32_t off = (uint32_t)(row * APITCH + ks * 16 + (mi >> 1) * 8) * 2;
            ldsm4(aq[ks], smb + off);
        }
    }
    const __half* Qs = (const __half*)asm_;
    for (int i = tid; i < 64 * NBb; i += 128) {
        int r = i / NBb, nb = i - r * NBb;
        const __half2* qrow = (const __half2*)(Qs + r * APITCH);
        const float2*  erow = (const float2*)(Es + nb * EPITCH);
        float acc = 0.f;
#pragma unroll
        for (int d2 = 0; d2 < 32; d2++) {
            float2 qf = __half22float2(qrow[d2]);
            float2 ef = erow[d2];
            acc = fmaf(qf.x, ef.x, acc);
            acc = fmaf(qf.y, ef.y, acc);
        }
        Cb[i] = acc + brel[h * NBb + nb];
    }
    __syncthreads();

    float m0 = -CUDART_INF_F, m1 = -CUDART_INF_F, l0 = 0.f, l1 = 0.f;
    float o[8][4];
#pragma unroll
    for (int i = 0; i < 8; i++)
#pragma unroll
        for (int c = 0; c < 4; c++) o[i][c] = 0.f;

    const int qr0 = w * 16 + g;
    const int grow0 = q0 + qr0;
    const int NT = Sq / 64;

    auto load_tile = [&](int t, uint32_t buf) {
        const int k0 = t * 64;
#pragma unroll
        for (int j = 0; j < 4; j++) {
            int chunk = tid + 128 * j;
            int r = chunk >> 3, c8 = chunk & 7;
            size_t go = ((size_t)(b * Sq + k0 + r)) * Dm + h * DHd + c8 * 8;
            uint32_t so = (uint32_t)(r * APITCH + c8 * 8) * 2;
            cp16s(buf + so, g_kh2 + go);
            cp16s(buf + 9216 + so, g_vh2 + go);
        }
#pragma unroll
        for (int j = 0; j < 2; j++) {
            int c2 = tid + 128 * j;
            int r = c2 >> 2, c16 = (c2 & 3) * 16;
            cp16s(buf + 18432 + (uint32_t)(r * 64 + c16),
                  g_rid8 + (size_t)(q0 + r) * Sq + k0 + c16);
        }
        asm volatile("cp.async.commit_group;\n");
    };

    load_tile(0, smb);

    for (int t = 0; t < NT; t++) {
        if (t + 1 < NT) {
            load_tile(t + 1, smb + ((t + 1) & 1) * ABUF);
            asm volatile("cp.async.wait_group 1;\n");
        } else {
            asm volatile("cp.async.wait_group 0;\n");
        }
        __syncthreads();
        const uint32_t k_b = smb + (t & 1) * ABUF;
        const uint32_t v_b = k_b + 9216;
        const unsigned char* R_s = (const unsigned char*)asm_ + (t & 1) * ABUF + 18432;

        float s[8][4];
#pragma unroll
        for (int i = 0; i < 8; i++)
#pragma unroll
            for (int c = 0; c < 4; c++) s[i][c] = 0.f;

#pragma unroll
        for (int ks = 0; ks < 4; ks++) {
#pragma unroll
            for (int ntp = 0; ntp < 4; ntp++) {
                uint32_t kb[4];
                uint32_t off = (uint32_t)((ntp * 16 + (mi >> 1) * 8 + li) * APITCH
                                          + ks * 16 + (mi & 1) * 8) * 2;
                ldsm4(kb, k_b + off);
                mma_f16(s[2 * ntp],     aq[ks], kb[0], kb[1]);
                mma_f16(s[2 * ntp + 1], aq[ks], kb[2], kb[3]);
            }
        }

        float mt0 = -CUDART_INF_F, mt1 = -CUDART_INF_F;
#pragma unroll
        for (int nt = 0; nt < 8; nt++) {
            const int colL = 8 * nt + 2 * tig;
            uchar2 rr0 = *(const uchar2*)(R_s + qr0 * 64 + colL);
            uchar2 rr1 = *(const uchar2*)(R_s + (qr0 + 8) * 64 + colL);
            float v0 = (s[nt][0] + Cb[qr0 * NBb + rr0.x]) * SCALE_ATTN;
            float v1 = (s[nt][1] + Cb[qr0 * NBb + rr0.y]) * SCALE_ATTN;
            float v2 = (s[nt][2] + Cb[(qr0 + 8) * NBb + rr1.x]) * SCALE_ATTN;
            float v3 = (s[nt][3] + Cb[(qr0 + 8) * NBb + rr1.y]) * SCALE_ATTN;
            s[nt][0] = v0; s[nt][1] = v1; s[nt][2] = v2; s[nt][3] = v3;
            mt0 = fmaxf(mt0, fmaxf(v0, v1));
            mt1 = fmaxf(mt1, fmaxf(v2, v3));
        }
        mt0 = fmaxf(mt0, __shfl_xor_sync(0xffffffffu, mt0, 1));
        mt0 = fmaxf(mt0, __shfl_xor_sync(0xffffffffu, mt0, 2));
        mt1 = fmaxf(mt1, __shfl_xor_sync(0xffffffffu, mt1, 1));
        mt1 = fmaxf(mt1, __shfl_xor_sync(0xffffffffu, mt1, 2));

        const float mn0 = fmaxf(m0, mt0), mn1 = fmaxf(m1, mt1);
        const float fac0 = __expf(m0 - mn0), fac1 = __expf(m1 - mn1);
        float rs0 = 0.f, rs1 = 0.f;
#pragma unroll
        for (int nt = 0; nt < 8; nt++) {
            float p0 = __expf(s[nt][0] - mn0);
            float p1 = __expf(s[nt][1] - mn0);
            float p2 = __expf(s[nt][2] - mn1);
            float p3 = __expf(s[nt][3] - mn1);
            s[nt][0] = p0; s[nt][1] = p1; s[nt][2] = p2; s[nt][3] = p3;
            rs0 += p0 + p1; rs1 += p2 + p3;
        }
        rs0 += __shfl_xor_sync(0xffffffffu, rs0, 1);
        rs0 += __shfl_xor_sync(0xffffffffu, rs0, 2);
        rs1 += __shfl_xor_sync(0xffffffffu, rs1, 1);
        rs1 += __shfl_xor_sync(0xffffffffu, rs1, 2);
        l0 = l0 * fac0 + rs0;  m0 = mn0;
        l1 = l1 * fac1 + rs1;  m1 = mn1;
#pragma unroll
        for (int nt = 0; nt < 8; nt++) {
            o[nt][0] *= fac0; o[nt][1] *= fac0;
            o[nt][2] *= fac1; o[nt][3] *= fac1;
        }

#pragma unroll
        for (int ks = 0; ks < 4; ks++) {
            uint32_t ap[4];
            ap[0] = pk_h2(s[2 * ks][0],     s[2 * ks][1]);
            ap[1] = pk_h2(s[2 * ks][2],     s[2 * ks][3]);
            ap[2] = pk_h2(s[2 * ks + 1][0], s[2 * ks + 1][1]);
            ap[3] = pk_h2(s[2 * ks + 1][2], s[2 * ks + 1][3]);
#pragma unroll
            for (int ntp = 0; ntp < 4; ntp++) {
                uint32_t vv[4];
                uint32_t off = (uint32_t)((ks * 16 + (mi & 1) * 8 + li) * APITCH
                                          + (2 * ntp + (mi >> 1)) * 8) * 2;
                ldsm4t(vv, v_b + off);
                mma_f16(o[2 * ntp],     ap, vv[0], vv[1]);
                mma_f16(o[2 * ntp + 1], ap, vv[2], vv[3]);
            }
        }
        __syncthreads();
    }

    const float inv0 = 1.f / l0, inv1 = 1.f / l1;
#pragma unroll
    for (int nt = 0; nt < 8; nt++) {
        const int col = h * DHd + 8 * nt + 2 * tig;
        const int row0 = b * Sq + grow0;
        *(__half2*)(g_ah + blk_idx(row0, col, Dm))     = __floats2half2_rn(o[nt][0] * inv0, o[nt][1] * inv0);
        *(__half2*)(g_ah + blk_idx(row0 + 8, col, Dm)) = __floats2half2_rn(o[nt][2] * inv1, o[nt][3] * inv1);
    }
}

// ---------------- layernorm (blocked fp16 out) ----------------
__device__ __forceinline__ float block_sum_256(float val, float* sh) {
#pragma unroll
    for (int off = 16; off; off >>= 1) val += __shfl_xor_sync(0xffffffffu, val, off);
    if ((threadIdx.x & 31) == 0) sh[threadIdx.x >> 5] = val;
    __syncthreads();
    float t = 0.f;
    if (threadIdx.x < 8) t = sh[threadIdx.x];
    if (threadIdx.x < 32) {
#pragma unroll
        for (int off = 4; off; off >>= 1) t += __shfl_xor_sync(0xffffffffu, t, off);
        if (threadIdx.x == 0) sh[0] = t;
    }
    __syncthreads();
    float r = sh[0];
    __syncthreads();
    return r;
}

__global__ void ln_kernel(const float* __restrict__ in, const float* __restrict__ gam,
                          const float* __restrict__ bet, float* __restrict__ out,
                          __half* __restrict__ oh)
{
    __shared__ float sh[8];
    int row = blockIdx.x, tid = threadIdx.x;
    float4 x4 = ((const float4*)(in + (size_t)row * Dm))[tid];
    float s = x4.x + x4.y + x4.z + x4.w;
    float mean = block_sum_256(s, sh) * (1.f / Dm);
    float dx = x4.x - mean, dy = x4.y - mean, dz = x4.z - mean, dw = x4.w - mean;
    float s2 = dx * dx + dy * dy + dz * dz + dw * dw;
    float var = block_sum_256(s2, sh) * (1.f / Dm);
    float inv = rsqrtf(var + 1e-6f);
    int c = tid * 4;
    float4 o;
    o.x = dx * inv * gam[c + 0] + bet[c + 0];
    o.y = dy * inv * gam[c + 1] + bet[c + 1];
    o.z = dz * inv * gam[c + 2] + bet[c + 2];
    o.w = dw * inv * gam[c + 3] + bet[c + 3];
    ((float4*)(out + (size_t)row * Dm))[tid] = o;
    if (oh) {
        *(__half2*)(oh + blk_idx(row, c, Dm))     = __floats2half2_rn(o.x, o.y);
        *(__half2*)(oh + blk_idx(row, c + 2, Dm)) = __floats2half2_rn(o.z, o.w);
    }
}

// ---------------- launch ----------------
extern "C" void kernel_launch(void* const* d_in, const int* in_sizes, int n_in,
                              void* d_out, int out_size)
{
    const float* x_in = (const float*)d_in[0];
    const int*   rid  = (const int*)  d_in[1];
    const float* Wq   = (const float*)d_in[2];
    const float* bqp  = (const float*)d_in[3];
    const float* Wk   = (const float*)d_in[4];
    const float* bkp  = (const float*)d_in[5];
    const float* Wv   = (const float*)d_in[6];
    const float* bvp  = (const float*)d_in[7];
    const float* Wo   = (const float*)d_in[8];
    const float* bop  = (const float*)d_in[9];
    const float* Erel = (const float*)d_in[10];
    const float* Brel = (const float*)d_in[11];
    const float* g1   = (const float*)d_in[12];
    const float* be1  = (const float*)d_in[13];
    const float* g2   = (const float*)d_in[14];
    const float* be2  = (const float*)d_in[15];
    const float* W1   = (const float*)d_in[16];
    const float* b1   = (const float*)d_in[17];
    const float* W2   = (const float*)d_in[18];
    const float* b2   = (const float*)d_in[19];
    float* outp = (float*)d_out;

    float *x, *y, *k, *v;
    __half *xh, *ah, *ffh, *hh;
    __half *wT4, *w1T, *w2T;
    cudaGetSymbolAddress((void**)&x,  g_x);
    cudaGetSymbolAddress((void**)&y,  g_y);
    cudaGetSymbolAddress((void**)&k,  g_k);
    cudaGetSymbolAddress((void**)&v,  g_v);
    cudaGetSymbolAddress((void**)&xh, g_xh);
    cudaGetSymbolAddress((void**)&ah, g_ah);
    cudaGetSymbolAddress((void**)&ffh, g_ffh);
    cudaGetSymbolAddress((void**)&hh, g_hh);
    cudaGetSymbolAddress((void**)&wT4, g_wT4);
    cudaGetSymbolAddress((void**)&w1T, g_w1T);
    cudaGetSymbolAddress((void**)&w2T, g_w2T);

    cudaFuncSetAttribute(gemm16_kernel,     cudaFuncAttributeMaxDynamicSharedMemorySize, GEMM_SMEM);
    cudaFuncSetAttribute(gemm16_qkv_kernel, cudaFuncAttributeMaxDynamicSharedMemorySize, GEMM_SMEM);
    cudaFuncSetAttribute(attn_kernel,       cudaFuncAttributeMaxDynamicSharedMemorySize, ATTN_SMEM);

    // ---- batched preconvert: 3 launches + rid + copy ----
    const dim3 tb(32, 8);
    wconv4_kernel<<<dim3(Dm / 32, Dm / 32, 4 * Ll), tb>>>(Wq, Wk, Wv, Wo, wT4);
    wconv1_kernel<<<dim3(Ff / 32, Dm / 32, Ll), tb>>>(W1, w1T);
    wconv2_kernel<<<dim3(Dm / 32, Ff / 32, Ll), tb>>>(W2, w2T);
    rid8_kernel<<<(Sq * Sq + 255) / 256, 256>>>(rid, Sq * Sq);
    copy_split_kernel<<<(ROWS * Dm + 255) / 256, 256>>>(x_in, x, xh, ROWS * Dm);

    for (int l = 0; l < Ll; l++) {
        const size_t o4 = (size_t)l * 4 * Dm * Dm;

        gemm16_qkv_kernel<<<dim3(Dm / 128, ROWS / 128, 3), 256, GEMM_SMEM>>>(
            xh, wT4 + o4, bqp + l * Dm, bkp + l * Dm, bvp + l * Dm, Dm, Dm);

        attn_kernel<<<dim3(Sq / 64, Hh, Bq), 128, ATTN_SMEM>>>(
            Brel + (size_t)l * Hh * NBb, Erel + (size_t)l * NBb * DHd);

        gemm16_kernel<<<dim3(Dm / 128, ROWS / 128), 256, GEMM_SMEM>>>(
            ah, wT4 + o4 + (size_t)3 * Dm * Dm,
            bop + l * Dm, x, y, nullptr, nullptr, Dm, Dm, 0);

        ln_kernel<<<ROWS, 256>>>(y, g1 + l * Dm, be1 + l * Dm, k, ffh);

        gemm16_kernel<<<dim3(Ff / 128, ROWS / 128), 256, GEMM_SMEM>>>(
            ffh, w1T + (size_t)l * Ff * Dm,
            b1 + l * Ff, nullptr, nullptr, nullptr, hh, Ff, Dm, 1);

        gemm16_kernel<<<dim3(Dm / 128, ROWS / 128), 256, GEMM_SMEM>>>(
            hh, w2T + (size_t)l * Dm * Ff,
            b2 + l * Dm, k, v, nullptr, nullptr, Dm, Ff, 0);

        ln_kernel<<<ROWS, 256>>>(v, g2 + l * Dm, be2 + l * Dm,
                                 (l == Ll - 1) ? outp : x, xh);
    }
}